// round 7
// baseline (speedup 1.0000x reference)
#include <cuda_runtime.h>
#include <cuda_fp16.h>
#include <math.h>
#include <stdint.h>

#define TT   2048
#define HH   2048
#define NHH  16
#define NOPE 128
#define ROPED 64
#define DQK  192     // NOPE + ROPE
#define VDIM 128
#define QLAT 1536
#define KVLAT 512
#define NE   8
#define MIDIM 512
#define SHI  1024    // 2*MI

// ---------------------------------------------------------------------------
// Scratch (static device memory; no allocations anywhere)
// ---------------------------------------------------------------------------
struct __align__(128) Scratch {
    // f32 buffers
    float x1[TT * HH];
    float qa_pre[TT * QLAT];
    float kv[TT * (KVLAT + ROPED)];
    float S[(long long)NHH * TT * TT];   // 256 MB scores
    float attn[TT * HH];
    float x2[TT * HH];
    float h[(long long)NE * TT * 2 * MIDIM];
    float hs[TT * 2 * SHI];
    float routed2[2 * TT * HH];
    float shared_o[TT * HH];
    float ew[NE * TT];
    int   tok[NE * TT];
    int   orow[NE * TT];
    int   counts[NE];
    // half activation buffers
    __half n1h[TT * HH];
    __half qah[TT * QLAT];
    __half qh[TT * NHH * DQK];
    __half ckvh[TT * KVLAT];
    __half knopeh[TT * NHH * NOPE];
    __half kfullh[TT * NHH * DQK];
    __half vTh[NHH * VDIM * TT];          // [h*128+d, t]
    __half Sh[(long long)NHH * TT * TT];  // 128 MB probs
    __half oh[TT * NHH * VDIM];
    __half n2h[TT * HH];
    __half hsah[TT * SHI];
    __half hah[(long long)NE * TT * MIDIM];
    // half weight copies
    __half wqa_h[QLAT * HH];
    __half wqb_h[NHH * DQK * QLAT];
    __half wkva_h[(KVLAT + ROPED) * HH];
    __half wkb_h[NHH * NOPE * KVLAT];
    __half wvb_h[NHH * VDIM * KVLAT];
    __half wo_h[HH * NHH * VDIM];
    __half wsup_h[2 * SHI * HH];
    __half wsdn_h[HH * SHI];
    __half wup_h[(long long)NE * 2 * MIDIM * HH];
    __half wdn_h[(long long)NE * HH * MIDIM];
};
__device__ Scratch g_s;

// ---------------------------------------------------------------------------
// helpers
// ---------------------------------------------------------------------------
__device__ __forceinline__ uint32_t smem_u32(const void* p) {
    uint32_t a;
    asm("{ .reg .u64 t; cvta.to.shared.u64 t, %1; cvt.u32.u64 %0, t; }" : "=r"(a) : "l"(p));
    return a;
}

__device__ __forceinline__ void cp16(uint32_t dst, const void* src, int sz) {
    asm volatile("cp.async.cg.shared.global [%0], [%1], 16, %2;"
                 :: "r"(dst), "l"(src), "r"(sz));
}
__device__ __forceinline__ void cp_commit() {
    asm volatile("cp.async.commit_group;" ::: "memory");
}

__device__ __forceinline__ void ldm_x4(unsigned& r0, unsigned& r1, unsigned& r2,
                                       unsigned& r3, uint32_t addr) {
    asm volatile("ldmatrix.sync.aligned.m8n8.x4.shared.b16 {%0,%1,%2,%3}, [%4];"
                 : "=r"(r0), "=r"(r1), "=r"(r2), "=r"(r3) : "r"(addr));
}

__device__ __forceinline__ void mma_f16(float* d, const unsigned* a, const unsigned* b) {
    asm volatile(
        "mma.sync.aligned.m16n8k16.row.col.f32.f16.f16.f32 "
        "{%0,%1,%2,%3}, {%4,%5,%6,%7}, {%8,%9}, {%0,%1,%2,%3};\n"
        : "+f"(d[0]), "+f"(d[1]), "+f"(d[2]), "+f"(d[3])
        : "r"(a[0]), "r"(a[1]), "r"(a[2]), "r"(a[3]), "r"(b[0]), "r"(b[1]));
}

// ---------------------------------------------------------------------------
// fp16 NT GEMM: C[M,N] = scale * A[M,K] * B^T  (A:[M,K], B:[N,K] half)
// Templated tile: CTA 128 x NTILE, NTHREADS/32 warps of 64x64, ktile 64 halves.
// smem: (128 + NTILE) rows x 128B, 16B-chunk swizzle ch^(row&7), NSTAGE stages.
// ---------------------------------------------------------------------------
#define SMEM_BYTES 98304

template <bool OUTH, int NTILE, int NSTAGE, int NTHREADS>
__global__ __launch_bounds__(NTHREADS)
void gemm_h(const __half* __restrict__ A, const __half* __restrict__ B,
            void* __restrict__ Cv,
            int M, int N, int K, int lda, int ldb, int ldc,
            long long sA, long long sB, long long sC,
            float scale, int causal, int klim,
            const int* __restrict__ aidx, const int* __restrict__ mdev,
            const int* __restrict__ cidx, const float* __restrict__ cscale,
            int pstride)
{
    constexpr int STG_BYTES = (128 + NTILE) * 128;
    constexpr int LOADS = (128 + NTILE) * 8 / NTHREADS;
    extern __shared__ __align__(128) char smem[];
    const int z = blockIdx.z;
    A += (long long)z * sA;
    B += (long long)z * sB;
    if (pstride) {
        if (mdev)   mdev   += z;
        if (aidx)   aidx   += (long long)z * pstride;
        if (cidx)   cidx   += (long long)z * pstride;
        if (cscale) cscale += (long long)z * pstride;
    }
    const int Meff = mdev ? *mdev : M;
    const int m0 = blockIdx.y * 128;
    const int n0 = blockIdx.x * NTILE;
    if (m0 >= Meff) return;
    if (causal && n0 > m0 + 127) return;
    const int kmax = klim ? min(K, m0 + 128) : K;
    const int ktiles = kmax >> 6;

    const uint32_t sbase = smem_u32(smem);
    const int tid = threadIdx.x;
    const int lane = tid & 31;
    const int wid = tid >> 5;
    const int wm = (wid & 1) * 64;
    const int wn = (wid >> 1) * 64;
    const int lr = lane >> 2;     // 0..7
    const int lm = lane & 3;      // 0..3

    float acc[4][8][4];
#pragma unroll
    for (int i = 0; i < 4; i++)
#pragma unroll
        for (int j = 0; j < 8; j++)
#pragma unroll
            for (int c = 0; c < 4; c++) acc[i][j][c] = 0.f;

    auto issue_stage = [&](int i) {
        const uint32_t base = sbase + (i % NSTAGE) * STG_BYTES;
        const int kt = i << 6;           // half offset
#pragma unroll
        for (int it = 0; it < LOADS; it++) {
            int c = tid + it * NTHREADS;
            int row = c >> 3, ch = c & 7;
            uint32_t dst = base + row * 128 + ((ch ^ (row & 7)) << 4);
            const __half* src;
            int sz = 0;
            if (row < 128) {
                int gm = m0 + row;
                src = A;
                if (gm < Meff) {
                    int ar = aidx ? aidx[gm] : gm;
                    src = A + (long long)ar * lda + kt + ch * 8;
                    sz = 16;
                }
            } else {
                int gn = n0 + row - 128;
                src = B;
                if (gn < N) {
                    src = B + (long long)gn * ldb + kt + ch * 8;
                    sz = 16;
                }
            }
            cp16(dst, src, sz);
        }
    };

#pragma unroll
    for (int s = 0; s < NSTAGE - 1; s++) {
        if (s < ktiles) issue_stage(s);
        cp_commit();
    }

    // ldmatrix lane address components
    const int a_row = lane & 15;
    const int a_h = lane >> 4;
    const int b_t = lane >> 3;
    const int b_r = lane & 7;

    for (int i = 0; i < ktiles; i++) {
        if (i + NSTAGE - 1 < ktiles) issue_stage(i + NSTAGE - 1);
        cp_commit();
        if (NSTAGE == 2)
            asm volatile("cp.async.wait_group 1;" ::: "memory");
        else
            asm volatile("cp.async.wait_group 2;" ::: "memory");
        __syncthreads();

        const uint32_t base = sbase + (i % NSTAGE) * STG_BYTES;
#pragma unroll
        for (int kk = 0; kk < 4; kk++) {
            unsigned afr[4][4], bfr[8][2];
#pragma unroll
            for (int im = 0; im < 4; im++) {
                int row = wm + im * 16 + a_row;
                int ch = kk * 2 + a_h;
                ldm_x4(afr[im][0], afr[im][1], afr[im][2], afr[im][3],
                       base + row * 128 + ((ch ^ (row & 7)) << 4));
            }
#pragma unroll
            for (int j2 = 0; j2 < 4; j2++) {
                int jn = j2 * 2 + (b_t >> 1);
                int row = 128 + wn + jn * 8 + b_r;
                int ch = kk * 2 + (b_t & 1);
                unsigned r0, r1, r2, r3;
                ldm_x4(r0, r1, r2, r3, base + row * 128 + ((ch ^ (row & 7)) << 4));
                bfr[j2 * 2][0] = r0;     bfr[j2 * 2][1] = r1;
                bfr[j2 * 2 + 1][0] = r2; bfr[j2 * 2 + 1][1] = r3;
            }
#pragma unroll
            for (int im = 0; im < 4; im++)
#pragma unroll
                for (int jn = 0; jn < 8; jn++)
                    mma_f16(acc[im][jn], afr[im], bfr[jn]);
        }
        __syncthreads();
    }

    // epilogue
#pragma unroll
    for (int im = 0; im < 4; im++) {
#pragma unroll
        for (int part = 0; part < 2; part++) {
            int gm = m0 + wm + im * 16 + lr + part * 8;
            if (gm >= Meff) continue;
            long long crow = gm;
            float w = scale;
            if (cidx) { crow = cidx[gm]; w = scale * cscale[gm]; }
#pragma unroll
            for (int jn = 0; jn < 8; jn++) {
                int gn = n0 + wn + jn * 8 + lm * 2;
                if (gn >= N) continue;
                float vx = acc[im][jn][part * 2] * w;
                float vy = acc[im][jn][part * 2 + 1] * w;
                if (OUTH) {
                    __half* cp = (__half*)Cv + ((long long)z * sC) + crow * (long long)ldc + gn;
                    *reinterpret_cast<__half2*>(cp) = __floats2half2_rn(vx, vy);
                } else {
                    float* cp = (float*)Cv + ((long long)z * sC) + crow * (long long)ldc + gn;
                    *reinterpret_cast<float2*>(cp) = make_float2(vx, vy);
                }
            }
        }
    }
}

// ---------------------------------------------------------------------------
// Elementwise / reduction kernels
// ---------------------------------------------------------------------------
__global__ void zero_counts_k() {
    if (threadIdx.x < NE) g_s.counts[threadIdx.x] = 0;
}

// vectorized f32 -> f16 (n must be multiple of 4)
__global__ void f2h_k(const float4* __restrict__ in, uint2* __restrict__ out,
                      long long n4) {
    for (long long i = blockIdx.x * (long long)blockDim.x + threadIdx.x; i < n4;
         i += (long long)gridDim.x * blockDim.x) {
        float4 v = in[i];
        __half2 h0 = __floats2half2_rn(v.x, v.y);
        __half2 h1 = __floats2half2_rn(v.z, v.w);
        uint2 o;
        o.x = *reinterpret_cast<unsigned*>(&h0);
        o.y = *reinterpret_cast<unsigned*>(&h1);
        out[i] = o;
    }
}

__global__ void add2_k(const float* __restrict__ a, const float* __restrict__ b,
                       float* __restrict__ c, int n) {
    for (int i = blockIdx.x * blockDim.x + threadIdx.x; i < n; i += gridDim.x * blockDim.x)
        c[i] = a[i] + b[i];
}

__global__ void x2_out_k(const float* __restrict__ x1, const float* __restrict__ attn,
                         float* __restrict__ x2, float* __restrict__ dout, int n) {
    for (int i = blockIdx.x * blockDim.x + threadIdx.x; i < n; i += gridDim.x * blockDim.x) {
        float v = x1[i] + attn[i];
        x2[i] = v;
        dout[i] = v;
    }
}

__global__ void combine_k(const float* __restrict__ routed2, const float* __restrict__ sh,
                          float* __restrict__ dout, int n) {
    for (int i = blockIdx.x * blockDim.x + threadIdx.x; i < n; i += gridDim.x * blockDim.x)
        dout[i] = routed2[i] + routed2[n + i] + sh[i];
}

// f32 in -> half out
__global__ __launch_bounds__(256)
void rmsnorm_h_k(const float* __restrict__ in, const float* __restrict__ w,
                 __half* __restrict__ out, int cols, int instride, int outstride) {
    int row = blockIdx.x;
    const float* ip = in + (long long)row * instride;
    float ss = 0.f;
    for (int j = threadIdx.x; j < cols; j += 256) { float v = ip[j]; ss += v * v; }
    __shared__ float red[256];
    red[threadIdx.x] = ss;
    __syncthreads();
    for (int st = 128; st > 0; st >>= 1) {
        if (threadIdx.x < st) red[threadIdx.x] += red[threadIdx.x + st];
        __syncthreads();
    }
    float scale = rsqrtf(red[0] / (float)cols + 1e-6f);
    __half* op = out + (long long)row * outstride;
    for (int j = threadIdx.x; j < cols; j += 256)
        op[j] = __float2half_rn(ip[j] * scale * w[j]);
}

__global__ void rope_q_k(__half* __restrict__ q, const float* __restrict__ rsin,
                         const float* __restrict__ rcos) {
    int t = blockIdx.x;
    for (int i = threadIdx.x; i < NHH * 32; i += blockDim.x) {
        int h = i >> 5;
        int p = i & 31;
        __half* base = q + (long long)t * (NHH * DQK) + h * DQK + NOPE + 2 * p;
        float s = rsin[t * 32 + p], c = rcos[t * 32 + p];
        float a = __half2float(base[0]), b = __half2float(base[1]);
        base[0] = __float2half_rn(a * c - b * s);
        base[1] = __float2half_rn(a * s + b * c);
    }
}

__global__ void build_k_k(const __half* __restrict__ knope, const float* __restrict__ kv,
                          const float* __restrict__ rsin, const float* __restrict__ rcos,
                          __half* __restrict__ kfull) {
    int t = blockIdx.x;
    __shared__ __half pe[ROPED];
    if (threadIdx.x < 32) {
        int p = threadIdx.x;
        float a = kv[(long long)t * (KVLAT + ROPED) + KVLAT + 2 * p];
        float b = kv[(long long)t * (KVLAT + ROPED) + KVLAT + 2 * p + 1];
        float s = rsin[t * 32 + p], c = rcos[t * 32 + p];
        pe[2 * p]     = __float2half_rn(a * c - b * s);
        pe[2 * p + 1] = __float2half_rn(a * s + b * c);
    }
    __syncthreads();
    for (int i = threadIdx.x; i < NHH * DQK; i += blockDim.x) {
        int h = i / DQK;
        int d = i % DQK;
        kfull[(long long)t * (NHH * DQK) + i] =
            (d < NOPE) ? knope[(long long)t * (NHH * NOPE) + h * NOPE + d] : pe[d - NOPE];
    }
}

// softmax: f32 scores -> half probs, zero fill to tile end
__global__ __launch_bounds__(256)
void softmax_causal_k() {
    int qrow = blockIdx.x;
    int h = blockIdx.y;
    const float* row = g_s.S + ((long long)h * TT + qrow) * TT;
    __half* orow = g_s.Sh + ((long long)h * TT + qrow) * TT;
    int len = qrow + 1;
    int fill_end = (qrow & ~127) + 128;
    __shared__ float redm[256], reds[256];

    float m = -1e30f, sum = 0.f;
    for (int k = threadIdx.x; k < len; k += 256) {
        float v = row[k];
        if (v > m) { sum *= __expf(m - v); m = v; }
        sum += __expf(v - m);
    }
    redm[threadIdx.x] = m;
    reds[threadIdx.x] = sum;
    __syncthreads();
    for (int st = 128; st > 0; st >>= 1) {
        if (threadIdx.x < st) {
            float m2 = redm[threadIdx.x + st], s2 = reds[threadIdx.x + st];
            float m1 = redm[threadIdx.x], s1 = reds[threadIdx.x];
            float mm = fmaxf(m1, m2);
            redm[threadIdx.x] = mm;
            reds[threadIdx.x] = s1 * __expf(m1 - mm) + s2 * __expf(m2 - mm);
        }
        __syncthreads();
    }
    m = redm[0];
    float inv = 1.0f / reds[0];

    for (int k = threadIdx.x; k < len; k += 256)
        orow[k] = __float2half_rn(__expf(row[k] - m) * inv);
    for (int k = len + threadIdx.x; k < fill_end; k += 256)
        orow[k] = __float2half_rn(0.f);
}

__global__ __launch_bounds__(256)
void gate_topk_k(const __half* __restrict__ n2, const float* __restrict__ gw) {
    int t = blockIdx.x;
    __shared__ float logits[NE];
    int warp = threadIdx.x >> 5, lane = threadIdx.x & 31;
    const __half* xp = n2 + (long long)t * HH;
    const float* wp = gw + warp * HH;
    float s = 0.f;
    for (int k = lane; k < HH; k += 32) s += __half2float(xp[k]) * wp[k];
    for (int off = 16; off > 0; off >>= 1) s += __shfl_down_sync(0xffffffffu, s, off);
    if (lane == 0) logits[warp] = s;
    __syncthreads();
    if (threadIdx.x == 0) {
        float m = logits[0];
        for (int e = 1; e < NE; e++) m = fmaxf(m, logits[e]);
        float p[NE];
        float sum = 0.f;
        for (int e = 0; e < NE; e++) { p[e] = __expf(logits[e] - m); sum += p[e]; }
        for (int e = 0; e < NE; e++) p[e] /= sum;
        int i0 = 0;
        for (int e = 1; e < NE; e++) if (p[e] > p[i0]) i0 = e;
        int i1 = -1;
        for (int e = 0; e < NE; e++) {
            if (e == i0) continue;
            if (i1 < 0 || p[e] > p[i1]) i1 = e;
        }
        float w0 = p[i0], w1 = p[i1];
        float tot = w0 + w1;
        w0 /= tot; w1 /= tot;
        int pos0 = atomicAdd(&g_s.counts[i0], 1);
        g_s.tok[i0 * TT + pos0] = t;
        g_s.orow[i0 * TT + pos0] = t;
        g_s.ew[i0 * TT + pos0] = w0;
        int pos1 = atomicAdd(&g_s.counts[i1], 1);
        g_s.tok[i1 * TT + pos1] = t;
        g_s.orow[i1 * TT + pos1] = TT + t;
        g_s.ew[i1 * TT + pos1] = w1;
    }
}

__global__ void silu_gate_k(const float* __restrict__ in, __half* __restrict__ out,
                            int half_) {
    int row = blockIdx.x;
    const float* ip = in + (long long)row * 2 * half_;
    __half* op = out + (long long)row * half_;
    for (int j = threadIdx.x; j < half_; j += blockDim.x) {
        float a = ip[j], b = ip[half_ + j];
        op[j] = __float2half_rn((a / (1.f + __expf(-a))) * b);
    }
}

__global__ void silu_gate_moe_k() {
    int e = blockIdx.y;
    int row = blockIdx.x;
    if (row >= g_s.counts[e]) return;
    const float* ip = g_s.h + ((long long)e * TT + row) * (2 * MIDIM);
    __half* op = g_s.hah + ((long long)e * TT + row) * MIDIM;
    for (int j = threadIdx.x; j < MIDIM; j += blockDim.x) {
        float a = ip[j], b = ip[MIDIM + j];
        op[j] = __float2half_rn((a / (1.f + __expf(-a))) * b);
    }
}

// ---------------------------------------------------------------------------
// Host-side launch helpers
// ---------------------------------------------------------------------------
static void launch_gemm(bool wide, bool outh, const __half* A, const __half* B, void* C,
                        int M, int N, int K, int lda, int ldb, int ldc,
                        long long sA, long long sB, long long sC, int bz,
                        float sc, int causal, int klim,
                        const int* aidx, const int* mdev,
                        const int* cidx, const float* cs, int pstride)
{
    if (wide) {
        dim3 grid((N + 255) / 256, (M + 127) / 128, bz);
        if (outh)
            gemm_h<true, 256, 2, 256><<<grid, 256, SMEM_BYTES>>>(
                A, B, C, M, N, K, lda, ldb, ldc, sA, sB, sC, sc, causal, klim,
                aidx, mdev, cidx, cs, pstride);
        else
            gemm_h<false, 256, 2, 256><<<grid, 256, SMEM_BYTES>>>(
                A, B, C, M, N, K, lda, ldb, ldc, sA, sB, sC, sc, causal, klim,
                aidx, mdev, cidx, cs, pstride);
    } else {
        dim3 grid((N + 127) / 128, (M + 127) / 128, bz);
        if (outh)
            gemm_h<true, 128, 3, 128><<<grid, 128, SMEM_BYTES>>>(
                A, B, C, M, N, K, lda, ldb, ldc, sA, sB, sC, sc, causal, klim,
                aidx, mdev, cidx, cs, pstride);
        else
            gemm_h<false, 128, 3, 128><<<grid, 128, SMEM_BYTES>>>(
                A, B, C, M, N, K, lda, ldb, ldc, sA, sB, sC, sc, causal, klim,
                aidx, mdev, cidx, cs, pstride);
    }
}

static void launch_nt(bool wide, bool outh, const __half* A, const __half* B, void* C,
                      int M, int N, int K, int lda, int ldb, int ldc)
{
    launch_gemm(wide, outh, A, B, C, M, N, K, lda, ldb, ldc, 0, 0, 0, 1, 1.f, 0, 0,
                nullptr, nullptr, nullptr, nullptr, 0);
}

// ---------------------------------------------------------------------------
extern "C" void kernel_launch(void* const* d_in, const int* in_sizes, int n_in,
                              void* d_out, int out_size)
{
    const float* x    = (const float*)d_in[0];
    const float* skip = (const float*)d_in[1];
    const float* rsin = (const float*)d_in[2];
    const float* rcos = (const float*)d_in[3];
    const float* ln1  = (const float*)d_in[4];
    const float* ln2  = (const float*)d_in[5];
    const float* wqa  = (const float*)d_in[6];
    const float* qan  = (const float*)d_in[7];
    const float* wqb  = (const float*)d_in[8];
    const float* wkva = (const float*)d_in[9];
    const float* kvan = (const float*)d_in[10];
    const float* wkb  = (const float*)d_in[11];
    const float* wvb  = (const float*)d_in[12];
    const float* wo   = (const float*)d_in[13];
    const float* gw   = (const float*)d_in[14];
    const float* wup  = (const float*)d_in[15];
    const float* wdn  = (const float*)d_in[16];
    const float* wsup = (const float*)d_in[17];
    const float* wsdn = (const float*)d_in[18];
    float* out = (float*)d_out;

    Scratch* s = nullptr;
    cudaGetSymbolAddress((void**)&s, g_s);
    cudaFuncSetAttribute((const void*)gemm_h<true, 256, 2, 256>,
                         cudaFuncAttributeMaxDynamicSharedMemorySize, SMEM_BYTES);
    cudaFuncSetAttribute((const void*)gemm_h<false, 256, 2, 256>,
                         cudaFuncAttributeMaxDynamicSharedMemorySize, SMEM_BYTES);
    cudaFuncSetAttribute((const void*)gemm_h<true, 128, 3, 128>,
                         cudaFuncAttributeMaxDynamicSharedMemorySize, SMEM_BYTES);
    cudaFuncSetAttribute((const void*)gemm_h<false, 128, 3, 128>,
                         cudaFuncAttributeMaxDynamicSharedMemorySize, SMEM_BYTES);

    const int n = TT * HH;

    zero_counts_k<<<1, 32>>>();

    // weights -> half (vectorized)
    f2h_k<<<1024, 256>>>((const float4*)wqa,  (uint2*)s->wqa_h,  (long long)QLAT * HH / 4);
    f2h_k<<<1024, 256>>>((const float4*)wqb,  (uint2*)s->wqb_h,  (long long)NHH * DQK * QLAT / 4);
    f2h_k<<<1024, 256>>>((const float4*)wkva, (uint2*)s->wkva_h, (long long)(KVLAT + ROPED) * HH / 4);
    f2h_k<<<1024, 256>>>((const float4*)wkb,  (uint2*)s->wkb_h,  (long long)NHH * NOPE * KVLAT / 4);
    f2h_k<<<1024, 256>>>((const float4*)wvb,  (uint2*)s->wvb_h,  (long long)NHH * VDIM * KVLAT / 4);
    f2h_k<<<1024, 256>>>((const float4*)wo,   (uint2*)s->wo_h,   (long long)HH * NHH * VDIM / 4);
    f2h_k<<<1024, 256>>>((const float4*)wsup, (uint2*)s->wsup_h, (long long)2 * SHI * HH / 4);
    f2h_k<<<1024, 256>>>((const float4*)wsdn, (uint2*)s->wsdn_h, (long long)HH * SHI / 4);
    f2h_k<<<2048, 256>>>((const float4*)wup,  (uint2*)s->wup_h,  (long long)NE * 2 * MIDIM * HH / 4);
    f2h_k<<<2048, 256>>>((const float4*)wdn,  (uint2*)s->wdn_h,  (long long)NE * HH * MIDIM / 4);

    // x1 = x + skip ; n1h = rms(x1)
    add2_k<<<4096, 256>>>(x, skip, s->x1, n);
    rmsnorm_h_k<<<TT, 256>>>(s->x1, ln1, s->n1h, HH, HH, HH);

    // q path
    launch_nt(true, false, s->n1h, s->wqa_h, s->qa_pre, TT, QLAT, HH, HH, HH, QLAT);
    rmsnorm_h_k<<<TT, 256>>>(s->qa_pre, qan, s->qah, QLAT, QLAT, QLAT);
    launch_nt(true, true, s->qah, s->wqb_h, s->qh, TT, NHH * DQK, QLAT, QLAT, QLAT, NHH * DQK);
    rope_q_k<<<TT, 256>>>(s->qh, rsin, rcos);

    // kv path
    launch_nt(false, false, s->n1h, s->wkva_h, s->kv, TT, KVLAT + ROPED, HH, HH, HH, KVLAT + ROPED);
    rmsnorm_h_k<<<TT, 256>>>(s->kv, kvan, s->ckvh, KVLAT, KVLAT + ROPED, KVLAT);
    launch_nt(true, true, s->ckvh, s->wkb_h, s->knopeh, TT, NHH * NOPE, KVLAT, KVLAT, KVLAT, NHH * NOPE);
    build_k_k<<<TT, 256>>>(s->knopeh, s->kv, rsin, rcos, s->kfullh);
    // vT[h*128+d, t] = sum_k wvb[h*128+d, k] * ckv[t, k]
    launch_nt(true, true, s->wvb_h, s->ckvh, s->vTh, NHH * VDIM, TT, KVLAT, KVLAT, KVLAT, TT);

    // attention
    float attn_scale = 1.0f / sqrtf((float)DQK);
    launch_gemm(true, false, s->qh, s->kfullh, s->S, TT, TT, DQK,
                NHH * DQK, NHH * DQK, TT,
                DQK, DQK, (long long)TT * TT, NHH,
                attn_scale, /*causal=*/1, 0, nullptr, nullptr, nullptr, nullptr, 0);
    softmax_causal_k<<<dim3(TT, NHH), 256>>>();
    // O[q, h*128+d] = sum_k P[h][q,k] * vT[h*128+d, k]
    launch_gemm(false, true, s->Sh, s->vTh, s->oh, TT, VDIM, TT,
                TT, TT, NHH * VDIM,
                (long long)TT * TT, (long long)VDIM * TT, VDIM, NHH,
                1.f, 0, /*klim=*/1, nullptr, nullptr, nullptr, nullptr, 0);

    // attn out + residual -> x2 (output part 1)
    launch_nt(true, false, s->oh, s->wo_h, s->attn, TT, HH, NHH * VDIM, NHH * VDIM, NHH * VDIM, HH);
    x2_out_k<<<4096, 256>>>(s->x1, s->attn, s->x2, out, n);

    // n2 and MoE gating
    rmsnorm_h_k<<<TT, 256>>>(s->x2, ln2, s->n2h, HH, HH, HH);
    gate_topk_k<<<TT, 256>>>(s->n2h, gw);

    // shared FFN
    launch_nt(true, false, s->n2h, s->wsup_h, s->hs, TT, 2 * SHI, HH, HH, HH, 2 * SHI);
    silu_gate_k<<<TT, 256>>>(s->hs, s->hsah, SHI);
    launch_nt(true, false, s->hsah, s->wsdn_h, s->shared_o, TT, HH, SHI, SHI, SHI, HH);

    // routed experts: batched over blockIdx.z = expert
    launch_gemm(true, false, s->n2h, s->wup_h, s->h, TT, 2 * MIDIM, HH,
                HH, HH, 2 * MIDIM,
                0, (long long)(2 * MIDIM) * HH, (long long)TT * 2 * MIDIM, NE,
                1.f, 0, 0,
                s->tok, s->counts, nullptr, nullptr, TT);
    silu_gate_moe_k<<<dim3(TT, NE), 256>>>();
    launch_gemm(true, false, s->hah, s->wdn_h, s->routed2, TT, HH, MIDIM,
                MIDIM, MIDIM, HH,
                (long long)TT * MIDIM, (long long)HH * MIDIM, 0, NE,
                1.f, 0, 0,
                nullptr, s->counts, s->orow, s->ew, TT);

    // ffn = routed(slot0) + routed(slot1) + shared  (output part 2)
    combine_k<<<4096, 256>>>(s->routed2, s->shared_o, out + (long long)n, n);
}

// round 8
// speedup vs baseline: 1.0592x; 1.0592x over previous
#include <cuda_runtime.h>
#include <cuda_fp16.h>
#include <math.h>
#include <stdint.h>

#define TT   2048
#define HH   2048
#define NHH  16
#define NOPE 128
#define ROPED 64
#define DQK  192     // NOPE + ROPE
#define VDIM 128
#define QLAT 1536
#define KVLAT 512
#define NE   8
#define MIDIM 512
#define SHI  1024    // 2*MI

// ---------------------------------------------------------------------------
// Scratch (static device memory; no allocations anywhere)
// ---------------------------------------------------------------------------
struct __align__(128) Scratch {
    // f32 buffers
    float x1[TT * HH];
    float qa_pre[TT * QLAT];
    float kv[TT * (KVLAT + ROPED)];
    float S[(long long)NHH * TT * TT];   // 256 MB scores
    float attn[TT * HH];
    float x2[TT * HH];
    float h[(long long)NE * TT * 2 * MIDIM];
    float hs[TT * 2 * SHI];
    float routed2[2 * TT * HH];
    float shared_o[TT * HH];
    float ew[NE * TT];
    int   tok[NE * TT];
    int   orow[NE * TT];
    int   counts[NE];
    // half activation buffers
    __half n1h[TT * HH];
    __half qah[TT * QLAT];
    __half qh[TT * NHH * DQK];
    __half ckvh[TT * KVLAT];
    __half knopeh[TT * NHH * NOPE];
    __half kfullh[TT * NHH * DQK];
    __half vTh[NHH * VDIM * TT];          // [h*128+d, t]
    __half Sh[(long long)NHH * TT * TT];  // 128 MB probs
    __half oh[TT * NHH * VDIM];
    __half n2h[TT * HH];
    __half hsah[TT * SHI];
    __half hah[(long long)NE * TT * MIDIM];
    // half weight copies
    __half wqa_h[QLAT * HH];
    __half wqb_h[NHH * DQK * QLAT];
    __half wkva_h[(KVLAT + ROPED) * HH];
    __half wkb_h[NHH * NOPE * KVLAT];
    __half wvb_h[NHH * VDIM * KVLAT];
    __half wo_h[HH * NHH * VDIM];
    __half wsup_h[2 * SHI * HH];
    __half wsdn_h[HH * SHI];
    __half wup_h[(long long)NE * 2 * MIDIM * HH];
    __half wdn_h[(long long)NE * HH * MIDIM];
};
__device__ Scratch g_s;

// ---------------------------------------------------------------------------
// helpers
// ---------------------------------------------------------------------------
__device__ __forceinline__ uint32_t smem_u32(const void* p) {
    uint32_t a;
    asm("{ .reg .u64 t; cvta.to.shared.u64 t, %1; cvt.u32.u64 %0, t; }" : "=r"(a) : "l"(p));
    return a;
}

__device__ __forceinline__ void cp16(uint32_t dst, const void* src, int sz) {
    asm volatile("cp.async.cg.shared.global [%0], [%1], 16, %2;"
                 :: "r"(dst), "l"(src), "r"(sz));
}
__device__ __forceinline__ void cp_commit() {
    asm volatile("cp.async.commit_group;" ::: "memory");
}

__device__ __forceinline__ void ldm_x4(unsigned& r0, unsigned& r1, unsigned& r2,
                                       unsigned& r3, uint32_t addr) {
    asm volatile("ldmatrix.sync.aligned.m8n8.x4.shared.b16 {%0,%1,%2,%3}, [%4];"
                 : "=r"(r0), "=r"(r1), "=r"(r2), "=r"(r3) : "r"(addr));
}

__device__ __forceinline__ void mma_f16(float* d, const unsigned* a, const unsigned* b) {
    asm volatile(
        "mma.sync.aligned.m16n8k16.row.col.f32.f16.f16.f32 "
        "{%0,%1,%2,%3}, {%4,%5,%6,%7}, {%8,%9}, {%0,%1,%2,%3};\n"
        : "+f"(d[0]), "+f"(d[1]), "+f"(d[2]), "+f"(d[3])
        : "r"(a[0]), "r"(a[1]), "r"(a[2]), "r"(a[3]), "r"(b[0]), "r"(b[1]));
}

// ---------------------------------------------------------------------------
// fp16 NT GEMM: C[M,N] = scale * A[M,K] * B^T  (A:[M,K], B:[N,K] half)
// CTA 128 x NTILE, warp tile 64x64, ktile 64 halves, NSTAGE cp.async stages.
// smem: (128 + NTILE) rows x 128B, 16B-chunk swizzle ch^(row&7).
// narrow: NTILE=128, 128 thr, 3 stg (96KB, 2 CTA/SM)
// wide:   NTILE=256, 256 thr, 3 stg (144KB, 1 CTA/SM)
// ---------------------------------------------------------------------------
#define SMEM_NARROW 98304
#define SMEM_WIDE   147456

template <bool OUTH, int NTILE, int NSTAGE, int NTHREADS>
__global__ __launch_bounds__(NTHREADS)
void gemm_h(const __half* __restrict__ A, const __half* __restrict__ B,
            void* __restrict__ Cv,
            int M, int N, int K, int lda, int ldb, int ldc,
            long long sA, long long sB, long long sC,
            float scale, int causal, int klim,
            const int* __restrict__ aidx, const int* __restrict__ mdev,
            const int* __restrict__ cidx, const float* __restrict__ cscale,
            int pstride)
{
    constexpr int STG_BYTES = (128 + NTILE) * 128;
    constexpr int LOADS = (128 + NTILE) * 8 / NTHREADS;
    extern __shared__ __align__(128) char smem[];
    const int z = blockIdx.z;
    A += (long long)z * sA;
    B += (long long)z * sB;
    if (pstride) {
        if (mdev)   mdev   += z;
        if (aidx)   aidx   += (long long)z * pstride;
        if (cidx)   cidx   += (long long)z * pstride;
        if (cscale) cscale += (long long)z * pstride;
    }
    const int Meff = mdev ? *mdev : M;
    const int m0 = blockIdx.y * 128;
    const int n0 = blockIdx.x * NTILE;
    if (m0 >= Meff) return;
    if (causal && n0 > m0 + 127) return;
    const int kmax = klim ? min(K, m0 + 128) : K;
    const int ktiles = kmax >> 6;

    const uint32_t sbase = smem_u32(smem);
    const int tid = threadIdx.x;
    const int lane = tid & 31;
    const int wid = tid >> 5;
    const int wm = (wid & 1) * 64;
    const int wn = (wid >> 1) * 64;
    const int lr = lane >> 2;     // 0..7
    const int lm = lane & 3;      // 0..3

    float acc[4][8][4];
#pragma unroll
    for (int i = 0; i < 4; i++)
#pragma unroll
        for (int j = 0; j < 8; j++)
#pragma unroll
            for (int c = 0; c < 4; c++) acc[i][j][c] = 0.f;

    auto issue_stage = [&](int i) {
        const uint32_t base = sbase + (i % NSTAGE) * STG_BYTES;
        const int kt = i << 6;           // half offset
#pragma unroll
        for (int it = 0; it < LOADS; it++) {
            int c = tid + it * NTHREADS;
            int row = c >> 3, ch = c & 7;
            uint32_t dst = base + row * 128 + ((ch ^ (row & 7)) << 4);
            const __half* src;
            int sz = 0;
            if (row < 128) {
                int gm = m0 + row;
                src = A;
                if (gm < Meff) {
                    int ar = aidx ? aidx[gm] : gm;
                    src = A + (long long)ar * lda + kt + ch * 8;
                    sz = 16;
                }
            } else {
                int gn = n0 + row - 128;
                src = B;
                if (gn < N) {
                    src = B + (long long)gn * ldb + kt + ch * 8;
                    sz = 16;
                }
            }
            cp16(dst, src, sz);
        }
    };

#pragma unroll
    for (int s = 0; s < NSTAGE - 1; s++) {
        if (s < ktiles) issue_stage(s);
        cp_commit();
    }

    // ldmatrix lane address components
    const int a_row = lane & 15;
    const int a_h = lane >> 4;
    const int b_t = lane >> 3;
    const int b_r = lane & 7;

    for (int i = 0; i < ktiles; i++) {
        if (i + NSTAGE - 1 < ktiles) issue_stage(i + NSTAGE - 1);
        cp_commit();
        asm volatile("cp.async.wait_group %0;" :: "n"(NSTAGE - 1) : "memory");
        __syncthreads();

        const uint32_t base = sbase + (i % NSTAGE) * STG_BYTES;
#pragma unroll
        for (int kk = 0; kk < 4; kk++) {
            unsigned afr[4][4], bfr[8][2];
#pragma unroll
            for (int im = 0; im < 4; im++) {
                int row = wm + im * 16 + a_row;
                int ch = kk * 2 + a_h;
                ldm_x4(afr[im][0], afr[im][1], afr[im][2], afr[im][3],
                       base + row * 128 + ((ch ^ (row & 7)) << 4));
            }
#pragma unroll
            for (int j2 = 0; j2 < 4; j2++) {
                int jn = j2 * 2 + (b_t >> 1);
                int row = 128 + wn + jn * 8 + b_r;
                int ch = kk * 2 + (b_t & 1);
                unsigned r0, r1, r2, r3;
                ldm_x4(r0, r1, r2, r3, base + row * 128 + ((ch ^ (row & 7)) << 4));
                bfr[j2 * 2][0] = r0;     bfr[j2 * 2][1] = r1;
                bfr[j2 * 2 + 1][0] = r2; bfr[j2 * 2 + 1][1] = r3;
            }
#pragma unroll
            for (int im = 0; im < 4; im++)
#pragma unroll
                for (int jn = 0; jn < 8; jn++)
                    mma_f16(acc[im][jn], afr[im], bfr[jn]);
        }
        __syncthreads();
    }

    // epilogue
#pragma unroll
    for (int im = 0; im < 4; im++) {
#pragma unroll
        for (int part = 0; part < 2; part++) {
            int gm = m0 + wm + im * 16 + lr + part * 8;
            if (gm >= Meff) continue;
            long long crow = gm;
            float w = scale;
            if (cidx) { crow = cidx[gm]; w = scale * cscale[gm]; }
#pragma unroll
            for (int jn = 0; jn < 8; jn++) {
                int gn = n0 + wn + jn * 8 + lm * 2;
                if (gn >= N) continue;
                float vx = acc[im][jn][part * 2] * w;
                float vy = acc[im][jn][part * 2 + 1] * w;
                if (OUTH) {
                    __half* cp = (__half*)Cv + ((long long)z * sC) + crow * (long long)ldc + gn;
                    *reinterpret_cast<__half2*>(cp) = __floats2half2_rn(vx, vy);
                } else {
                    float* cp = (float*)Cv + ((long long)z * sC) + crow * (long long)ldc + gn;
                    *reinterpret_cast<float2*>(cp) = make_float2(vx, vy);
                }
            }
        }
    }
}

// ---------------------------------------------------------------------------
// Elementwise / reduction kernels
// ---------------------------------------------------------------------------
__global__ void zero_counts_k() {
    if (threadIdx.x < NE) g_s.counts[threadIdx.x] = 0;
}

// vectorized f32 -> f16 (n must be multiple of 4)
__global__ void f2h_k(const float4* __restrict__ in, uint2* __restrict__ out,
                      long long n4) {
    for (long long i = blockIdx.x * (long long)blockDim.x + threadIdx.x; i < n4;
         i += (long long)gridDim.x * blockDim.x) {
        float4 v = in[i];
        __half2 h0 = __floats2half2_rn(v.x, v.y);
        __half2 h1 = __floats2half2_rn(v.z, v.w);
        uint2 o;
        o.x = *reinterpret_cast<unsigned*>(&h0);
        o.y = *reinterpret_cast<unsigned*>(&h1);
        out[i] = o;
    }
}

__global__ void add2_k(const float* __restrict__ a, const float* __restrict__ b,
                       float* __restrict__ c, int n) {
    for (int i = blockIdx.x * blockDim.x + threadIdx.x; i < n; i += gridDim.x * blockDim.x)
        c[i] = a[i] + b[i];
}

__global__ void x2_out_k(const float* __restrict__ x1, const float* __restrict__ attn,
                         float* __restrict__ x2, float* __restrict__ dout, int n) {
    for (int i = blockIdx.x * blockDim.x + threadIdx.x; i < n; i += gridDim.x * blockDim.x) {
        float v = x1[i] + attn[i];
        x2[i] = v;
        dout[i] = v;
    }
}

__global__ void combine_k(const float* __restrict__ routed2, const float* __restrict__ sh,
                          float* __restrict__ dout, int n) {
    for (int i = blockIdx.x * blockDim.x + threadIdx.x; i < n; i += gridDim.x * blockDim.x)
        dout[i] = routed2[i] + routed2[n + i] + sh[i];
}

// f32 in -> half out
__global__ __launch_bounds__(256)
void rmsnorm_h_k(const float* __restrict__ in, const float* __restrict__ w,
                 __half* __restrict__ out, int cols, int instride, int outstride) {
    int row = blockIdx.x;
    const float* ip = in + (long long)row * instride;
    float ss = 0.f;
    for (int j = threadIdx.x; j < cols; j += 256) { float v = ip[j]; ss += v * v; }
    __shared__ float red[256];
    red[threadIdx.x] = ss;
    __syncthreads();
    for (int st = 128; st > 0; st >>= 1) {
        if (threadIdx.x < st) red[threadIdx.x] += red[threadIdx.x + st];
        __syncthreads();
    }
    float scale = rsqrtf(red[0] / (float)cols + 1e-6f);
    __half* op = out + (long long)row * outstride;
    for (int j = threadIdx.x; j < cols; j += 256)
        op[j] = __float2half_rn(ip[j] * scale * w[j]);
}

__global__ void rope_q_k(__half* __restrict__ q, const float* __restrict__ rsin,
                         const float* __restrict__ rcos) {
    int t = blockIdx.x;
    for (int i = threadIdx.x; i < NHH * 32; i += blockDim.x) {
        int h = i >> 5;
        int p = i & 31;
        __half* base = q + (long long)t * (NHH * DQK) + h * DQK + NOPE + 2 * p;
        float s = rsin[t * 32 + p], c = rcos[t * 32 + p];
        float a = __half2float(base[0]), b = __half2float(base[1]);
        base[0] = __float2half_rn(a * c - b * s);
        base[1] = __float2half_rn(a * s + b * c);
    }
}

__global__ void build_k_k(const __half* __restrict__ knope, const float* __restrict__ kv,
                          const float* __restrict__ rsin, const float* __restrict__ rcos,
                          __half* __restrict__ kfull) {
    int t = blockIdx.x;
    __shared__ __half pe[ROPED];
    if (threadIdx.x < 32) {
        int p = threadIdx.x;
        float a = kv[(long long)t * (KVLAT + ROPED) + KVLAT + 2 * p];
        float b = kv[(long long)t * (KVLAT + ROPED) + KVLAT + 2 * p + 1];
        float s = rsin[t * 32 + p], c = rcos[t * 32 + p];
        pe[2 * p]     = __float2half_rn(a * c - b * s);
        pe[2 * p + 1] = __float2half_rn(a * s + b * c);
    }
    __syncthreads();
    for (int i = threadIdx.x; i < NHH * DQK; i += blockDim.x) {
        int h = i / DQK;
        int d = i % DQK;
        kfull[(long long)t * (NHH * DQK) + i] =
            (d < NOPE) ? knope[(long long)t * (NHH * NOPE) + h * NOPE + d] : pe[d - NOPE];
    }
}

// softmax: f32 scores -> half probs, zero fill to tile end
__global__ __launch_bounds__(256)
void softmax_causal_k() {
    int qrow = blockIdx.x;
    int h = blockIdx.y;
    const float* row = g_s.S + ((long long)h * TT + qrow) * TT;
    __half* orow = g_s.Sh + ((long long)h * TT + qrow) * TT;
    int len = qrow + 1;
    int fill_end = (qrow & ~127) + 128;
    __shared__ float redm[256], reds[256];

    float m = -1e30f, sum = 0.f;
    for (int k = threadIdx.x; k < len; k += 256) {
        float v = row[k];
        if (v > m) { sum *= __expf(m - v); m = v; }
        sum += __expf(v - m);
    }
    redm[threadIdx.x] = m;
    reds[threadIdx.x] = sum;
    __syncthreads();
    for (int st = 128; st > 0; st >>= 1) {
        if (threadIdx.x < st) {
            float m2 = redm[threadIdx.x + st], s2 = reds[threadIdx.x + st];
            float m1 = redm[threadIdx.x], s1 = reds[threadIdx.x];
            float mm = fmaxf(m1, m2);
            redm[threadIdx.x] = mm;
            reds[threadIdx.x] = s1 * __expf(m1 - mm) + s2 * __expf(m2 - mm);
        }
        __syncthreads();
    }
    m = redm[0];
    float inv = 1.0f / reds[0];

    for (int k = threadIdx.x; k < len; k += 256)
        orow[k] = __float2half_rn(__expf(row[k] - m) * inv);
    for (int k = len + threadIdx.x; k < fill_end; k += 256)
        orow[k] = __float2half_rn(0.f);
}

__global__ __launch_bounds__(256)
void gate_topk_k(const __half* __restrict__ n2, const float* __restrict__ gw) {
    int t = blockIdx.x;
    __shared__ float logits[NE];
    int warp = threadIdx.x >> 5, lane = threadIdx.x & 31;
    const __half* xp = n2 + (long long)t * HH;
    const float* wp = gw + warp * HH;
    float s = 0.f;
    for (int k = lane; k < HH; k += 32) s += __half2float(xp[k]) * wp[k];
    for (int off = 16; off > 0; off >>= 1) s += __shfl_down_sync(0xffffffffu, s, off);
    if (lane == 0) logits[warp] = s;
    __syncthreads();
    if (threadIdx.x == 0) {
        float m = logits[0];
        for (int e = 1; e < NE; e++) m = fmaxf(m, logits[e]);
        float p[NE];
        float sum = 0.f;
        for (int e = 0; e < NE; e++) { p[e] = __expf(logits[e] - m); sum += p[e]; }
        for (int e = 0; e < NE; e++) p[e] /= sum;
        int i0 = 0;
        for (int e = 1; e < NE; e++) if (p[e] > p[i0]) i0 = e;
        int i1 = -1;
        for (int e = 0; e < NE; e++) {
            if (e == i0) continue;
            if (i1 < 0 || p[e] > p[i1]) i1 = e;
        }
        float w0 = p[i0], w1 = p[i1];
        float tot = w0 + w1;
        w0 /= tot; w1 /= tot;
        int pos0 = atomicAdd(&g_s.counts[i0], 1);
        g_s.tok[i0 * TT + pos0] = t;
        g_s.orow[i0 * TT + pos0] = t;
        g_s.ew[i0 * TT + pos0] = w0;
        int pos1 = atomicAdd(&g_s.counts[i1], 1);
        g_s.tok[i1 * TT + pos1] = t;
        g_s.orow[i1 * TT + pos1] = TT + t;
        g_s.ew[i1 * TT + pos1] = w1;
    }
}

__global__ void silu_gate_k(const float* __restrict__ in, __half* __restrict__ out,
                            int half_) {
    int row = blockIdx.x;
    const float* ip = in + (long long)row * 2 * half_;
    __half* op = out + (long long)row * half_;
    for (int j = threadIdx.x; j < half_; j += blockDim.x) {
        float a = ip[j], b = ip[half_ + j];
        op[j] = __float2half_rn((a / (1.f + __expf(-a))) * b);
    }
}

__global__ void silu_gate_moe_k() {
    int e = blockIdx.y;
    int row = blockIdx.x;
    if (row >= g_s.counts[e]) return;
    const float* ip = g_s.h + ((long long)e * TT + row) * (2 * MIDIM);
    __half* op = g_s.hah + ((long long)e * TT + row) * MIDIM;
    for (int j = threadIdx.x; j < MIDIM; j += blockDim.x) {
        float a = ip[j], b = ip[MIDIM + j];
        op[j] = __float2half_rn((a / (1.f + __expf(-a))) * b);
    }
}

// ---------------------------------------------------------------------------
// Host-side launch helpers
// ---------------------------------------------------------------------------
static void launch_gemm(bool wide, bool outh, const __half* A, const __half* B, void* C,
                        int M, int N, int K, int lda, int ldb, int ldc,
                        long long sA, long long sB, long long sC, int bz,
                        float sc, int causal, int klim,
                        const int* aidx, const int* mdev,
                        const int* cidx, const float* cs, int pstride)
{
    if (wide) {
        dim3 grid((N + 255) / 256, (M + 127) / 128, bz);
        if (outh)
            gemm_h<true, 256, 3, 256><<<grid, 256, SMEM_WIDE>>>(
                A, B, C, M, N, K, lda, ldb, ldc, sA, sB, sC, sc, causal, klim,
                aidx, mdev, cidx, cs, pstride);
        else
            gemm_h<false, 256, 3, 256><<<grid, 256, SMEM_WIDE>>>(
                A, B, C, M, N, K, lda, ldb, ldc, sA, sB, sC, sc, causal, klim,
                aidx, mdev, cidx, cs, pstride);
    } else {
        dim3 grid((N + 127) / 128, (M + 127) / 128, bz);
        if (outh)
            gemm_h<true, 128, 3, 128><<<grid, 128, SMEM_NARROW>>>(
                A, B, C, M, N, K, lda, ldb, ldc, sA, sB, sC, sc, causal, klim,
                aidx, mdev, cidx, cs, pstride);
        else
            gemm_h<false, 128, 3, 128><<<grid, 128, SMEM_NARROW>>>(
                A, B, C, M, N, K, lda, ldb, ldc, sA, sB, sC, sc, causal, klim,
                aidx, mdev, cidx, cs, pstride);
    }
}

static void launch_nt(bool wide, bool outh, const __half* A, const __half* B, void* C,
                      int M, int N, int K, int lda, int ldb, int ldc)
{
    launch_gemm(wide, outh, A, B, C, M, N, K, lda, ldb, ldc, 0, 0, 0, 1, 1.f, 0, 0,
                nullptr, nullptr, nullptr, nullptr, 0);
}

// ---------------------------------------------------------------------------
extern "C" void kernel_launch(void* const* d_in, const int* in_sizes, int n_in,
                              void* d_out, int out_size)
{
    const float* x    = (const float*)d_in[0];
    const float* skip = (const float*)d_in[1];
    const float* rsin = (const float*)d_in[2];
    const float* rcos = (const float*)d_in[3];
    const float* ln1  = (const float*)d_in[4];
    const float* ln2  = (const float*)d_in[5];
    const float* wqa  = (const float*)d_in[6];
    const float* qan  = (const float*)d_in[7];
    const float* wqb  = (const float*)d_in[8];
    const float* wkva = (const float*)d_in[9];
    const float* kvan = (const float*)d_in[10];
    const float* wkb  = (const float*)d_in[11];
    const float* wvb  = (const float*)d_in[12];
    const float* wo   = (const float*)d_in[13];
    const float* gw   = (const float*)d_in[14];
    const float* wup  = (const float*)d_in[15];
    const float* wdn  = (const float*)d_in[16];
    const float* wsup = (const float*)d_in[17];
    const float* wsdn = (const float*)d_in[18];
    float* out = (float*)d_out;

    Scratch* s = nullptr;
    cudaGetSymbolAddress((void**)&s, g_s);
    cudaFuncSetAttribute((const void*)gemm_h<true, 256, 3, 256>,
                         cudaFuncAttributeMaxDynamicSharedMemorySize, SMEM_WIDE);
    cudaFuncSetAttribute((const void*)gemm_h<false, 256, 3, 256>,
                         cudaFuncAttributeMaxDynamicSharedMemorySize, SMEM_WIDE);
    cudaFuncSetAttribute((const void*)gemm_h<true, 128, 3, 128>,
                         cudaFuncAttributeMaxDynamicSharedMemorySize, SMEM_NARROW);
    cudaFuncSetAttribute((const void*)gemm_h<false, 128, 3, 128>,
                         cudaFuncAttributeMaxDynamicSharedMemorySize, SMEM_NARROW);

    const int n = TT * HH;

    zero_counts_k<<<1, 32>>>();

    // weights -> half (vectorized)
    f2h_k<<<1024, 256>>>((const float4*)wqa,  (uint2*)s->wqa_h,  (long long)QLAT * HH / 4);
    f2h_k<<<1024, 256>>>((const float4*)wqb,  (uint2*)s->wqb_h,  (long long)NHH * DQK * QLAT / 4);
    f2h_k<<<1024, 256>>>((const float4*)wkva, (uint2*)s->wkva_h, (long long)(KVLAT + ROPED) * HH / 4);
    f2h_k<<<1024, 256>>>((const float4*)wkb,  (uint2*)s->wkb_h,  (long long)NHH * NOPE * KVLAT / 4);
    f2h_k<<<1024, 256>>>((const float4*)wvb,  (uint2*)s->wvb_h,  (long long)NHH * VDIM * KVLAT / 4);
    f2h_k<<<1024, 256>>>((const float4*)wo,   (uint2*)s->wo_h,   (long long)HH * NHH * VDIM / 4);
    f2h_k<<<1024, 256>>>((const float4*)wsup, (uint2*)s->wsup_h, (long long)2 * SHI * HH / 4);
    f2h_k<<<1024, 256>>>((const float4*)wsdn, (uint2*)s->wsdn_h, (long long)HH * SHI / 4);
    f2h_k<<<2048, 256>>>((const float4*)wup,  (uint2*)s->wup_h,  (long long)NE * 2 * MIDIM * HH / 4);
    f2h_k<<<2048, 256>>>((const float4*)wdn,  (uint2*)s->wdn_h,  (long long)NE * HH * MIDIM / 4);

    // x1 = x + skip ; n1h = rms(x1)
    add2_k<<<4096, 256>>>(x, skip, s->x1, n);
    rmsnorm_h_k<<<TT, 256>>>(s->x1, ln1, s->n1h, HH, HH, HH);

    // q path
    launch_nt(true, false, s->n1h, s->wqa_h, s->qa_pre, TT, QLAT, HH, HH, HH, QLAT);
    rmsnorm_h_k<<<TT, 256>>>(s->qa_pre, qan, s->qah, QLAT, QLAT, QLAT);
    launch_nt(true, true, s->qah, s->wqb_h, s->qh, TT, NHH * DQK, QLAT, QLAT, QLAT, NHH * DQK);
    rope_q_k<<<TT, 256>>>(s->qh, rsin, rcos);

    // kv path
    launch_nt(false, false, s->n1h, s->wkva_h, s->kv, TT, KVLAT + ROPED, HH, HH, HH, KVLAT + ROPED);
    rmsnorm_h_k<<<TT, 256>>>(s->kv, kvan, s->ckvh, KVLAT, KVLAT + ROPED, KVLAT);
    launch_nt(true, true, s->ckvh, s->wkb_h, s->knopeh, TT, NHH * NOPE, KVLAT, KVLAT, KVLAT, NHH * NOPE);
    build_k_k<<<TT, 256>>>(s->knopeh, s->kv, rsin, rcos, s->kfullh);
    // vT[h*128+d, t] = sum_k wvb[h*128+d, k] * ckv[t, k]
    launch_nt(true, true, s->wvb_h, s->ckvh, s->vTh, NHH * VDIM, TT, KVLAT, KVLAT, KVLAT, TT);

    // attention
    float attn_scale = 1.0f / sqrtf((float)DQK);
    launch_gemm(true, false, s->qh, s->kfullh, s->S, TT, TT, DQK,
                NHH * DQK, NHH * DQK, TT,
                DQK, DQK, (long long)TT * TT, NHH,
                attn_scale, /*causal=*/1, 0, nullptr, nullptr, nullptr, nullptr, 0);
    softmax_causal_k<<<dim3(TT, NHH), 256>>>();
    // O[q, h*128+d] = sum_k P[h][q,k] * vT[h*128+d, k]
    launch_gemm(false, true, s->Sh, s->vTh, s->oh, TT, VDIM, TT,
                TT, TT, NHH * VDIM,
                (long long)TT * TT, (long long)VDIM * TT, VDIM, NHH,
                1.f, 0, /*klim=*/1, nullptr, nullptr, nullptr, nullptr, 0);

    // attn out + residual -> x2 (output part 1)
    launch_nt(true, false, s->oh, s->wo_h, s->attn, TT, HH, NHH * VDIM, NHH * VDIM, NHH * VDIM, HH);
    x2_out_k<<<4096, 256>>>(s->x1, s->attn, s->x2, out, n);

    // n2 and MoE gating
    rmsnorm_h_k<<<TT, 256>>>(s->x2, ln2, s->n2h, HH, HH, HH);
    gate_topk_k<<<TT, 256>>>(s->n2h, gw);

    // shared FFN
    launch_nt(true, false, s->n2h, s->wsup_h, s->hs, TT, 2 * SHI, HH, HH, HH, 2 * SHI);
    silu_gate_k<<<TT, 256>>>(s->hs, s->hsah, SHI);
    launch_nt(true, false, s->hsah, s->wsdn_h, s->shared_o, TT, HH, SHI, SHI, SHI, HH);

    // routed experts: batched over blockIdx.z = expert
    launch_gemm(true, false, s->n2h, s->wup_h, s->h, TT, 2 * MIDIM, HH,
                HH, HH, 2 * MIDIM,
                0, (long long)(2 * MIDIM) * HH, (long long)TT * 2 * MIDIM, NE,
                1.f, 0, 0,
                s->tok, s->counts, nullptr, nullptr, TT);
    silu_gate_moe_k<<<dim3(TT, NE), 256>>>();
    launch_gemm(true, false, s->hah, s->wdn_h, s->routed2, TT, HH, MIDIM,
                MIDIM, MIDIM, HH,
                (long long)TT * MIDIM, (long long)HH * MIDIM, 0, NE,
                1.f, 0, 0,
                nullptr, s->counts, s->orow, s->ew, TT);

    // ffn = routed(slot0) + routed(slot1) + shared  (output part 2)
    combine_k<<<4096, 256>>>(s->routed2, s->shared_o, out + (long long)n, n);
}

// round 9
// speedup vs baseline: 1.1848x; 1.1186x over previous
#include <cuda_runtime.h>
#include <cuda_fp16.h>
#include <math.h>
#include <stdint.h>

#define TT   2048
#define HH   2048
#define NHH  16
#define NOPE 128
#define ROPED 64
#define DQK  192     // NOPE + ROPE
#define VDIM 128
#define QLAT 1536
#define KVLAT 512
#define NE   8
#define MIDIM 512
#define SHI  1024    // 2*MI

// ---------------------------------------------------------------------------
// Scratch (static device memory; no allocations anywhere)
// ---------------------------------------------------------------------------
struct __align__(128) Scratch {
    // f32 buffers
    float x1[TT * HH];
    float qa_pre[TT * QLAT];
    float kv[TT * (KVLAT + ROPED)];
    float attn[TT * HH];
    float x2[TT * HH];
    float h[(long long)NE * TT * 2 * MIDIM];
    float hs[TT * 2 * SHI];
    float routed2[2 * TT * HH];
    float shared_o[TT * HH];
    float ew[NE * TT];
    int   tok[NE * TT];
    int   orow[NE * TT];
    int   counts[NE];
    // half activation buffers
    __half n1h[TT * HH];
    __half qah[TT * QLAT];
    __half qh[TT * NHH * DQK];
    __half ckvh[TT * KVLAT];
    __half knopeh[TT * NHH * NOPE];
    __half kfullh[TT * NHH * DQK];
    __half vTh[NHH * VDIM * TT];          // [h*128+d, t]
    __half oh[TT * NHH * VDIM];
    __half n2h[TT * HH];
    __half hsah[TT * SHI];
    __half hah[(long long)NE * TT * MIDIM];
    // half weight copies
    __half wqa_h[QLAT * HH];
    __half wqb_h[NHH * DQK * QLAT];
    __half wkva_h[(KVLAT + ROPED) * HH];
    __half wkb_h[NHH * NOPE * KVLAT];
    __half wvb_h[NHH * VDIM * KVLAT];
    __half wo_h[HH * NHH * VDIM];
    __half wsup_h[2 * SHI * HH];
    __half wsdn_h[HH * SHI];
    __half wup_h[(long long)NE * 2 * MIDIM * HH];
    __half wdn_h[(long long)NE * HH * MIDIM];
};
__device__ Scratch g_s;

// ---------------------------------------------------------------------------
// helpers
// ---------------------------------------------------------------------------
__device__ __forceinline__ uint32_t smem_u32(const void* p) {
    uint32_t a;
    asm("{ .reg .u64 t; cvta.to.shared.u64 t, %1; cvt.u32.u64 %0, t; }" : "=r"(a) : "l"(p));
    return a;
}

__device__ __forceinline__ void cp16(uint32_t dst, const void* src, int sz) {
    asm volatile("cp.async.cg.shared.global [%0], [%1], 16, %2;"
                 :: "r"(dst), "l"(src), "r"(sz));
}
__device__ __forceinline__ void cp_commit() {
    asm volatile("cp.async.commit_group;" ::: "memory");
}

__device__ __forceinline__ void ldm_x4(unsigned& r0, unsigned& r1, unsigned& r2,
                                       unsigned& r3, uint32_t addr) {
    asm volatile("ldmatrix.sync.aligned.m8n8.x4.shared.b16 {%0,%1,%2,%3}, [%4];"
                 : "=r"(r0), "=r"(r1), "=r"(r2), "=r"(r3) : "r"(addr));
}

__device__ __forceinline__ void mma_f16(float* d, const unsigned* a, const unsigned* b) {
    asm volatile(
        "mma.sync.aligned.m16n8k16.row.col.f32.f16.f16.f32 "
        "{%0,%1,%2,%3}, {%4,%5,%6,%7}, {%8,%9}, {%0,%1,%2,%3};\n"
        : "+f"(d[0]), "+f"(d[1]), "+f"(d[2]), "+f"(d[3])
        : "r"(a[0]), "r"(a[1]), "r"(a[2]), "r"(a[3]), "r"(b[0]), "r"(b[1]));
}

__device__ __forceinline__ unsigned packh2(float x, float y) {
    __half2 h = __floats2half2_rn(x, y);
    return *reinterpret_cast<unsigned*>(&h);
}

// ---------------------------------------------------------------------------
// fp16 NT GEMM (identical to the 881us R5 config)
// ---------------------------------------------------------------------------
#define SMEM_BYTES 98304

template <bool OUTH, int NTILE, int NSTAGE, int NTHREADS>
__global__ __launch_bounds__(NTHREADS)
void gemm_h(const __half* __restrict__ A, const __half* __restrict__ B,
            void* __restrict__ Cv,
            int M, int N, int K, int lda, int ldb, int ldc,
            long long sA, long long sB, long long sC,
            float scale, int causal, int klim,
            const int* __restrict__ aidx, const int* __restrict__ mdev,
            const int* __restrict__ cidx, const float* __restrict__ cscale,
            int pstride)
{
    constexpr int STG_BYTES = (128 + NTILE) * 128;
    constexpr int LOADS = (128 + NTILE) * 8 / NTHREADS;
    extern __shared__ __align__(128) char smem[];
    const int z = blockIdx.z;
    A += (long long)z * sA;
    B += (long long)z * sB;
    if (pstride) {
        if (mdev)   mdev   += z;
        if (aidx)   aidx   += (long long)z * pstride;
        if (cidx)   cidx   += (long long)z * pstride;
        if (cscale) cscale += (long long)z * pstride;
    }
    const int Meff = mdev ? *mdev : M;
    const int m0 = blockIdx.y * 128;
    const int n0 = blockIdx.x * NTILE;
    if (m0 >= Meff) return;
    if (causal && n0 > m0 + 127) return;
    const int kmax = klim ? min(K, m0 + 128) : K;
    const int ktiles = kmax >> 6;

    const uint32_t sbase = smem_u32(smem);
    const int tid = threadIdx.x;
    const int lane = tid & 31;
    const int wid = tid >> 5;
    const int wm = (wid & 1) * 64;
    const int wn = (wid >> 1) * 64;
    const int lr = lane >> 2;
    const int lm = lane & 3;

    float acc[4][8][4];
#pragma unroll
    for (int i = 0; i < 4; i++)
#pragma unroll
        for (int j = 0; j < 8; j++)
#pragma unroll
            for (int c = 0; c < 4; c++) acc[i][j][c] = 0.f;

    auto issue_stage = [&](int i) {
        const uint32_t base = sbase + (i % NSTAGE) * STG_BYTES;
        const int kt = i << 6;
#pragma unroll
        for (int it = 0; it < LOADS; it++) {
            int c = tid + it * NTHREADS;
            int row = c >> 3, ch = c & 7;
            uint32_t dst = base + row * 128 + ((ch ^ (row & 7)) << 4);
            const __half* src;
            int sz = 0;
            if (row < 128) {
                int gm = m0 + row;
                src = A;
                if (gm < Meff) {
                    int ar = aidx ? aidx[gm] : gm;
                    src = A + (long long)ar * lda + kt + ch * 8;
                    sz = 16;
                }
            } else {
                int gn = n0 + row - 128;
                src = B;
                if (gn < N) {
                    src = B + (long long)gn * ldb + kt + ch * 8;
                    sz = 16;
                }
            }
            cp16(dst, src, sz);
        }
    };

#pragma unroll
    for (int s = 0; s < NSTAGE - 1; s++) {
        if (s < ktiles) issue_stage(s);
        cp_commit();
    }

    const int a_row = lane & 15;
    const int a_h = lane >> 4;
    const int b_t = lane >> 3;
    const int b_r = lane & 7;

    for (int i = 0; i < ktiles; i++) {
        if (i + NSTAGE - 1 < ktiles) issue_stage(i + NSTAGE - 1);
        cp_commit();
        if (NSTAGE == 2)
            asm volatile("cp.async.wait_group 1;" ::: "memory");
        else
            asm volatile("cp.async.wait_group 2;" ::: "memory");
        __syncthreads();

        const uint32_t base = sbase + (i % NSTAGE) * STG_BYTES;
#pragma unroll
        for (int kk = 0; kk < 4; kk++) {
            unsigned afr[4][4], bfr[8][2];
#pragma unroll
            for (int im = 0; im < 4; im++) {
                int row = wm + im * 16 + a_row;
                int ch = kk * 2 + a_h;
                ldm_x4(afr[im][0], afr[im][1], afr[im][2], afr[im][3],
                       base + row * 128 + ((ch ^ (row & 7)) << 4));
            }
#pragma unroll
            for (int j2 = 0; j2 < 4; j2++) {
                int jn = j2 * 2 + (b_t >> 1);
                int row = 128 + wn + jn * 8 + b_r;
                int ch = kk * 2 + (b_t & 1);
                unsigned r0, r1, r2, r3;
                ldm_x4(r0, r1, r2, r3, base + row * 128 + ((ch ^ (row & 7)) << 4));
                bfr[j2 * 2][0] = r0;     bfr[j2 * 2][1] = r1;
                bfr[j2 * 2 + 1][0] = r2; bfr[j2 * 2 + 1][1] = r3;
            }
#pragma unroll
            for (int im = 0; im < 4; im++)
#pragma unroll
                for (int jn = 0; jn < 8; jn++)
                    mma_f16(acc[im][jn], afr[im], bfr[jn]);
        }
        __syncthreads();
    }

#pragma unroll
    for (int im = 0; im < 4; im++) {
#pragma unroll
        for (int part = 0; part < 2; part++) {
            int gm = m0 + wm + im * 16 + lr + part * 8;
            if (gm >= Meff) continue;
            long long crow = gm;
            float w = scale;
            if (cidx) { crow = cidx[gm]; w = scale * cscale[gm]; }
#pragma unroll
            for (int jn = 0; jn < 8; jn++) {
                int gn = n0 + wn + jn * 8 + lm * 2;
                if (gn >= N) continue;
                float vx = acc[im][jn][part * 2] * w;
                float vy = acc[im][jn][part * 2 + 1] * w;
                if (OUTH) {
                    __half* cp = (__half*)Cv + ((long long)z * sC) + crow * (long long)ldc + gn;
                    *reinterpret_cast<__half2*>(cp) = __floats2half2_rn(vx, vy);
                } else {
                    float* cp = (float*)Cv + ((long long)z * sC) + crow * (long long)ldc + gn;
                    *reinterpret_cast<float2*>(cp) = make_float2(vx, vy);
                }
            }
        }
    }
}

// ---------------------------------------------------------------------------
// Flash attention: CTA = (head, 128 q rows); k-blocks of 64, online softmax.
// Q tile resident (128x384B), K (64x384B) + Vt (128x128B) double buffered.
// ---------------------------------------------------------------------------
#define SMEM_FLASH 131072

__global__ __launch_bounds__(128, 1)
void flash_attn_k(const __half* __restrict__ Q, const __half* __restrict__ K,
                  const __half* __restrict__ Vt, __half* __restrict__ O,
                  float scale)
{
    extern __shared__ __align__(128) char smem[];
    const int h = blockIdx.x;
    const int qb = (int)gridDim.y - 1 - (int)blockIdx.y;   // heaviest first
    const int nkb = 2 * qb + 2;
    const uint32_t sb = smem_u32(smem);
    const uint32_t Qs = sb;                  // 49152
    const uint32_t Ks = sb + 49152;          // 2 x 24576
    const uint32_t Vs = sb + 49152 + 49152;  // 2 x 16384
    const int tid = threadIdx.x, lane = tid & 31, wid = tid >> 5;
    const int wq = wid * 32;
    const int lr = lane >> 2, lm = lane & 3;

    // load Q tile (rows qb*128.., head h)
    for (int c = tid; c < 3072; c += 128) {
        int row = c / 24, kc = c % 24;
        int sub = kc >> 3, ch = kc & 7;
        cp16(Qs + row * 384 + sub * 128 + ((ch ^ (row & 7)) << 4),
             Q + ((long long)(qb * 128 + row) * (NHH * DQK) + h * DQK + kc * 8), 16);
    }
    auto load_kv = [&](int kb) {
        int buf = kb & 1;
        for (int c = tid; c < 1536; c += 128) {
            int row = c / 24, kc = c % 24;
            int sub = kc >> 3, ch = kc & 7;
            cp16(Ks + buf * 24576 + row * 384 + sub * 128 + ((ch ^ (row & 7)) << 4),
                 K + ((long long)(kb * 64 + row) * (NHH * DQK) + h * DQK + kc * 8), 16);
        }
        for (int c = tid; c < 1024; c += 128) {
            int row = c >> 3, ch = c & 7;
            cp16(Vs + buf * 16384 + row * 128 + ((ch ^ (row & 7)) << 4),
                 Vt + ((long long)(h * 128 + row) * TT + kb * 64 + ch * 8), 16);
        }
    };

    load_kv(0);
    cp_commit();

    float m_s[2][2], l_s[2][2];
    float acc[2][16][4];
#pragma unroll
    for (int im = 0; im < 2; im++)
#pragma unroll
        for (int p = 0; p < 2; p++) { m_s[im][p] = -1e30f; l_s[im][p] = 0.f; }
#pragma unroll
    for (int im = 0; im < 2; im++)
#pragma unroll
        for (int dn = 0; dn < 16; dn++)
#pragma unroll
            for (int c = 0; c < 4; c++) acc[im][dn][c] = 0.f;

    const int a_row = lane & 15, a_h = lane >> 4;
    const int b_t = lane >> 3, b_r = lane & 7;

    for (int kb = 0; kb < nkb; kb++) {
        if (kb + 1 < nkb) load_kv(kb + 1);
        cp_commit();
        asm volatile("cp.async.wait_group 1;" ::: "memory");
        __syncthreads();
        const uint32_t kbase = Ks + (kb & 1) * 24576;
        const uint32_t vbase = Vs + (kb & 1) * 16384;

        // S = Q K^T  (warp: 32 q x 64 k)
        float s[2][8][4];
#pragma unroll
        for (int im = 0; im < 2; im++)
#pragma unroll
            for (int jn = 0; jn < 8; jn++)
#pragma unroll
                for (int c = 0; c < 4; c++) s[im][jn][c] = 0.f;

#pragma unroll
        for (int ks = 0; ks < 12; ks++) {
            unsigned afr[2][4], bfr[8][2];
#pragma unroll
            for (int im = 0; im < 2; im++) {
                int row = wq + im * 16 + a_row;
                int kc = ks * 2 + a_h;
                ldm_x4(afr[im][0], afr[im][1], afr[im][2], afr[im][3],
                       Qs + row * 384 + (kc >> 3) * 128 + (((kc & 7) ^ (row & 7)) << 4));
            }
#pragma unroll
            for (int j2 = 0; j2 < 4; j2++) {
                int jn = j2 * 2 + (b_t >> 1);
                int row = jn * 8 + b_r;
                int kc = ks * 2 + (b_t & 1);
                unsigned r0, r1, r2, r3;
                ldm_x4(r0, r1, r2, r3,
                       kbase + row * 384 + (kc >> 3) * 128 + (((kc & 7) ^ (row & 7)) << 4));
                bfr[j2 * 2][0] = r0;     bfr[j2 * 2][1] = r1;
                bfr[j2 * 2 + 1][0] = r2; bfr[j2 * 2 + 1][1] = r3;
            }
#pragma unroll
            for (int im = 0; im < 2; im++)
#pragma unroll
                for (int jn = 0; jn < 8; jn++)
                    mma_f16(s[im][jn], afr[im], bfr[jn]);
        }

        // scale + causal mask + online softmax
        const int coff = kb * 64 - qb * 128;
        float alpha[2][2];
#pragma unroll
        for (int im = 0; im < 2; im++) {
#pragma unroll
            for (int part = 0; part < 2; part++) {
                int r = wq + im * 16 + lr + part * 8;
                float mx = -1e30f;
#pragma unroll
                for (int jn = 0; jn < 8; jn++) {
#pragma unroll
                    for (int q = 0; q < 2; q++) {
                        int c = jn * 8 + lm * 2 + q;
                        float v = s[im][jn][part * 2 + q] * scale;
                        if (c + coff > r) v = -1e30f;
                        s[im][jn][part * 2 + q] = v;
                        mx = fmaxf(mx, v);
                    }
                }
                mx = fmaxf(mx, __shfl_xor_sync(0xffffffffu, mx, 1));
                mx = fmaxf(mx, __shfl_xor_sync(0xffffffffu, mx, 2));
                float mo = m_s[im][part];
                float mn = fmaxf(mo, mx);
                float al = __expf(mo - mn);
                float sum = 0.f;
#pragma unroll
                for (int jn = 0; jn < 8; jn++) {
#pragma unroll
                    for (int q = 0; q < 2; q++) {
                        float p = __expf(s[im][jn][part * 2 + q] - mn);
                        s[im][jn][part * 2 + q] = p;
                        sum += p;
                    }
                }
                sum += __shfl_xor_sync(0xffffffffu, sum, 1);
                sum += __shfl_xor_sync(0xffffffffu, sum, 2);
                l_s[im][part] = l_s[im][part] * al + sum;
                m_s[im][part] = mn;
                alpha[im][part] = al;
            }
        }
        // rescale O accumulators
#pragma unroll
        for (int im = 0; im < 2; im++)
#pragma unroll
            for (int dn = 0; dn < 16; dn++) {
                acc[im][dn][0] *= alpha[im][0];
                acc[im][dn][1] *= alpha[im][0];
                acc[im][dn][2] *= alpha[im][1];
                acc[im][dn][3] *= alpha[im][1];
            }

        // O += P @ V  (P in regs -> A frags; V from smem)
#pragma unroll
        for (int kv = 0; kv < 4; kv++) {
            unsigned ap[2][4];
#pragma unroll
            for (int im = 0; im < 2; im++) {
                ap[im][0] = packh2(s[im][2 * kv][0], s[im][2 * kv][1]);
                ap[im][1] = packh2(s[im][2 * kv][2], s[im][2 * kv][3]);
                ap[im][2] = packh2(s[im][2 * kv + 1][0], s[im][2 * kv + 1][1]);
                ap[im][3] = packh2(s[im][2 * kv + 1][2], s[im][2 * kv + 1][3]);
            }
#pragma unroll
            for (int j2 = 0; j2 < 8; j2++) {
                int dn = j2 * 2 + (b_t >> 1);
                int row = dn * 8 + b_r;
                int ch = kv * 2 + (b_t & 1);
                unsigned r0, r1, r2, r3;
                ldm_x4(r0, r1, r2, r3, vbase + row * 128 + ((ch ^ (row & 7)) << 4));
                unsigned bv0[2] = {r0, r1}, bv1[2] = {r2, r3};
#pragma unroll
                for (int im = 0; im < 2; im++) {
                    mma_f16(acc[im][j2 * 2], ap[im], bv0);
                    mma_f16(acc[im][j2 * 2 + 1], ap[im], bv1);
                }
            }
        }
        __syncthreads();
    }

    // epilogue: O = acc / l
#pragma unroll
    for (int im = 0; im < 2; im++) {
#pragma unroll
        for (int part = 0; part < 2; part++) {
            float inv = 1.0f / l_s[im][part];
            int grow = qb * 128 + wq + im * 16 + lr + part * 8;
            __half* op = O + (long long)grow * (NHH * VDIM) + h * VDIM;
#pragma unroll
            for (int dn = 0; dn < 16; dn++) {
                int col = dn * 8 + lm * 2;
                *reinterpret_cast<__half2*>(op + col) =
                    __floats2half2_rn(acc[im][dn][part * 2] * inv,
                                      acc[im][dn][part * 2 + 1] * inv);
            }
        }
    }
}

// ---------------------------------------------------------------------------
// Elementwise / reduction kernels
// ---------------------------------------------------------------------------
__global__ void zero_counts_k() {
    if (threadIdx.x < NE) g_s.counts[threadIdx.x] = 0;
}

__global__ void f2h_k(const float4* __restrict__ in, uint2* __restrict__ out,
                      long long n4) {
    for (long long i = blockIdx.x * (long long)blockDim.x + threadIdx.x; i < n4;
         i += (long long)gridDim.x * blockDim.x) {
        float4 v = in[i];
        __half2 h0 = __floats2half2_rn(v.x, v.y);
        __half2 h1 = __floats2half2_rn(v.z, v.w);
        uint2 o;
        o.x = *reinterpret_cast<unsigned*>(&h0);
        o.y = *reinterpret_cast<unsigned*>(&h1);
        out[i] = o;
    }
}

__global__ void add2_k(const float* __restrict__ a, const float* __restrict__ b,
                       float* __restrict__ c, int n) {
    for (int i = blockIdx.x * blockDim.x + threadIdx.x; i < n; i += gridDim.x * blockDim.x)
        c[i] = a[i] + b[i];
}

__global__ void x2_out_k(const float* __restrict__ x1, const float* __restrict__ attn,
                         float* __restrict__ x2, float* __restrict__ dout, int n) {
    for (int i = blockIdx.x * blockDim.x + threadIdx.x; i < n; i += gridDim.x * blockDim.x) {
        float v = x1[i] + attn[i];
        x2[i] = v;
        dout[i] = v;
    }
}

__global__ void combine_k(const float* __restrict__ routed2, const float* __restrict__ sh,
                          float* __restrict__ dout, int n) {
    for (int i = blockIdx.x * blockDim.x + threadIdx.x; i < n; i += gridDim.x * blockDim.x)
        dout[i] = routed2[i] + routed2[n + i] + sh[i];
}

__global__ __launch_bounds__(256)
void rmsnorm_h_k(const float* __restrict__ in, const float* __restrict__ w,
                 __half* __restrict__ out, int cols, int instride, int outstride) {
    int row = blockIdx.x;
    const float* ip = in + (long long)row * instride;
    float ss = 0.f;
    for (int j = threadIdx.x; j < cols; j += 256) { float v = ip[j]; ss += v * v; }
    __shared__ float red[256];
    red[threadIdx.x] = ss;
    __syncthreads();
    for (int st = 128; st > 0; st >>= 1) {
        if (threadIdx.x < st) red[threadIdx.x] += red[threadIdx.x + st];
        __syncthreads();
    }
    float scale = rsqrtf(red[0] / (float)cols + 1e-6f);
    __half* op = out + (long long)row * outstride;
    for (int j = threadIdx.x; j < cols; j += 256)
        op[j] = __float2half_rn(ip[j] * scale * w[j]);
}

__global__ void rope_q_k(__half* __restrict__ q, const float* __restrict__ rsin,
                         const float* __restrict__ rcos) {
    int t = blockIdx.x;
    for (int i = threadIdx.x; i < NHH * 32; i += blockDim.x) {
        int h = i >> 5;
        int p = i & 31;
        __half* base = q + (long long)t * (NHH * DQK) + h * DQK + NOPE + 2 * p;
        float s = rsin[t * 32 + p], c = rcos[t * 32 + p];
        float a = __half2float(base[0]), b = __half2float(base[1]);
        base[0] = __float2half_rn(a * c - b * s);
        base[1] = __float2half_rn(a * s + b * c);
    }
}

__global__ void build_k_k(const __half* __restrict__ knope, const float* __restrict__ kv,
                          const float* __restrict__ rsin, const float* __restrict__ rcos,
                          __half* __restrict__ kfull) {
    int t = blockIdx.x;
    __shared__ __half pe[ROPED];
    if (threadIdx.x < 32) {
        int p = threadIdx.x;
        float a = kv[(long long)t * (KVLAT + ROPED) + KVLAT + 2 * p];
        float b = kv[(long long)t * (KVLAT + ROPED) + KVLAT + 2 * p + 1];
        float s = rsin[t * 32 + p], c = rcos[t * 32 + p];
        pe[2 * p]     = __float2half_rn(a * c - b * s);
        pe[2 * p + 1] = __float2half_rn(a * s + b * c);
    }
    __syncthreads();
    for (int i = threadIdx.x; i < NHH * DQK; i += blockDim.x) {
        int h = i / DQK;
        int d = i % DQK;
        kfull[(long long)t * (NHH * DQK) + i] =
            (d < NOPE) ? knope[(long long)t * (NHH * NOPE) + h * NOPE + d] : pe[d - NOPE];
    }
}

__global__ __launch_bounds__(256)
void gate_topk_k(const __half* __restrict__ n2, const float* __restrict__ gw) {
    int t = blockIdx.x;
    __shared__ float logits[NE];
    int warp = threadIdx.x >> 5, lane = threadIdx.x & 31;
    const __half* xp = n2 + (long long)t * HH;
    const float* wp = gw + warp * HH;
    float s = 0.f;
    for (int k = lane; k < HH; k += 32) s += __half2float(xp[k]) * wp[k];
    for (int off = 16; off > 0; off >>= 1) s += __shfl_down_sync(0xffffffffu, s, off);
    if (lane == 0) logits[warp] = s;
    __syncthreads();
    if (threadIdx.x == 0) {
        float m = logits[0];
        for (int e = 1; e < NE; e++) m = fmaxf(m, logits[e]);
        float p[NE];
        float sum = 0.f;
        for (int e = 0; e < NE; e++) { p[e] = __expf(logits[e] - m); sum += p[e]; }
        for (int e = 0; e < NE; e++) p[e] /= sum;
        int i0 = 0;
        for (int e = 1; e < NE; e++) if (p[e] > p[i0]) i0 = e;
        int i1 = -1;
        for (int e = 0; e < NE; e++) {
            if (e == i0) continue;
            if (i1 < 0 || p[e] > p[i1]) i1 = e;
        }
        float w0 = p[i0], w1 = p[i1];
        float tot = w0 + w1;
        w0 /= tot; w1 /= tot;
        int pos0 = atomicAdd(&g_s.counts[i0], 1);
        g_s.tok[i0 * TT + pos0] = t;
        g_s.orow[i0 * TT + pos0] = t;
        g_s.ew[i0 * TT + pos0] = w0;
        int pos1 = atomicAdd(&g_s.counts[i1], 1);
        g_s.tok[i1 * TT + pos1] = t;
        g_s.orow[i1 * TT + pos1] = TT + t;
        g_s.ew[i1 * TT + pos1] = w1;
    }
}

__global__ void silu_gate_k(const float* __restrict__ in, __half* __restrict__ out,
                            int half_) {
    int row = blockIdx.x;
    const float* ip = in + (long long)row * 2 * half_;
    __half* op = out + (long long)row * half_;
    for (int j = threadIdx.x; j < half_; j += blockDim.x) {
        float a = ip[j], b = ip[half_ + j];
        op[j] = __float2half_rn((a / (1.f + __expf(-a))) * b);
    }
}

__global__ void silu_gate_moe_k() {
    int e = blockIdx.y;
    int row = blockIdx.x;
    if (row >= g_s.counts[e]) return;
    const float* ip = g_s.h + ((long long)e * TT + row) * (2 * MIDIM);
    __half* op = g_s.hah + ((long long)e * TT + row) * MIDIM;
    for (int j = threadIdx.x; j < MIDIM; j += blockDim.x) {
        float a = ip[j], b = ip[MIDIM + j];
        op[j] = __float2half_rn((a / (1.f + __expf(-a))) * b);
    }
}

// ---------------------------------------------------------------------------
// Host-side launch helpers
// ---------------------------------------------------------------------------
static void launch_gemm(bool wide, bool outh, const __half* A, const __half* B, void* C,
                        int M, int N, int K, int lda, int ldb, int ldc,
                        long long sA, long long sB, long long sC, int bz,
                        float sc, int causal, int klim,
                        const int* aidx, const int* mdev,
                        const int* cidx, const float* cs, int pstride)
{
    if (wide) {
        dim3 grid((N + 255) / 256, (M + 127) / 128, bz);
        if (outh)
            gemm_h<true, 256, 2, 256><<<grid, 256, SMEM_BYTES>>>(
                A, B, C, M, N, K, lda, ldb, ldc, sA, sB, sC, sc, causal, klim,
                aidx, mdev, cidx, cs, pstride);
        else
            gemm_h<false, 256, 2, 256><<<grid, 256, SMEM_BYTES>>>(
                A, B, C, M, N, K, lda, ldb, ldc, sA, sB, sC, sc, causal, klim,
                aidx, mdev, cidx, cs, pstride);
    } else {
        dim3 grid((N + 127) / 128, (M + 127) / 128, bz);
        if (outh)
            gemm_h<true, 128, 3, 128><<<grid, 128, SMEM_BYTES>>>(
                A, B, C, M, N, K, lda, ldb, ldc, sA, sB, sC, sc, causal, klim,
                aidx, mdev, cidx, cs, pstride);
        else
            gemm_h<false, 128, 3, 128><<<grid, 128, SMEM_BYTES>>>(
                A, B, C, M, N, K, lda, ldb, ldc, sA, sB, sC, sc, causal, klim,
                aidx, mdev, cidx, cs, pstride);
    }
}

static void launch_nt(bool wide, bool outh, const __half* A, const __half* B, void* C,
                      int M, int N, int K, int lda, int ldb, int ldc)
{
    launch_gemm(wide, outh, A, B, C, M, N, K, lda, ldb, ldc, 0, 0, 0, 1, 1.f, 0, 0,
                nullptr, nullptr, nullptr, nullptr, 0);
}

// ---------------------------------------------------------------------------
extern "C" void kernel_launch(void* const* d_in, const int* in_sizes, int n_in,
                              void* d_out, int out_size)
{
    const float* x    = (const float*)d_in[0];
    const float* skip = (const float*)d_in[1];
    const float* rsin = (const float*)d_in[2];
    const float* rcos = (const float*)d_in[3];
    const float* ln1  = (const float*)d_in[4];
    const float* ln2  = (const float*)d_in[5];
    const float* wqa  = (const float*)d_in[6];
    const float* qan  = (const float*)d_in[7];
    const float* wqb  = (const float*)d_in[8];
    const float* wkva = (const float*)d_in[9];
    const float* kvan = (const float*)d_in[10];
    const float* wkb  = (const float*)d_in[11];
    const float* wvb  = (const float*)d_in[12];
    const float* wo   = (const float*)d_in[13];
    const float* gw   = (const float*)d_in[14];
    const float* wup  = (const float*)d_in[15];
    const float* wdn  = (const float*)d_in[16];
    const float* wsup = (const float*)d_in[17];
    const float* wsdn = (const float*)d_in[18];
    float* out = (float*)d_out;

    Scratch* s = nullptr;
    cudaGetSymbolAddress((void**)&s, g_s);
    cudaFuncSetAttribute((const void*)gemm_h<true, 256, 2, 256>,
                         cudaFuncAttributeMaxDynamicSharedMemorySize, SMEM_BYTES);
    cudaFuncSetAttribute((const void*)gemm_h<false, 256, 2, 256>,
                         cudaFuncAttributeMaxDynamicSharedMemorySize, SMEM_BYTES);
    cudaFuncSetAttribute((const void*)gemm_h<true, 128, 3, 128>,
                         cudaFuncAttributeMaxDynamicSharedMemorySize, SMEM_BYTES);
    cudaFuncSetAttribute((const void*)gemm_h<false, 128, 3, 128>,
                         cudaFuncAttributeMaxDynamicSharedMemorySize, SMEM_BYTES);
    cudaFuncSetAttribute((const void*)flash_attn_k,
                         cudaFuncAttributeMaxDynamicSharedMemorySize, SMEM_FLASH);

    const int n = TT * HH;

    zero_counts_k<<<1, 32>>>();

    // weights -> half (vectorized)
    f2h_k<<<1024, 256>>>((const float4*)wqa,  (uint2*)s->wqa_h,  (long long)QLAT * HH / 4);
    f2h_k<<<1024, 256>>>((const float4*)wqb,  (uint2*)s->wqb_h,  (long long)NHH * DQK * QLAT / 4);
    f2h_k<<<1024, 256>>>((const float4*)wkva, (uint2*)s->wkva_h, (long long)(KVLAT + ROPED) * HH / 4);
    f2h_k<<<1024, 256>>>((const float4*)wkb,  (uint2*)s->wkb_h,  (long long)NHH * NOPE * KVLAT / 4);
    f2h_k<<<1024, 256>>>((const float4*)wvb,  (uint2*)s->wvb_h,  (long long)NHH * VDIM * KVLAT / 4);
    f2h_k<<<1024, 256>>>((const float4*)wo,   (uint2*)s->wo_h,   (long long)HH * NHH * VDIM / 4);
    f2h_k<<<1024, 256>>>((const float4*)wsup, (uint2*)s->wsup_h, (long long)2 * SHI * HH / 4);
    f2h_k<<<1024, 256>>>((const float4*)wsdn, (uint2*)s->wsdn_h, (long long)HH * SHI / 4);
    f2h_k<<<2048, 256>>>((const float4*)wup,  (uint2*)s->wup_h,  (long long)NE * 2 * MIDIM * HH / 4);
    f2h_k<<<2048, 256>>>((const float4*)wdn,  (uint2*)s->wdn_h,  (long long)NE * HH * MIDIM / 4);

    // x1 = x + skip ; n1h = rms(x1)
    add2_k<<<4096, 256>>>(x, skip, s->x1, n);
    rmsnorm_h_k<<<TT, 256>>>(s->x1, ln1, s->n1h, HH, HH, HH);

    // q path
    launch_nt(true, false, s->n1h, s->wqa_h, s->qa_pre, TT, QLAT, HH, HH, HH, QLAT);
    rmsnorm_h_k<<<TT, 256>>>(s->qa_pre, qan, s->qah, QLAT, QLAT, QLAT);
    launch_nt(true, true, s->qah, s->wqb_h, s->qh, TT, NHH * DQK, QLAT, QLAT, QLAT, NHH * DQK);
    rope_q_k<<<TT, 256>>>(s->qh, rsin, rcos);

    // kv path
    launch_nt(false, false, s->n1h, s->wkva_h, s->kv, TT, KVLAT + ROPED, HH, HH, HH, KVLAT + ROPED);
    rmsnorm_h_k<<<TT, 256>>>(s->kv, kvan, s->ckvh, KVLAT, KVLAT + ROPED, KVLAT);
    launch_nt(true, true, s->ckvh, s->wkb_h, s->knopeh, TT, NHH * NOPE, KVLAT, KVLAT, KVLAT, NHH * NOPE);
    build_k_k<<<TT, 256>>>(s->knopeh, s->kv, rsin, rcos, s->kfullh);
    // vT[h*128+d, t] = sum_k wvb[h*128+d, k] * ckv[t, k]
    launch_nt(true, true, s->wvb_h, s->ckvh, s->vTh, NHH * VDIM, TT, KVLAT, KVLAT, KVLAT, TT);

    // fused flash attention (QK + softmax + PV)
    float attn_scale = 1.0f / sqrtf((float)DQK);
    flash_attn_k<<<dim3(NHH, TT / 128), 128, SMEM_FLASH>>>(
        s->qh, s->kfullh, s->vTh, s->oh, attn_scale);

    // attn out + residual -> x2 (output part 1)
    launch_nt(true, false, s->oh, s->wo_h, s->attn, TT, HH, NHH * VDIM, NHH * VDIM, NHH * VDIM, HH);
    x2_out_k<<<4096, 256>>>(s->x1, s->attn, s->x2, out, n);

    // n2 and MoE gating
    rmsnorm_h_k<<<TT, 256>>>(s->x2, ln2, s->n2h, HH, HH, HH);
    gate_topk_k<<<TT, 256>>>(s->n2h, gw);

    // shared FFN
    launch_nt(true, false, s->n2h, s->wsup_h, s->hs, TT, 2 * SHI, HH, HH, HH, 2 * SHI);
    silu_gate_k<<<TT, 256>>>(s->hs, s->hsah, SHI);
    launch_nt(true, false, s->hsah, s->wsdn_h, s->shared_o, TT, HH, SHI, SHI, SHI, HH);

    // routed experts: batched over blockIdx.z = expert
    launch_gemm(true, false, s->n2h, s->wup_h, s->h, TT, 2 * MIDIM, HH,
                HH, HH, 2 * MIDIM,
                0, (long long)(2 * MIDIM) * HH, (long long)TT * 2 * MIDIM, NE,
                1.f, 0, 0,
                s->tok, s->counts, nullptr, nullptr, TT);
    silu_gate_moe_k<<<dim3(TT, NE), 256>>>();
    launch_gemm(true, false, s->hah, s->wdn_h, s->routed2, TT, HH, MIDIM,
                MIDIM, MIDIM, HH,
                (long long)TT * MIDIM, (long long)HH * MIDIM, 0, NE,
                1.f, 0, 0,
                nullptr, s->counts, s->orow, s->ew, TT);

    // ffn = routed(slot0) + routed(slot1) + shared  (output part 2)
    combine_k<<<4096, 256>>>(s->routed2, s->shared_o, out + (long long)n, n);
}

// round 10
// speedup vs baseline: 1.2622x; 1.0653x over previous
#include <cuda_runtime.h>
#include <cuda_fp16.h>
#include <math.h>
#include <stdint.h>

#define TT   2048
#define HH   2048
#define NHH  16
#define NOPE 128
#define ROPED 64
#define DQK  192     // NOPE + ROPE
#define VDIM 128
#define QLAT 1536
#define KVLAT 512
#define NE   8
#define MIDIM 512
#define SHI  1024    // 2*MI

// ---------------------------------------------------------------------------
// Scratch (static device memory; no allocations anywhere)
// ---------------------------------------------------------------------------
struct __align__(128) Scratch {
    // f32 buffers
    float x1[TT * HH];
    float qa_pre[TT * QLAT];
    float kv[TT * (KVLAT + ROPED)];
    float x2[TT * HH];
    float h[(long long)NE * TT * 2 * MIDIM];
    float hs[TT * 2 * SHI];
    float ew[NE * TT];
    int   tok[NE * TT];
    int   counts[NE];
    // half activation buffers
    __half n1h[TT * HH];
    __half qah[TT * QLAT];
    __half qh[TT * NHH * DQK];
    __half ckvh[TT * KVLAT];
    __half knopeh[TT * NHH * NOPE];
    __half kfullh[TT * NHH * DQK];
    __half vTh[NHH * VDIM * TT];          // [h*128+d, t]
    __half oh[TT * NHH * VDIM];
    __half n2h[TT * HH];
    __half hsah[TT * SHI];
    __half hah[(long long)NE * TT * MIDIM];
    // half weight copies
    __half wqa_h[QLAT * HH];
    __half wqb_h[NHH * DQK * QLAT];
    __half wkva_h[(KVLAT + ROPED) * HH];
    __half wkb_h[NHH * NOPE * KVLAT];
    __half wvb_h[NHH * VDIM * KVLAT];
    __half wo_h[HH * NHH * VDIM];
    __half wsup_h[2 * SHI * HH];
    __half wsdn_h[HH * SHI];
    __half wup_h[(long long)NE * 2 * MIDIM * HH];
    __half wdn_h[(long long)NE * HH * MIDIM];
};
__device__ Scratch g_s;

// ---------------------------------------------------------------------------
// helpers
// ---------------------------------------------------------------------------
__device__ __forceinline__ uint32_t smem_u32(const void* p) {
    uint32_t a;
    asm("{ .reg .u64 t; cvta.to.shared.u64 t, %1; cvt.u32.u64 %0, t; }" : "=r"(a) : "l"(p));
    return a;
}

__device__ __forceinline__ void cp16(uint32_t dst, const void* src, int sz) {
    asm volatile("cp.async.cg.shared.global [%0], [%1], 16, %2;"
                 :: "r"(dst), "l"(src), "r"(sz));
}
__device__ __forceinline__ void cp_commit() {
    asm volatile("cp.async.commit_group;" ::: "memory");
}

__device__ __forceinline__ void ldm_x4(unsigned& r0, unsigned& r1, unsigned& r2,
                                       unsigned& r3, uint32_t addr) {
    asm volatile("ldmatrix.sync.aligned.m8n8.x4.shared.b16 {%0,%1,%2,%3}, [%4];"
                 : "=r"(r0), "=r"(r1), "=r"(r2), "=r"(r3) : "r"(addr));
}

__device__ __forceinline__ void mma_f16(float* d, const unsigned* a, const unsigned* b) {
    asm volatile(
        "mma.sync.aligned.m16n8k16.row.col.f32.f16.f16.f32 "
        "{%0,%1,%2,%3}, {%4,%5,%6,%7}, {%8,%9}, {%0,%1,%2,%3};\n"
        : "+f"(d[0]), "+f"(d[1]), "+f"(d[2]), "+f"(d[3])
        : "r"(a[0]), "r"(a[1]), "r"(a[2]), "r"(a[3]), "r"(b[0]), "r"(b[1]));
}

__device__ __forceinline__ unsigned packh2(float x, float y) {
    __half2 h = __floats2half2_rn(x, y);
    return *reinterpret_cast<unsigned*>(&h);
}

// ---------------------------------------------------------------------------
// fp16 NT GEMM (R5 config, frozen) + epilogue fusions:
//   resid  : add f32 residual (indexed like C) before store
//   C2     : secondary f32 destination (same value)
//   atomicC: atomicAdd into C instead of store
// ---------------------------------------------------------------------------
#define SMEM_BYTES 98304

template <bool OUTH, int NTILE, int NSTAGE, int NTHREADS>
__global__ __launch_bounds__(NTHREADS)
void gemm_h(const __half* __restrict__ A, const __half* __restrict__ B,
            void* __restrict__ Cv,
            int M, int N, int K, int lda, int ldb, int ldc,
            long long sA, long long sB, long long sC,
            float scale, int causal, int klim,
            const int* __restrict__ aidx, const int* __restrict__ mdev,
            const int* __restrict__ cidx, const float* __restrict__ cscale,
            int pstride,
            const float* __restrict__ resid, float* __restrict__ C2, int atomicC)
{
    constexpr int STG_BYTES = (128 + NTILE) * 128;
    constexpr int LOADS = (128 + NTILE) * 8 / NTHREADS;
    extern __shared__ __align__(128) char smem[];
    const int z = blockIdx.z;
    A += (long long)z * sA;
    B += (long long)z * sB;
    if (pstride) {
        if (mdev)   mdev   += z;
        if (aidx)   aidx   += (long long)z * pstride;
        if (cidx)   cidx   += (long long)z * pstride;
        if (cscale) cscale += (long long)z * pstride;
    }
    const int Meff = mdev ? *mdev : M;
    const int m0 = blockIdx.y * 128;
    const int n0 = blockIdx.x * NTILE;
    if (m0 >= Meff) return;
    if (causal && n0 > m0 + 127) return;
    const int kmax = klim ? min(K, m0 + 128) : K;
    const int ktiles = kmax >> 6;

    const uint32_t sbase = smem_u32(smem);
    const int tid = threadIdx.x;
    const int lane = tid & 31;
    const int wid = tid >> 5;
    const int wm = (wid & 1) * 64;
    const int wn = (wid >> 1) * 64;
    const int lr = lane >> 2;
    const int lm = lane & 3;

    float acc[4][8][4];
#pragma unroll
    for (int i = 0; i < 4; i++)
#pragma unroll
        for (int j = 0; j < 8; j++)
#pragma unroll
            for (int c = 0; c < 4; c++) acc[i][j][c] = 0.f;

    auto issue_stage = [&](int i) {
        const uint32_t base = sbase + (i % NSTAGE) * STG_BYTES;
        const int kt = i << 6;
#pragma unroll
        for (int it = 0; it < LOADS; it++) {
            int c = tid + it * NTHREADS;
            int row = c >> 3, ch = c & 7;
            uint32_t dst = base + row * 128 + ((ch ^ (row & 7)) << 4);
            const __half* src;
            int sz = 0;
            if (row < 128) {
                int gm = m0 + row;
                src = A;
                if (gm < Meff) {
                    int ar = aidx ? aidx[gm] : gm;
                    src = A + (long long)ar * lda + kt + ch * 8;
                    sz = 16;
                }
            } else {
                int gn = n0 + row - 128;
                src = B;
                if (gn < N) {
                    src = B + (long long)gn * ldb + kt + ch * 8;
                    sz = 16;
                }
            }
            cp16(dst, src, sz);
        }
    };

#pragma unroll
    for (int s = 0; s < NSTAGE - 1; s++) {
        if (s < ktiles) issue_stage(s);
        cp_commit();
    }

    const int a_row = lane & 15;
    const int a_h = lane >> 4;
    const int b_t = lane >> 3;
    const int b_r = lane & 7;

    for (int i = 0; i < ktiles; i++) {
        if (i + NSTAGE - 1 < ktiles) issue_stage(i + NSTAGE - 1);
        cp_commit();
        if (NSTAGE == 2)
            asm volatile("cp.async.wait_group 1;" ::: "memory");
        else
            asm volatile("cp.async.wait_group 2;" ::: "memory");
        __syncthreads();

        const uint32_t base = sbase + (i % NSTAGE) * STG_BYTES;
#pragma unroll
        for (int kk = 0; kk < 4; kk++) {
            unsigned afr[4][4], bfr[8][2];
#pragma unroll
            for (int im = 0; im < 4; im++) {
                int row = wm + im * 16 + a_row;
                int ch = kk * 2 + a_h;
                ldm_x4(afr[im][0], afr[im][1], afr[im][2], afr[im][3],
                       base + row * 128 + ((ch ^ (row & 7)) << 4));
            }
#pragma unroll
            for (int j2 = 0; j2 < 4; j2++) {
                int jn = j2 * 2 + (b_t >> 1);
                int row = 128 + wn + jn * 8 + b_r;
                int ch = kk * 2 + (b_t & 1);
                unsigned r0, r1, r2, r3;
                ldm_x4(r0, r1, r2, r3, base + row * 128 + ((ch ^ (row & 7)) << 4));
                bfr[j2 * 2][0] = r0;     bfr[j2 * 2][1] = r1;
                bfr[j2 * 2 + 1][0] = r2; bfr[j2 * 2 + 1][1] = r3;
            }
#pragma unroll
            for (int im = 0; im < 4; im++)
#pragma unroll
                for (int jn = 0; jn < 8; jn++)
                    mma_f16(acc[im][jn], afr[im], bfr[jn]);
        }
        __syncthreads();
    }

#pragma unroll
    for (int im = 0; im < 4; im++) {
#pragma unroll
        for (int part = 0; part < 2; part++) {
            int gm = m0 + wm + im * 16 + lr + part * 8;
            if (gm >= Meff) continue;
            long long crow = gm;
            float w = scale;
            if (cidx) { crow = cidx[gm]; w = scale * cscale[gm]; }
#pragma unroll
            for (int jn = 0; jn < 8; jn++) {
                int gn = n0 + wn + jn * 8 + lm * 2;
                if (gn >= N) continue;
                float vx = acc[im][jn][part * 2] * w;
                float vy = acc[im][jn][part * 2 + 1] * w;
                if (OUTH) {
                    __half* cp = (__half*)Cv + ((long long)z * sC) + crow * (long long)ldc + gn;
                    *reinterpret_cast<__half2*>(cp) = __floats2half2_rn(vx, vy);
                } else {
                    long long off = crow * (long long)ldc + gn;
                    if (resid) {
                        vx += resid[off];
                        vy += resid[off + 1];
                    }
                    float* cp = (float*)Cv + ((long long)z * sC) + off;
                    if (atomicC) {
                        atomicAdd(cp, vx);
                        atomicAdd(cp + 1, vy);
                    } else {
                        *reinterpret_cast<float2*>(cp) = make_float2(vx, vy);
                        if (C2)
                            *reinterpret_cast<float2*>(C2 + off) = make_float2(vx, vy);
                    }
                }
            }
        }
    }
}

// ---------------------------------------------------------------------------
// Flash attention: 256 threads, 8 warps x 16 q-rows; k-blocks of 64.
// Q tile resident (128x384B), K (64x384B) + Vt (128x128B) double buffered.
// ---------------------------------------------------------------------------
#define SMEM_FLASH 131072

__global__ __launch_bounds__(256, 1)
void flash_attn_k(const __half* __restrict__ Q, const __half* __restrict__ K,
                  const __half* __restrict__ Vt, __half* __restrict__ O,
                  float scale)
{
    extern __shared__ __align__(128) char smem[];
    const int h = blockIdx.x;
    const int qb = (int)gridDim.y - 1 - (int)blockIdx.y;   // heaviest first
    const int nkb = 2 * qb + 2;
    const uint32_t sb = smem_u32(smem);
    const uint32_t Qs = sb;                  // 49152
    const uint32_t Ks = sb + 49152;          // 2 x 24576
    const uint32_t Vs = sb + 49152 + 49152;  // 2 x 16384
    const int tid = threadIdx.x, lane = tid & 31, wid = tid >> 5;
    const int wq = wid * 16;
    const int lr = lane >> 2, lm = lane & 3;

    // load Q tile (rows qb*128.., head h)
    for (int c = tid; c < 3072; c += 256) {
        int row = c / 24, kc = c % 24;
        int sub = kc >> 3, ch = kc & 7;
        cp16(Qs + row * 384 + sub * 128 + ((ch ^ (row & 7)) << 4),
             Q + ((long long)(qb * 128 + row) * (NHH * DQK) + h * DQK + kc * 8), 16);
    }
    auto load_kv = [&](int kb) {
        int buf = kb & 1;
        for (int c = tid; c < 1536; c += 256) {
            int row = c / 24, kc = c % 24;
            int sub = kc >> 3, ch = kc & 7;
            cp16(Ks + buf * 24576 + row * 384 + sub * 128 + ((ch ^ (row & 7)) << 4),
                 K + ((long long)(kb * 64 + row) * (NHH * DQK) + h * DQK + kc * 8), 16);
        }
        for (int c = tid; c < 1024; c += 256) {
            int row = c >> 3, ch = c & 7;
            cp16(Vs + buf * 16384 + row * 128 + ((ch ^ (row & 7)) << 4),
                 Vt + ((long long)(h * 128 + row) * TT + kb * 64 + ch * 8), 16);
        }
    };

    load_kv(0);
    cp_commit();

    float m_s[2] = {-1e30f, -1e30f}, l_s[2] = {0.f, 0.f};
    float acc[16][4];
#pragma unroll
    for (int dn = 0; dn < 16; dn++)
#pragma unroll
        for (int c = 0; c < 4; c++) acc[dn][c] = 0.f;

    const int a_row = lane & 15, a_h = lane >> 4;
    const int b_t = lane >> 3, b_r = lane & 7;

    for (int kb = 0; kb < nkb; kb++) {
        if (kb + 1 < nkb) load_kv(kb + 1);
        cp_commit();
        asm volatile("cp.async.wait_group 1;" ::: "memory");
        __syncthreads();
        const uint32_t kbase = Ks + (kb & 1) * 24576;
        const uint32_t vbase = Vs + (kb & 1) * 16384;

        // S = Q K^T  (warp: 16 q x 64 k)
        float s[8][4];
#pragma unroll
        for (int jn = 0; jn < 8; jn++)
#pragma unroll
            for (int c = 0; c < 4; c++) s[jn][c] = 0.f;

#pragma unroll
        for (int ks = 0; ks < 12; ks++) {
            unsigned afr[4], bfr[8][2];
            {
                int row = wq + a_row;
                int kc = ks * 2 + a_h;
                ldm_x4(afr[0], afr[1], afr[2], afr[3],
                       Qs + row * 384 + (kc >> 3) * 128 + (((kc & 7) ^ (row & 7)) << 4));
            }
#pragma unroll
            for (int j2 = 0; j2 < 4; j2++) {
                int jn = j2 * 2 + (b_t >> 1);
                int row = jn * 8 + b_r;
                int kc = ks * 2 + (b_t & 1);
                unsigned r0, r1, r2, r3;
                ldm_x4(r0, r1, r2, r3,
                       kbase + row * 384 + (kc >> 3) * 128 + (((kc & 7) ^ (row & 7)) << 4));
                bfr[j2 * 2][0] = r0;     bfr[j2 * 2][1] = r1;
                bfr[j2 * 2 + 1][0] = r2; bfr[j2 * 2 + 1][1] = r3;
            }
#pragma unroll
            for (int jn = 0; jn < 8; jn++)
                mma_f16(s[jn], afr, bfr[jn]);
        }

        // scale + causal mask + online softmax (per 8-row part)
        const int coff = kb * 64 - qb * 128;
        float alpha[2];
#pragma unroll
        for (int part = 0; part < 2; part++) {
            int r = wq + lr + part * 8;
            float mx = -1e30f;
#pragma unroll
            for (int jn = 0; jn < 8; jn++) {
#pragma unroll
                for (int q = 0; q < 2; q++) {
                    int c = jn * 8 + lm * 2 + q;
                    float v = s[jn][part * 2 + q] * scale;
                    if (c + coff > r) v = -1e30f;
                    s[jn][part * 2 + q] = v;
                    mx = fmaxf(mx, v);
                }
            }
            mx = fmaxf(mx, __shfl_xor_sync(0xffffffffu, mx, 1));
            mx = fmaxf(mx, __shfl_xor_sync(0xffffffffu, mx, 2));
            float mo = m_s[part];
            float mn = fmaxf(mo, mx);
            float al = __expf(mo - mn);
            float sum = 0.f;
#pragma unroll
            for (int jn = 0; jn < 8; jn++) {
#pragma unroll
                for (int q = 0; q < 2; q++) {
                    float p = __expf(s[jn][part * 2 + q] - mn);
                    s[jn][part * 2 + q] = p;
                    sum += p;
                }
            }
            sum += __shfl_xor_sync(0xffffffffu, sum, 1);
            sum += __shfl_xor_sync(0xffffffffu, sum, 2);
            l_s[part] = l_s[part] * al + sum;
            m_s[part] = mn;
            alpha[part] = al;
        }
#pragma unroll
        for (int dn = 0; dn < 16; dn++) {
            acc[dn][0] *= alpha[0];
            acc[dn][1] *= alpha[0];
            acc[dn][2] *= alpha[1];
            acc[dn][3] *= alpha[1];
        }

        // O += P @ V  (P in regs -> A frags; V from smem)
#pragma unroll
        for (int kv = 0; kv < 4; kv++) {
            unsigned ap[4];
            ap[0] = packh2(s[2 * kv][0], s[2 * kv][1]);
            ap[1] = packh2(s[2 * kv][2], s[2 * kv][3]);
            ap[2] = packh2(s[2 * kv + 1][0], s[2 * kv + 1][1]);
            ap[3] = packh2(s[2 * kv + 1][2], s[2 * kv + 1][3]);
#pragma unroll
            for (int j2 = 0; j2 < 8; j2++) {
                int dn = j2 * 2 + (b_t >> 1);
                int row = dn * 8 + b_r;
                int ch = kv * 2 + (b_t & 1);
                unsigned r0, r1, r2, r3;
                ldm_x4(r0, r1, r2, r3, vbase + row * 128 + ((ch ^ (row & 7)) << 4));
                unsigned bv0[2] = {r0, r1}, bv1[2] = {r2, r3};
                mma_f16(acc[j2 * 2], ap, bv0);
                mma_f16(acc[j2 * 2 + 1], ap, bv1);
            }
        }
        __syncthreads();
    }

    // epilogue: O = acc / l
#pragma unroll
    for (int part = 0; part < 2; part++) {
        float inv = 1.0f / l_s[part];
        int grow = qb * 128 + wq + lr + part * 8;
        __half* op = O + (long long)grow * (NHH * VDIM) + h * VDIM;
#pragma unroll
        for (int dn = 0; dn < 16; dn++) {
            int col = dn * 8 + lm * 2;
            *reinterpret_cast<__half2*>(op + col) =
                __floats2half2_rn(acc[dn][part * 2] * inv,
                                  acc[dn][part * 2 + 1] * inv);
        }
    }
}

// ---------------------------------------------------------------------------
// Elementwise / reduction kernels
// ---------------------------------------------------------------------------
__global__ void zero_counts_k() {
    if (threadIdx.x < NE) g_s.counts[threadIdx.x] = 0;
}

__global__ void f2h_k(const float4* __restrict__ in, uint2* __restrict__ out,
                      long long n4) {
    for (long long i = blockIdx.x * (long long)blockDim.x + threadIdx.x; i < n4;
         i += (long long)gridDim.x * blockDim.x) {
        float4 v = in[i];
        __half2 h0 = __floats2half2_rn(v.x, v.y);
        __half2 h1 = __floats2half2_rn(v.z, v.w);
        uint2 o;
        o.x = *reinterpret_cast<unsigned*>(&h0);
        o.y = *reinterpret_cast<unsigned*>(&h1);
        out[i] = o;
    }
}

__global__ void add2_k(const float* __restrict__ a, const float* __restrict__ b,
                       float* __restrict__ c, int n) {
    for (int i = blockIdx.x * blockDim.x + threadIdx.x; i < n; i += gridDim.x * blockDim.x)
        c[i] = a[i] + b[i];
}

__global__ __launch_bounds__(256)
void rmsnorm_h_k(const float* __restrict__ in, const float* __restrict__ w,
                 __half* __restrict__ out, int cols, int instride, int outstride) {
    int row = blockIdx.x;
    const float* ip = in + (long long)row * instride;
    float ss = 0.f;
    for (int j = threadIdx.x; j < cols; j += 256) { float v = ip[j]; ss += v * v; }
    __shared__ float red[256];
    red[threadIdx.x] = ss;
    __syncthreads();
    for (int st = 128; st > 0; st >>= 1) {
        if (threadIdx.x < st) red[threadIdx.x] += red[threadIdx.x + st];
        __syncthreads();
    }
    float scale = rsqrtf(red[0] / (float)cols + 1e-6f);
    __half* op = out + (long long)row * outstride;
    for (int j = threadIdx.x; j < cols; j += 256)
        op[j] = __float2half_rn(ip[j] * scale * w[j]);
}

__global__ void rope_q_k(__half* __restrict__ q, const float* __restrict__ rsin,
                         const float* __restrict__ rcos) {
    int t = blockIdx.x;
    for (int i = threadIdx.x; i < NHH * 32; i += blockDim.x) {
        int h = i >> 5;
        int p = i & 31;
        __half* base = q + (long long)t * (NHH * DQK) + h * DQK + NOPE + 2 * p;
        float s = rsin[t * 32 + p], c = rcos[t * 32 + p];
        float a = __half2float(base[0]), b = __half2float(base[1]);
        base[0] = __float2half_rn(a * c - b * s);
        base[1] = __float2half_rn(a * s + b * c);
    }
}

__global__ void build_k_k(const __half* __restrict__ knope, const float* __restrict__ kv,
                          const float* __restrict__ rsin, const float* __restrict__ rcos,
                          __half* __restrict__ kfull) {
    int t = blockIdx.x;
    __shared__ __half pe[ROPED];
    if (threadIdx.x < 32) {
        int p = threadIdx.x;
        float a = kv[(long long)t * (KVLAT + ROPED) + KVLAT + 2 * p];
        float b = kv[(long long)t * (KVLAT + ROPED) + KVLAT + 2 * p + 1];
        float s = rsin[t * 32 + p], c = rcos[t * 32 + p];
        pe[2 * p]     = __float2half_rn(a * c - b * s);
        pe[2 * p + 1] = __float2half_rn(a * s + b * c);
    }
    __syncthreads();
    for (int i = threadIdx.x; i < NHH * DQK; i += blockDim.x) {
        int h = i / DQK;
        int d = i % DQK;
        kfull[(long long)t * (NHH * DQK) + i] =
            (d < NOPE) ? knope[(long long)t * (NHH * NOPE) + h * NOPE + d] : pe[d - NOPE];
    }
}

__global__ __launch_bounds__(256)
void gate_topk_k(const __half* __restrict__ n2, const float* __restrict__ gw) {
    int t = blockIdx.x;
    __shared__ float logits[NE];
    int warp = threadIdx.x >> 5, lane = threadIdx.x & 31;
    const __half* xp = n2 + (long long)t * HH;
    const float* wp = gw + warp * HH;
    float s = 0.f;
    for (int k = lane; k < HH; k += 32) s += __half2float(xp[k]) * wp[k];
    for (int off = 16; off > 0; off >>= 1) s += __shfl_down_sync(0xffffffffu, s, off);
    if (lane == 0) logits[warp] = s;
    __syncthreads();
    if (threadIdx.x == 0) {
        float m = logits[0];
        for (int e = 1; e < NE; e++) m = fmaxf(m, logits[e]);
        float p[NE];
        float sum = 0.f;
        for (int e = 0; e < NE; e++) { p[e] = __expf(logits[e] - m); sum += p[e]; }
        for (int e = 0; e < NE; e++) p[e] /= sum;
        int i0 = 0;
        for (int e = 1; e < NE; e++) if (p[e] > p[i0]) i0 = e;
        int i1 = -1;
        for (int e = 0; e < NE; e++) {
            if (e == i0) continue;
            if (i1 < 0 || p[e] > p[i1]) i1 = e;
        }
        float w0 = p[i0], w1 = p[i1];
        float tot = w0 + w1;
        w0 /= tot; w1 /= tot;
        int pos0 = atomicAdd(&g_s.counts[i0], 1);
        g_s.tok[i0 * TT + pos0] = t;
        g_s.ew[i0 * TT + pos0] = w0;
        int pos1 = atomicAdd(&g_s.counts[i1], 1);
        g_s.tok[i1 * TT + pos1] = t;
        g_s.ew[i1 * TT + pos1] = w1;
    }
}

__global__ void silu_gate_k(const float* __restrict__ in, __half* __restrict__ out,
                            int half_) {
    int row = blockIdx.x;
    const float* ip = in + (long long)row * 2 * half_;
    __half* op = out + (long long)row * half_;
    for (int j = threadIdx.x; j < half_; j += blockDim.x) {
        float a = ip[j], b = ip[half_ + j];
        op[j] = __float2half_rn((a / (1.f + __expf(-a))) * b);
    }
}

__global__ void silu_gate_moe_k() {
    int e = blockIdx.y;
    int row = blockIdx.x;
    if (row >= g_s.counts[e]) return;
    const float* ip = g_s.h + ((long long)e * TT + row) * (2 * MIDIM);
    __half* op = g_s.hah + ((long long)e * TT + row) * MIDIM;
    for (int j = threadIdx.x; j < MIDIM; j += blockDim.x) {
        float a = ip[j], b = ip[MIDIM + j];
        op[j] = __float2half_rn((a / (1.f + __expf(-a))) * b);
    }
}

// ---------------------------------------------------------------------------
// Host-side launch helpers
// ---------------------------------------------------------------------------
static void launch_gemm(bool wide, bool outh, const __half* A, const __half* B, void* C,
                        int M, int N, int K, int lda, int ldb, int ldc,
                        long long sA, long long sB, long long sC, int bz,
                        float sc, int causal, int klim,
                        const int* aidx, const int* mdev,
                        const int* cidx, const float* cs, int pstride,
                        const float* resid = nullptr, float* C2 = nullptr,
                        int atomicC = 0)
{
    if (wide) {
        dim3 grid((N + 255) / 256, (M + 127) / 128, bz);
        if (outh)
            gemm_h<true, 256, 2, 256><<<grid, 256, SMEM_BYTES>>>(
                A, B, C, M, N, K, lda, ldb, ldc, sA, sB, sC, sc, causal, klim,
                aidx, mdev, cidx, cs, pstride, resid, C2, atomicC);
        else
            gemm_h<false, 256, 2, 256><<<grid, 256, SMEM_BYTES>>>(
                A, B, C, M, N, K, lda, ldb, ldc, sA, sB, sC, sc, causal, klim,
                aidx, mdev, cidx, cs, pstride, resid, C2, atomicC);
    } else {
        dim3 grid((N + 127) / 128, (M + 127) / 128, bz);
        if (outh)
            gemm_h<true, 128, 3, 128><<<grid, 128, SMEM_BYTES>>>(
                A, B, C, M, N, K, lda, ldb, ldc, sA, sB, sC, sc, causal, klim,
                aidx, mdev, cidx, cs, pstride, resid, C2, atomicC);
        else
            gemm_h<false, 128, 3, 128><<<grid, 128, SMEM_BYTES>>>(
                A, B, C, M, N, K, lda, ldb, ldc, sA, sB, sC, sc, causal, klim,
                aidx, mdev, cidx, cs, pstride, resid, C2, atomicC);
    }
}

static void launch_nt(bool wide, bool outh, const __half* A, const __half* B, void* C,
                      int M, int N, int K, int lda, int ldb, int ldc)
{
    launch_gemm(wide, outh, A, B, C, M, N, K, lda, ldb, ldc, 0, 0, 0, 1, 1.f, 0, 0,
                nullptr, nullptr, nullptr, nullptr, 0);
}

// ---------------------------------------------------------------------------
extern "C" void kernel_launch(void* const* d_in, const int* in_sizes, int n_in,
                              void* d_out, int out_size)
{
    const float* x    = (const float*)d_in[0];
    const float* skip = (const float*)d_in[1];
    const float* rsin = (const float*)d_in[2];
    const float* rcos = (const float*)d_in[3];
    const float* ln1  = (const float*)d_in[4];
    const float* ln2  = (const float*)d_in[5];
    const float* wqa  = (const float*)d_in[6];
    const float* qan  = (const float*)d_in[7];
    const float* wqb  = (const float*)d_in[8];
    const float* wkva = (const float*)d_in[9];
    const float* kvan = (const float*)d_in[10];
    const float* wkb  = (const float*)d_in[11];
    const float* wvb  = (const float*)d_in[12];
    const float* wo   = (const float*)d_in[13];
    const float* gw   = (const float*)d_in[14];
    const float* wup  = (const float*)d_in[15];
    const float* wdn  = (const float*)d_in[16];
    const float* wsup = (const float*)d_in[17];
    const float* wsdn = (const float*)d_in[18];
    float* out = (float*)d_out;

    Scratch* s = nullptr;
    cudaGetSymbolAddress((void**)&s, g_s);
    cudaFuncSetAttribute((const void*)gemm_h<true, 256, 2, 256>,
                         cudaFuncAttributeMaxDynamicSharedMemorySize, SMEM_BYTES);
    cudaFuncSetAttribute((const void*)gemm_h<false, 256, 2, 256>,
                         cudaFuncAttributeMaxDynamicSharedMemorySize, SMEM_BYTES);
    cudaFuncSetAttribute((const void*)gemm_h<true, 128, 3, 128>,
                         cudaFuncAttributeMaxDynamicSharedMemorySize, SMEM_BYTES);
    cudaFuncSetAttribute((const void*)gemm_h<false, 128, 3, 128>,
                         cudaFuncAttributeMaxDynamicSharedMemorySize, SMEM_BYTES);
    cudaFuncSetAttribute((const void*)flash_attn_k,
                         cudaFuncAttributeMaxDynamicSharedMemorySize, SMEM_FLASH);

    const int n = TT * HH;
    float* out2 = out + (long long)n;

    zero_counts_k<<<1, 32>>>();

    // weights -> half (vectorized)
    f2h_k<<<1024, 256>>>((const float4*)wqa,  (uint2*)s->wqa_h,  (long long)QLAT * HH / 4);
    f2h_k<<<1024, 256>>>((const float4*)wqb,  (uint2*)s->wqb_h,  (long long)NHH * DQK * QLAT / 4);
    f2h_k<<<1024, 256>>>((const float4*)wkva, (uint2*)s->wkva_h, (long long)(KVLAT + ROPED) * HH / 4);
    f2h_k<<<1024, 256>>>((const float4*)wkb,  (uint2*)s->wkb_h,  (long long)NHH * NOPE * KVLAT / 4);
    f2h_k<<<1024, 256>>>((const float4*)wvb,  (uint2*)s->wvb_h,  (long long)NHH * VDIM * KVLAT / 4);
    f2h_k<<<1024, 256>>>((const float4*)wo,   (uint2*)s->wo_h,   (long long)HH * NHH * VDIM / 4);
    f2h_k<<<1024, 256>>>((const float4*)wsup, (uint2*)s->wsup_h, (long long)2 * SHI * HH / 4);
    f2h_k<<<1024, 256>>>((const float4*)wsdn, (uint2*)s->wsdn_h, (long long)HH * SHI / 4);
    f2h_k<<<2048, 256>>>((const float4*)wup,  (uint2*)s->wup_h,  (long long)NE * 2 * MIDIM * HH / 4);
    f2h_k<<<2048, 256>>>((const float4*)wdn,  (uint2*)s->wdn_h,  (long long)NE * HH * MIDIM / 4);

    // x1 = x + skip ; n1h = rms(x1)
    add2_k<<<4096, 256>>>(x, skip, s->x1, n);
    rmsnorm_h_k<<<TT, 256>>>(s->x1, ln1, s->n1h, HH, HH, HH);

    // q path
    launch_nt(true, false, s->n1h, s->wqa_h, s->qa_pre, TT, QLAT, HH, HH, HH, QLAT);
    rmsnorm_h_k<<<TT, 256>>>(s->qa_pre, qan, s->qah, QLAT, QLAT, QLAT);
    launch_nt(true, true, s->qah, s->wqb_h, s->qh, TT, NHH * DQK, QLAT, QLAT, QLAT, NHH * DQK);
    rope_q_k<<<TT, 256>>>(s->qh, rsin, rcos);

    // kv path
    launch_nt(false, false, s->n1h, s->wkva_h, s->kv, TT, KVLAT + ROPED, HH, HH, HH, KVLAT + ROPED);
    rmsnorm_h_k<<<TT, 256>>>(s->kv, kvan, s->ckvh, KVLAT, KVLAT + ROPED, KVLAT);
    launch_nt(true, true, s->ckvh, s->wkb_h, s->knopeh, TT, NHH * NOPE, KVLAT, KVLAT, KVLAT, NHH * NOPE);
    build_k_k<<<TT, 256>>>(s->knopeh, s->kv, rsin, rcos, s->kfullh);
    launch_nt(true, true, s->wvb_h, s->ckvh, s->vTh, NHH * VDIM, TT, KVLAT, KVLAT, KVLAT, TT);

    // fused flash attention (QK + softmax + PV)
    float attn_scale = 1.0f / sqrtf((float)DQK);
    flash_attn_k<<<dim3(NHH, TT / 128), 256, SMEM_FLASH>>>(
        s->qh, s->kfullh, s->vTh, s->oh, attn_scale);

    // attn out + residual fused: out[0:n] = x2 = x1 + oh @ wo^T
    launch_gemm(true, false, s->oh, s->wo_h, out, TT, HH, NHH * VDIM,
                NHH * VDIM, NHH * VDIM, HH, 0, 0, 0, 1,
                1.f, 0, 0, nullptr, nullptr, nullptr, nullptr, 0,
                s->x1, s->x2, 0);

    // n2 and MoE gating
    rmsnorm_h_k<<<TT, 256>>>(s->x2, ln2, s->n2h, HH, HH, HH);
    gate_topk_k<<<TT, 256>>>(s->n2h, gw);

    // shared FFN -> out2 directly
    launch_nt(true, false, s->n2h, s->wsup_h, s->hs, TT, 2 * SHI, HH, HH, HH, 2 * SHI);
    silu_gate_k<<<TT, 256>>>(s->hs, s->hsah, SHI);
    launch_nt(true, false, s->hsah, s->wsdn_h, out2, TT, HH, SHI, SHI, SHI, HH);

    // routed experts: batched over blockIdx.z = expert
    launch_gemm(true, false, s->n2h, s->wup_h, s->h, TT, 2 * MIDIM, HH,
                HH, HH, 2 * MIDIM,
                0, (long long)(2 * MIDIM) * HH, (long long)TT * 2 * MIDIM, NE,
                1.f, 0, 0,
                s->tok, s->counts, nullptr, nullptr, TT);
    silu_gate_moe_k<<<dim3(TT, NE), 256>>>();
    // down: out2[tok[e][r]] += ew * (ha @ dn^T)  via atomicAdd
    launch_gemm(true, false, s->hah, s->wdn_h, out2, TT, HH, MIDIM,
                MIDIM, MIDIM, HH,
                (long long)TT * MIDIM, (long long)HH * MIDIM, 0, NE,
                1.f, 0, 0,
                nullptr, s->counts, s->tok, s->ew, TT,
                nullptr, nullptr, 1);
}

// round 11
// speedup vs baseline: 1.3391x; 1.0609x over previous
#include <cuda_runtime.h>
#include <cuda_fp16.h>
#include <math.h>
#include <stdint.h>

#define TT   2048
#define HH   2048
#define NHH  16
#define NOPE 128
#define ROPED 64
#define DQK  192     // NOPE + ROPE
#define VDIM 128
#define QLAT 1536
#define KVLAT 512
#define NE   8
#define MIDIM 512
#define SHI  1024    // 2*MI
#define QKVN (QLAT + KVLAT + ROPED)   // 2112

// ---------------------------------------------------------------------------
// Scratch (static device memory; no allocations anywhere)
// ---------------------------------------------------------------------------
struct __align__(128) Scratch {
    // f32 buffers
    float x1[TT * HH];
    float qkv_pre[TT * QKVN];            // [qa_pre | kv] fused
    float x2[TT * HH];
    float h[(long long)NE * TT * 2 * MIDIM];
    float hs[TT * 2 * SHI];
    float ew[NE * TT];
    int   tok[NE * TT];
    int   counts[NE];
    // half activation buffers
    __half n1h[TT * HH];
    __half qah[TT * QLAT];
    __half qh[TT * NHH * DQK];
    __half ckvh[TT * KVLAT];
    __half knopeh[TT * NHH * NOPE];
    __half kfullh[TT * NHH * DQK];
    __half vTh[NHH * VDIM * TT];          // [h*128+d, t]
    __half oh[TT * NHH * VDIM];
    __half n2h[TT * HH];
    __half hsah[TT * SHI];
    __half hah[(long long)NE * TT * MIDIM];
    // half weight copies
    __half wqkva_h[QKVN * HH];            // [wqa ; wkva] fused
    __half wqb_h[NHH * DQK * QLAT];
    __half wkb_h[NHH * NOPE * KVLAT];
    __half wvb_h[NHH * VDIM * KVLAT];
    __half wo_h[HH * NHH * VDIM];
    __half wsup_h[2 * SHI * HH];
    __half wsdn_h[HH * SHI];
    __half wup_h[(long long)NE * 2 * MIDIM * HH];
    __half wdn_h[(long long)NE * HH * MIDIM];
};
__device__ Scratch g_s;

// ---------------------------------------------------------------------------
// helpers
// ---------------------------------------------------------------------------
__device__ __forceinline__ uint32_t smem_u32(const void* p) {
    uint32_t a;
    asm("{ .reg .u64 t; cvta.to.shared.u64 t, %1; cvt.u32.u64 %0, t; }" : "=r"(a) : "l"(p));
    return a;
}

__device__ __forceinline__ void cp16(uint32_t dst, const void* src, int sz) {
    asm volatile("cp.async.cg.shared.global [%0], [%1], 16, %2;"
                 :: "r"(dst), "l"(src), "r"(sz));
}
__device__ __forceinline__ void cp_commit() {
    asm volatile("cp.async.commit_group;" ::: "memory");
}

__device__ __forceinline__ void ldm_x4(unsigned& r0, unsigned& r1, unsigned& r2,
                                       unsigned& r3, uint32_t addr) {
    asm volatile("ldmatrix.sync.aligned.m8n8.x4.shared.b16 {%0,%1,%2,%3}, [%4];"
                 : "=r"(r0), "=r"(r1), "=r"(r2), "=r"(r3) : "r"(addr));
}

__device__ __forceinline__ void mma_f16(float* d, const unsigned* a, const unsigned* b) {
    asm volatile(
        "mma.sync.aligned.m16n8k16.row.col.f32.f16.f16.f32 "
        "{%0,%1,%2,%3}, {%4,%5,%6,%7}, {%8,%9}, {%0,%1,%2,%3};\n"
        : "+f"(d[0]), "+f"(d[1]), "+f"(d[2]), "+f"(d[3])
        : "r"(a[0]), "r"(a[1]), "r"(a[2]), "r"(a[3]), "r"(b[0]), "r"(b[1]));
}

__device__ __forceinline__ unsigned packh2(float x, float y) {
    __half2 h = __floats2half2_rn(x, y);
    return *reinterpret_cast<unsigned*>(&h);
}

// ---------------------------------------------------------------------------
// fp16 NT GEMM (R5 config, frozen) + epilogue fusions
// ---------------------------------------------------------------------------
#define SMEM_BYTES 98304

template <bool OUTH, int NTILE, int NSTAGE, int NTHREADS>
__global__ __launch_bounds__(NTHREADS)
void gemm_h(const __half* __restrict__ A, const __half* __restrict__ B,
            void* __restrict__ Cv,
            int M, int N, int K, int lda, int ldb, int ldc,
            long long sA, long long sB, long long sC,
            float scale, int causal, int klim,
            const int* __restrict__ aidx, const int* __restrict__ mdev,
            const int* __restrict__ cidx, const float* __restrict__ cscale,
            int pstride,
            const float* __restrict__ resid, float* __restrict__ C2, int atomicC)
{
    constexpr int STG_BYTES = (128 + NTILE) * 128;
    constexpr int LOADS = (128 + NTILE) * 8 / NTHREADS;
    extern __shared__ __align__(128) char smem[];
    const int z = blockIdx.z;
    A += (long long)z * sA;
    B += (long long)z * sB;
    if (pstride) {
        if (mdev)   mdev   += z;
        if (aidx)   aidx   += (long long)z * pstride;
        if (cidx)   cidx   += (long long)z * pstride;
        if (cscale) cscale += (long long)z * pstride;
    }
    const int Meff = mdev ? *mdev : M;
    const int m0 = blockIdx.y * 128;
    const int n0 = blockIdx.x * NTILE;
    if (m0 >= Meff) return;
    if (causal && n0 > m0 + 127) return;
    const int kmax = klim ? min(K, m0 + 128) : K;
    const int ktiles = kmax >> 6;

    const uint32_t sbase = smem_u32(smem);
    const int tid = threadIdx.x;
    const int lane = tid & 31;
    const int wid = tid >> 5;
    const int wm = (wid & 1) * 64;
    const int wn = (wid >> 1) * 64;
    const int lr = lane >> 2;
    const int lm = lane & 3;

    float acc[4][8][4];
#pragma unroll
    for (int i = 0; i < 4; i++)
#pragma unroll
        for (int j = 0; j < 8; j++)
#pragma unroll
            for (int c = 0; c < 4; c++) acc[i][j][c] = 0.f;

    auto issue_stage = [&](int i) {
        const uint32_t base = sbase + (i % NSTAGE) * STG_BYTES;
        const int kt = i << 6;
#pragma unroll
        for (int it = 0; it < LOADS; it++) {
            int c = tid + it * NTHREADS;
            int row = c >> 3, ch = c & 7;
            uint32_t dst = base + row * 128 + ((ch ^ (row & 7)) << 4);
            const __half* src;
            int sz = 0;
            if (row < 128) {
                int gm = m0 + row;
                src = A;
                if (gm < Meff) {
                    int ar = aidx ? aidx[gm] : gm;
                    src = A + (long long)ar * lda + kt + ch * 8;
                    sz = 16;
                }
            } else {
                int gn = n0 + row - 128;
                src = B;
                if (gn < N) {
                    src = B + (long long)gn * ldb + kt + ch * 8;
                    sz = 16;
                }
            }
            cp16(dst, src, sz);
        }
    };

#pragma unroll
    for (int s = 0; s < NSTAGE - 1; s++) {
        if (s < ktiles) issue_stage(s);
        cp_commit();
    }

    const int a_row = lane & 15;
    const int a_h = lane >> 4;
    const int b_t = lane >> 3;
    const int b_r = lane & 7;

    for (int i = 0; i < ktiles; i++) {
        if (i + NSTAGE - 1 < ktiles) issue_stage(i + NSTAGE - 1);
        cp_commit();
        if (NSTAGE == 2)
            asm volatile("cp.async.wait_group 1;" ::: "memory");
        else
            asm volatile("cp.async.wait_group 2;" ::: "memory");
        __syncthreads();

        const uint32_t base = sbase + (i % NSTAGE) * STG_BYTES;
#pragma unroll
        for (int kk = 0; kk < 4; kk++) {
            unsigned afr[4][4], bfr[8][2];
#pragma unroll
            for (int im = 0; im < 4; im++) {
                int row = wm + im * 16 + a_row;
                int ch = kk * 2 + a_h;
                ldm_x4(afr[im][0], afr[im][1], afr[im][2], afr[im][3],
                       base + row * 128 + ((ch ^ (row & 7)) << 4));
            }
#pragma unroll
            for (int j2 = 0; j2 < 4; j2++) {
                int jn = j2 * 2 + (b_t >> 1);
                int row = 128 + wn + jn * 8 + b_r;
                int ch = kk * 2 + (b_t & 1);
                unsigned r0, r1, r2, r3;
                ldm_x4(r0, r1, r2, r3, base + row * 128 + ((ch ^ (row & 7)) << 4));
                bfr[j2 * 2][0] = r0;     bfr[j2 * 2][1] = r1;
                bfr[j2 * 2 + 1][0] = r2; bfr[j2 * 2 + 1][1] = r3;
            }
#pragma unroll
            for (int im = 0; im < 4; im++)
#pragma unroll
                for (int jn = 0; jn < 8; jn++)
                    mma_f16(acc[im][jn], afr[im], bfr[jn]);
        }
        __syncthreads();
    }

#pragma unroll
    for (int im = 0; im < 4; im++) {
#pragma unroll
        for (int part = 0; part < 2; part++) {
            int gm = m0 + wm + im * 16 + lr + part * 8;
            if (gm >= Meff) continue;
            long long crow = gm;
            float w = scale;
            if (cidx) { crow = cidx[gm]; w = scale * cscale[gm]; }
#pragma unroll
            for (int jn = 0; jn < 8; jn++) {
                int gn = n0 + wn + jn * 8 + lm * 2;
                if (gn >= N) continue;
                float vx = acc[im][jn][part * 2] * w;
                float vy = acc[im][jn][part * 2 + 1] * w;
                if (OUTH) {
                    __half* cp = (__half*)Cv + ((long long)z * sC) + crow * (long long)ldc + gn;
                    *reinterpret_cast<__half2*>(cp) = __floats2half2_rn(vx, vy);
                } else {
                    long long off = crow * (long long)ldc + gn;
                    if (resid) {
                        vx += resid[off];
                        vy += resid[off + 1];
                    }
                    float* cp = (float*)Cv + ((long long)z * sC) + off;
                    if (atomicC) {
                        atomicAdd(cp, vx);
                        atomicAdd(cp + 1, vy);
                    } else {
                        *reinterpret_cast<float2*>(cp) = make_float2(vx, vy);
                        if (C2)
                            *reinterpret_cast<float2*>(C2 + off) = make_float2(vx, vy);
                    }
                }
            }
        }
    }
}

// ---------------------------------------------------------------------------
// Flash attention: 256 threads, 8 warps x 16 q-rows; k-blocks of 64.
// ---------------------------------------------------------------------------
#define SMEM_FLASH 131072

__global__ __launch_bounds__(256, 1)
void flash_attn_k(const __half* __restrict__ Q, const __half* __restrict__ K,
                  const __half* __restrict__ Vt, __half* __restrict__ O,
                  float scale)
{
    extern __shared__ __align__(128) char smem[];
    const int h = blockIdx.x;
    const int qb = (int)gridDim.y - 1 - (int)blockIdx.y;   // heaviest first
    const int nkb = 2 * qb + 2;
    const uint32_t sb = smem_u32(smem);
    const uint32_t Qs = sb;
    const uint32_t Ks = sb + 49152;
    const uint32_t Vs = sb + 49152 + 49152;
    const int tid = threadIdx.x, lane = tid & 31, wid = tid >> 5;
    const int wq = wid * 16;
    const int lr = lane >> 2, lm = lane & 3;

    for (int c = tid; c < 3072; c += 256) {
        int row = c / 24, kc = c % 24;
        int sub = kc >> 3, ch = kc & 7;
        cp16(Qs + row * 384 + sub * 128 + ((ch ^ (row & 7)) << 4),
             Q + ((long long)(qb * 128 + row) * (NHH * DQK) + h * DQK + kc * 8), 16);
    }
    auto load_kv = [&](int kb) {
        int buf = kb & 1;
        for (int c = tid; c < 1536; c += 256) {
            int row = c / 24, kc = c % 24;
            int sub = kc >> 3, ch = kc & 7;
            cp16(Ks + buf * 24576 + row * 384 + sub * 128 + ((ch ^ (row & 7)) << 4),
                 K + ((long long)(kb * 64 + row) * (NHH * DQK) + h * DQK + kc * 8), 16);
        }
        for (int c = tid; c < 1024; c += 256) {
            int row = c >> 3, ch = c & 7;
            cp16(Vs + buf * 16384 + row * 128 + ((ch ^ (row & 7)) << 4),
                 Vt + ((long long)(h * 128 + row) * TT + kb * 64 + ch * 8), 16);
        }
    };

    load_kv(0);
    cp_commit();

    float m_s[2] = {-1e30f, -1e30f}, l_s[2] = {0.f, 0.f};
    float acc[16][4];
#pragma unroll
    for (int dn = 0; dn < 16; dn++)
#pragma unroll
        for (int c = 0; c < 4; c++) acc[dn][c] = 0.f;

    const int a_row = lane & 15, a_h = lane >> 4;
    const int b_t = lane >> 3, b_r = lane & 7;

    for (int kb = 0; kb < nkb; kb++) {
        if (kb + 1 < nkb) load_kv(kb + 1);
        cp_commit();
        asm volatile("cp.async.wait_group 1;" ::: "memory");
        __syncthreads();
        const uint32_t kbase = Ks + (kb & 1) * 24576;
        const uint32_t vbase = Vs + (kb & 1) * 16384;

        float s[8][4];
#pragma unroll
        for (int jn = 0; jn < 8; jn++)
#pragma unroll
            for (int c = 0; c < 4; c++) s[jn][c] = 0.f;

#pragma unroll
        for (int ks = 0; ks < 12; ks++) {
            unsigned afr[4], bfr[8][2];
            {
                int row = wq + a_row;
                int kc = ks * 2 + a_h;
                ldm_x4(afr[0], afr[1], afr[2], afr[3],
                       Qs + row * 384 + (kc >> 3) * 128 + (((kc & 7) ^ (row & 7)) << 4));
            }
#pragma unroll
            for (int j2 = 0; j2 < 4; j2++) {
                int jn = j2 * 2 + (b_t >> 1);
                int row = jn * 8 + b_r;
                int kc = ks * 2 + (b_t & 1);
                unsigned r0, r1, r2, r3;
                ldm_x4(r0, r1, r2, r3,
                       kbase + row * 384 + (kc >> 3) * 128 + (((kc & 7) ^ (row & 7)) << 4));
                bfr[j2 * 2][0] = r0;     bfr[j2 * 2][1] = r1;
                bfr[j2 * 2 + 1][0] = r2; bfr[j2 * 2 + 1][1] = r3;
            }
#pragma unroll
            for (int jn = 0; jn < 8; jn++)
                mma_f16(s[jn], afr, bfr[jn]);
        }

        const int coff = kb * 64 - qb * 128;
        float alpha[2];
#pragma unroll
        for (int part = 0; part < 2; part++) {
            int r = wq + lr + part * 8;
            float mx = -1e30f;
#pragma unroll
            for (int jn = 0; jn < 8; jn++) {
#pragma unroll
                for (int q = 0; q < 2; q++) {
                    int c = jn * 8 + lm * 2 + q;
                    float v = s[jn][part * 2 + q] * scale;
                    if (c + coff > r) v = -1e30f;
                    s[jn][part * 2 + q] = v;
                    mx = fmaxf(mx, v);
                }
            }
            mx = fmaxf(mx, __shfl_xor_sync(0xffffffffu, mx, 1));
            mx = fmaxf(mx, __shfl_xor_sync(0xffffffffu, mx, 2));
            float mo = m_s[part];
            float mn = fmaxf(mo, mx);
            float al = __expf(mo - mn);
            float sum = 0.f;
#pragma unroll
            for (int jn = 0; jn < 8; jn++) {
#pragma unroll
                for (int q = 0; q < 2; q++) {
                    float p = __expf(s[jn][part * 2 + q] - mn);
                    s[jn][part * 2 + q] = p;
                    sum += p;
                }
            }
            sum += __shfl_xor_sync(0xffffffffu, sum, 1);
            sum += __shfl_xor_sync(0xffffffffu, sum, 2);
            l_s[part] = l_s[part] * al + sum;
            m_s[part] = mn;
            alpha[part] = al;
        }
#pragma unroll
        for (int dn = 0; dn < 16; dn++) {
            acc[dn][0] *= alpha[0];
            acc[dn][1] *= alpha[0];
            acc[dn][2] *= alpha[1];
            acc[dn][3] *= alpha[1];
        }

#pragma unroll
        for (int kv = 0; kv < 4; kv++) {
            unsigned ap[4];
            ap[0] = packh2(s[2 * kv][0], s[2 * kv][1]);
            ap[1] = packh2(s[2 * kv][2], s[2 * kv][3]);
            ap[2] = packh2(s[2 * kv + 1][0], s[2 * kv + 1][1]);
            ap[3] = packh2(s[2 * kv + 1][2], s[2 * kv + 1][3]);
#pragma unroll
            for (int j2 = 0; j2 < 8; j2++) {
                int dn = j2 * 2 + (b_t >> 1);
                int row = dn * 8 + b_r;
                int ch = kv * 2 + (b_t & 1);
                unsigned r0, r1, r2, r3;
                ldm_x4(r0, r1, r2, r3, vbase + row * 128 + ((ch ^ (row & 7)) << 4));
                unsigned bv0[2] = {r0, r1}, bv1[2] = {r2, r3};
                mma_f16(acc[j2 * 2], ap, bv0);
                mma_f16(acc[j2 * 2 + 1], ap, bv1);
            }
        }
        __syncthreads();
    }

#pragma unroll
    for (int part = 0; part < 2; part++) {
        float inv = 1.0f / l_s[part];
        int grow = qb * 128 + wq + lr + part * 8;
        __half* op = O + (long long)grow * (NHH * VDIM) + h * VDIM;
#pragma unroll
        for (int dn = 0; dn < 16; dn++) {
            int col = dn * 8 + lm * 2;
            *reinterpret_cast<__half2*>(op + col) =
                __floats2half2_rn(acc[dn][part * 2] * inv,
                                  acc[dn][part * 2 + 1] * inv);
        }
    }
}

// ---------------------------------------------------------------------------
// Elementwise / reduction kernels
// ---------------------------------------------------------------------------
__global__ void zero_counts_k() {
    if (threadIdx.x < NE) g_s.counts[threadIdx.x] = 0;
}

// f32 -> f16, MLP=4 (four independent loads in flight)
__global__ void f2h_k(const float4* __restrict__ in, uint2* __restrict__ out,
                      long long n4) {
    const long long stride = (long long)gridDim.x * blockDim.x;
    long long i = blockIdx.x * (long long)blockDim.x + threadIdx.x;
    for (; i + 3 * stride < n4; i += 4 * stride) {
        float4 a = in[i];
        float4 b = in[i + stride];
        float4 c = in[i + 2 * stride];
        float4 d = in[i + 3 * stride];
        uint2 oa, ob, oc, od;
        __half2 t;
        t = __floats2half2_rn(a.x, a.y); oa.x = *reinterpret_cast<unsigned*>(&t);
        t = __floats2half2_rn(a.z, a.w); oa.y = *reinterpret_cast<unsigned*>(&t);
        t = __floats2half2_rn(b.x, b.y); ob.x = *reinterpret_cast<unsigned*>(&t);
        t = __floats2half2_rn(b.z, b.w); ob.y = *reinterpret_cast<unsigned*>(&t);
        t = __floats2half2_rn(c.x, c.y); oc.x = *reinterpret_cast<unsigned*>(&t);
        t = __floats2half2_rn(c.z, c.w); oc.y = *reinterpret_cast<unsigned*>(&t);
        t = __floats2half2_rn(d.x, d.y); od.x = *reinterpret_cast<unsigned*>(&t);
        t = __floats2half2_rn(d.z, d.w); od.y = *reinterpret_cast<unsigned*>(&t);
        out[i] = oa;
        out[i + stride] = ob;
        out[i + 2 * stride] = oc;
        out[i + 3 * stride] = od;
    }
    for (; i < n4; i += stride) {
        float4 v = in[i];
        __half2 h0 = __floats2half2_rn(v.x, v.y);
        __half2 h1 = __floats2half2_rn(v.z, v.w);
        uint2 o;
        o.x = *reinterpret_cast<unsigned*>(&h0);
        o.y = *reinterpret_cast<unsigned*>(&h1);
        out[i] = o;
    }
}

// fused: x1 = x + skip (stored), n1h = rms(x1)*w  (row stays in registers)
__global__ __launch_bounds__(256)
void addrms_k(const float* __restrict__ x, const float* __restrict__ skip,
              const float* __restrict__ w, float* __restrict__ x1,
              __half* __restrict__ out) {
    int row = blockIdx.x;
    const float* xp = x + (long long)row * HH;
    const float* sp = skip + (long long)row * HH;
    float* x1p = x1 + (long long)row * HH;
    float vals[8];
    float ss = 0.f;
#pragma unroll
    for (int i = 0; i < 8; i++) {
        int j = threadIdx.x + i * 256;
        float v = xp[j] + sp[j];
        vals[i] = v;
        x1p[j] = v;
        ss += v * v;
    }
    __shared__ float red[256];
    red[threadIdx.x] = ss;
    __syncthreads();
    for (int st = 128; st > 0; st >>= 1) {
        if (threadIdx.x < st) red[threadIdx.x] += red[threadIdx.x + st];
        __syncthreads();
    }
    float scale = rsqrtf(red[0] / (float)HH + 1e-6f);
    __half* op = out + (long long)row * HH;
#pragma unroll
    for (int i = 0; i < 8; i++) {
        int j = threadIdx.x + i * 256;
        op[j] = __float2half_rn(vals[i] * scale * w[j]);
    }
}

__global__ __launch_bounds__(256)
void rmsnorm_h_k(const float* __restrict__ in, const float* __restrict__ w,
                 __half* __restrict__ out, int cols, int instride, int outstride) {
    int row = blockIdx.x;
    const float* ip = in + (long long)row * instride;
    float ss = 0.f;
    for (int j = threadIdx.x; j < cols; j += 256) { float v = ip[j]; ss += v * v; }
    __shared__ float red[256];
    red[threadIdx.x] = ss;
    __syncthreads();
    for (int st = 128; st > 0; st >>= 1) {
        if (threadIdx.x < st) red[threadIdx.x] += red[threadIdx.x + st];
        __syncthreads();
    }
    float scale = rsqrtf(red[0] / (float)cols + 1e-6f);
    __half* op = out + (long long)row * outstride;
    for (int j = threadIdx.x; j < cols; j += 256)
        op[j] = __float2half_rn(ip[j] * scale * w[j]);
}

__global__ void rope_q_k(__half* __restrict__ q, const float* __restrict__ rsin,
                         const float* __restrict__ rcos) {
    int t = blockIdx.x;
    for (int i = threadIdx.x; i < NHH * 32; i += blockDim.x) {
        int h = i >> 5;
        int p = i & 31;
        __half* base = q + (long long)t * (NHH * DQK) + h * DQK + NOPE + 2 * p;
        float s = rsin[t * 32 + p], c = rcos[t * 32 + p];
        float a = __half2float(base[0]), b = __half2float(base[1]);
        base[0] = __float2half_rn(a * c - b * s);
        base[1] = __float2half_rn(a * s + b * c);
    }
}

// kv rope part now read from fused qkv_pre (stride QKVN, offset QLAT+KVLAT)
__global__ void build_k_k(const __half* __restrict__ knope, const float* __restrict__ qkv,
                          const float* __restrict__ rsin, const float* __restrict__ rcos,
                          __half* __restrict__ kfull) {
    int t = blockIdx.x;
    __shared__ __half pe[ROPED];
    if (threadIdx.x < 32) {
        int p = threadIdx.x;
        float a = qkv[(long long)t * QKVN + QLAT + KVLAT + 2 * p];
        float b = qkv[(long long)t * QKVN + QLAT + KVLAT + 2 * p + 1];
        float s = rsin[t * 32 + p], c = rcos[t * 32 + p];
        pe[2 * p]     = __float2half_rn(a * c - b * s);
        pe[2 * p + 1] = __float2half_rn(a * s + b * c);
    }
    __syncthreads();
    for (int i = threadIdx.x; i < NHH * DQK; i += blockDim.x) {
        int h = i / DQK;
        int d = i % DQK;
        kfull[(long long)t * (NHH * DQK) + i] =
            (d < NOPE) ? knope[(long long)t * (NHH * NOPE) + h * NOPE + d] : pe[d - NOPE];
    }
}

__global__ __launch_bounds__(256)
void gate_topk_k(const __half* __restrict__ n2, const float* __restrict__ gw) {
    int t = blockIdx.x;
    __shared__ float logits[NE];
    int warp = threadIdx.x >> 5, lane = threadIdx.x & 31;
    const __half* xp = n2 + (long long)t * HH;
    const float* wp = gw + warp * HH;
    float s = 0.f;
    for (int k = lane; k < HH; k += 32) s += __half2float(xp[k]) * wp[k];
    for (int off = 16; off > 0; off >>= 1) s += __shfl_down_sync(0xffffffffu, s, off);
    if (lane == 0) logits[warp] = s;
    __syncthreads();
    if (threadIdx.x == 0) {
        float m = logits[0];
        for (int e = 1; e < NE; e++) m = fmaxf(m, logits[e]);
        float p[NE];
        float sum = 0.f;
        for (int e = 0; e < NE; e++) { p[e] = __expf(logits[e] - m); sum += p[e]; }
        for (int e = 0; e < NE; e++) p[e] /= sum;
        int i0 = 0;
        for (int e = 1; e < NE; e++) if (p[e] > p[i0]) i0 = e;
        int i1 = -1;
        for (int e = 0; e < NE; e++) {
            if (e == i0) continue;
            if (i1 < 0 || p[e] > p[i1]) i1 = e;
        }
        float w0 = p[i0], w1 = p[i1];
        float tot = w0 + w1;
        w0 /= tot; w1 /= tot;
        int pos0 = atomicAdd(&g_s.counts[i0], 1);
        g_s.tok[i0 * TT + pos0] = t;
        g_s.ew[i0 * TT + pos0] = w0;
        int pos1 = atomicAdd(&g_s.counts[i1], 1);
        g_s.tok[i1 * TT + pos1] = t;
        g_s.ew[i1 * TT + pos1] = w1;
    }
}

__global__ void silu_gate_k(const float* __restrict__ in, __half* __restrict__ out,
                            int half_) {
    int row = blockIdx.x;
    const float* ip = in + (long long)row * 2 * half_;
    __half* op = out + (long long)row * half_;
    for (int j = threadIdx.x; j < half_; j += blockDim.x) {
        float a = ip[j], b = ip[half_ + j];
        op[j] = __float2half_rn((a / (1.f + __expf(-a))) * b);
    }
}

__global__ void silu_gate_moe_k() {
    int e = blockIdx.y;
    int row = blockIdx.x;
    if (row >= g_s.counts[e]) return;
    const float* ip = g_s.h + ((long long)e * TT + row) * (2 * MIDIM);
    __half* op = g_s.hah + ((long long)e * TT + row) * MIDIM;
    for (int j = threadIdx.x; j < MIDIM; j += blockDim.x) {
        float a = ip[j], b = ip[MIDIM + j];
        op[j] = __float2half_rn((a / (1.f + __expf(-a))) * b);
    }
}

// ---------------------------------------------------------------------------
// Host-side launch helpers
// ---------------------------------------------------------------------------
static void launch_gemm(bool wide, bool outh, const __half* A, const __half* B, void* C,
                        int M, int N, int K, int lda, int ldb, int ldc,
                        long long sA, long long sB, long long sC, int bz,
                        float sc, int causal, int klim,
                        const int* aidx, const int* mdev,
                        const int* cidx, const float* cs, int pstride,
                        const float* resid = nullptr, float* C2 = nullptr,
                        int atomicC = 0)
{
    if (wide) {
        dim3 grid((N + 255) / 256, (M + 127) / 128, bz);
        if (outh)
            gemm_h<true, 256, 2, 256><<<grid, 256, SMEM_BYTES>>>(
                A, B, C, M, N, K, lda, ldb, ldc, sA, sB, sC, sc, causal, klim,
                aidx, mdev, cidx, cs, pstride, resid, C2, atomicC);
        else
            gemm_h<false, 256, 2, 256><<<grid, 256, SMEM_BYTES>>>(
                A, B, C, M, N, K, lda, ldb, ldc, sA, sB, sC, sc, causal, klim,
                aidx, mdev, cidx, cs, pstride, resid, C2, atomicC);
    } else {
        dim3 grid((N + 127) / 128, (M + 127) / 128, bz);
        if (outh)
            gemm_h<true, 128, 3, 128><<<grid, 128, SMEM_BYTES>>>(
                A, B, C, M, N, K, lda, ldb, ldc, sA, sB, sC, sc, causal, klim,
                aidx, mdev, cidx, cs, pstride, resid, C2, atomicC);
        else
            gemm_h<false, 128, 3, 128><<<grid, 128, SMEM_BYTES>>>(
                A, B, C, M, N, K, lda, ldb, ldc, sA, sB, sC, sc, causal, klim,
                aidx, mdev, cidx, cs, pstride, resid, C2, atomicC);
    }
}

static void launch_nt(bool wide, bool outh, const __half* A, const __half* B, void* C,
                      int M, int N, int K, int lda, int ldb, int ldc)
{
    launch_gemm(wide, outh, A, B, C, M, N, K, lda, ldb, ldc, 0, 0, 0, 1, 1.f, 0, 0,
                nullptr, nullptr, nullptr, nullptr, 0);
}

// ---------------------------------------------------------------------------
extern "C" void kernel_launch(void* const* d_in, const int* in_sizes, int n_in,
                              void* d_out, int out_size)
{
    const float* x    = (const float*)d_in[0];
    const float* skip = (const float*)d_in[1];
    const float* rsin = (const float*)d_in[2];
    const float* rcos = (const float*)d_in[3];
    const float* ln1  = (const float*)d_in[4];
    const float* ln2  = (const float*)d_in[5];
    const float* wqa  = (const float*)d_in[6];
    const float* qan  = (const float*)d_in[7];
    const float* wqb  = (const float*)d_in[8];
    const float* wkva = (const float*)d_in[9];
    const float* kvan = (const float*)d_in[10];
    const float* wkb  = (const float*)d_in[11];
    const float* wvb  = (const float*)d_in[12];
    const float* wo   = (const float*)d_in[13];
    const float* gw   = (const float*)d_in[14];
    const float* wup  = (const float*)d_in[15];
    const float* wdn  = (const float*)d_in[16];
    const float* wsup = (const float*)d_in[17];
    const float* wsdn = (const float*)d_in[18];
    float* out = (float*)d_out;

    Scratch* s = nullptr;
    cudaGetSymbolAddress((void**)&s, g_s);
    cudaFuncSetAttribute((const void*)gemm_h<true, 256, 2, 256>,
                         cudaFuncAttributeMaxDynamicSharedMemorySize, SMEM_BYTES);
    cudaFuncSetAttribute((const void*)gemm_h<false, 256, 2, 256>,
                         cudaFuncAttributeMaxDynamicSharedMemorySize, SMEM_BYTES);
    cudaFuncSetAttribute((const void*)gemm_h<true, 128, 3, 128>,
                         cudaFuncAttributeMaxDynamicSharedMemorySize, SMEM_BYTES);
    cudaFuncSetAttribute((const void*)gemm_h<false, 128, 3, 128>,
                         cudaFuncAttributeMaxDynamicSharedMemorySize, SMEM_BYTES);
    cudaFuncSetAttribute((const void*)flash_attn_k,
                         cudaFuncAttributeMaxDynamicSharedMemorySize, SMEM_FLASH);

    const int n = TT * HH;
    float* out2 = out + (long long)n;

    zero_counts_k<<<1, 32>>>();

    // weights -> half (MLP=4 conversion); wqa+wkva fused into one buffer
    f2h_k<<<1024, 256>>>((const float4*)wqa,  (uint2*)s->wqkva_h, (long long)QLAT * HH / 4);
    f2h_k<<<1024, 256>>>((const float4*)wkva, (uint2*)(s->wqkva_h + (long long)QLAT * HH),
                         (long long)(KVLAT + ROPED) * HH / 4);
    f2h_k<<<1024, 256>>>((const float4*)wqb,  (uint2*)s->wqb_h,  (long long)NHH * DQK * QLAT / 4);
    f2h_k<<<1024, 256>>>((const float4*)wkb,  (uint2*)s->wkb_h,  (long long)NHH * NOPE * KVLAT / 4);
    f2h_k<<<1024, 256>>>((const float4*)wvb,  (uint2*)s->wvb_h,  (long long)NHH * VDIM * KVLAT / 4);
    f2h_k<<<1024, 256>>>((const float4*)wo,   (uint2*)s->wo_h,   (long long)HH * NHH * VDIM / 4);
    f2h_k<<<1024, 256>>>((const float4*)wsup, (uint2*)s->wsup_h, (long long)2 * SHI * HH / 4);
    f2h_k<<<1024, 256>>>((const float4*)wsdn, (uint2*)s->wsdn_h, (long long)HH * SHI / 4);
    f2h_k<<<2048, 256>>>((const float4*)wup,  (uint2*)s->wup_h,  (long long)NE * 2 * MIDIM * HH / 4);
    f2h_k<<<2048, 256>>>((const float4*)wdn,  (uint2*)s->wdn_h,  (long long)NE * HH * MIDIM / 4);

    // x1 = x + skip ; n1h = rms(x1)   (fused)
    addrms_k<<<TT, 256>>>(x, skip, ln1, s->x1, s->n1h);

    // fused qa+kva projection: qkv_pre[T, 2112] = n1h @ [wqa; wkva]^T
    launch_nt(true, false, s->n1h, s->wqkva_h, s->qkv_pre, TT, QKVN, HH, HH, HH, QKVN);

    // q path
    rmsnorm_h_k<<<TT, 256>>>(s->qkv_pre, qan, s->qah, QLAT, QKVN, QLAT);
    launch_nt(true, true, s->qah, s->wqb_h, s->qh, TT, NHH * DQK, QLAT, QLAT, QLAT, NHH * DQK);
    rope_q_k<<<TT, 256>>>(s->qh, rsin, rcos);

    // kv path
    rmsnorm_h_k<<<TT, 256>>>(s->qkv_pre + QLAT, kvan, s->ckvh, KVLAT, QKVN, KVLAT);
    launch_nt(true, true, s->ckvh, s->wkb_h, s->knopeh, TT, NHH * NOPE, KVLAT, KVLAT, KVLAT, NHH * NOPE);
    build_k_k<<<TT, 256>>>(s->knopeh, s->qkv_pre, rsin, rcos, s->kfullh);
    launch_nt(true, true, s->wvb_h, s->ckvh, s->vTh, NHH * VDIM, TT, KVLAT, KVLAT, KVLAT, TT);

    // fused flash attention (QK + softmax + PV)
    float attn_scale = 1.0f / sqrtf((float)DQK);
    flash_attn_k<<<dim3(NHH, TT / 128), 256, SMEM_FLASH>>>(
        s->qh, s->kfullh, s->vTh, s->oh, attn_scale);

    // attn out + residual fused: out[0:n] = x2 = x1 + oh @ wo^T
    launch_gemm(true, false, s->oh, s->wo_h, out, TT, HH, NHH * VDIM,
                NHH * VDIM, NHH * VDIM, HH, 0, 0, 0, 1,
                1.f, 0, 0, nullptr, nullptr, nullptr, nullptr, 0,
                s->x1, s->x2, 0);

    // n2 and MoE gating
    rmsnorm_h_k<<<TT, 256>>>(s->x2, ln2, s->n2h, HH, HH, HH);
    gate_topk_k<<<TT, 256>>>(s->n2h, gw);

    // shared FFN -> out2 directly
    launch_nt(true, false, s->n2h, s->wsup_h, s->hs, TT, 2 * SHI, HH, HH, HH, 2 * SHI);
    silu_gate_k<<<TT, 256>>>(s->hs, s->hsah, SHI);
    launch_nt(true, false, s->hsah, s->wsdn_h, out2, TT, HH, SHI, SHI, SHI, HH);

    // routed experts: batched over blockIdx.z = expert
    launch_gemm(true, false, s->n2h, s->wup_h, s->h, TT, 2 * MIDIM, HH,
                HH, HH, 2 * MIDIM,
                0, (long long)(2 * MIDIM) * HH, (long long)TT * 2 * MIDIM, NE,
                1.f, 0, 0,
                s->tok, s->counts, nullptr, nullptr, TT);
    silu_gate_moe_k<<<dim3(TT, NE), 256>>>();
    // down: out2[tok[e][r]] += ew * (ha @ dn^T)  via atomicAdd
    launch_gemm(true, false, s->hah, s->wdn_h, out2, TT, HH, MIDIM,
                MIDIM, MIDIM, HH,
                (long long)TT * MIDIM, (long long)HH * MIDIM, 0, NE,
                1.f, 0, 0,
                nullptr, s->counts, s->tok, s->ew, TT,
                nullptr, nullptr, 1);
}

// round 12
// speedup vs baseline: 1.3430x; 1.0029x over previous
#include <cuda_runtime.h>
#include <cuda_fp16.h>
#include <math.h>
#include <stdint.h>

#define TT   2048
#define HH   2048
#define NHH  16
#define NOPE 128
#define ROPED 64
#define DQK  192     // NOPE + ROPE
#define VDIM 128
#define QLAT 1536
#define KVLAT 512
#define NE   8
#define MIDIM 512
#define SHI  1024    // 2*MI
#define QKVN (QLAT + KVLAT + ROPED)   // 2112

// ---------------------------------------------------------------------------
// Scratch (static device memory; no allocations anywhere)
// ---------------------------------------------------------------------------
struct __align__(128) Scratch {
    // f32 buffers
    float x1[TT * HH];
    float qkv_pre[TT * QKVN];            // [qa_pre | kv] fused
    float x2[TT * HH];
    float h[(long long)NE * TT * 2 * MIDIM];
    float hs[TT * 2 * SHI];
    float ew[NE * TT];
    int   tok[NE * TT];
    int   counts[NE];
    // half activation buffers
    __half n1h[TT * HH];
    __half qah[TT * QLAT];
    __half qh[TT * NHH * DQK];
    __half ckvh[TT * KVLAT];
    __half knopeh[TT * NHH * NOPE];
    __half kfullh[TT * NHH * DQK];
    __half vTh[NHH * VDIM * TT];          // [h*128+d, t]
    __half oh[TT * NHH * VDIM];
    __half n2h[TT * HH];
    __half hsah[TT * SHI];
    __half hah[(long long)NE * TT * MIDIM];
    // half weight copies
    __half wqkva_h[QKVN * HH];            // [wqa ; wkva] fused
    __half wqb_h[NHH * DQK * QLAT];
    __half wkb_h[NHH * NOPE * KVLAT];
    __half wvb_h[NHH * VDIM * KVLAT];
    __half wo_h[HH * NHH * VDIM];
    __half wsup_h[2 * SHI * HH];
    __half wsdn_h[HH * SHI];
    __half wup_h[(long long)NE * 2 * MIDIM * HH];
    __half wdn_h[(long long)NE * HH * MIDIM];
};
__device__ Scratch g_s;

// ---------------------------------------------------------------------------
// helpers
// ---------------------------------------------------------------------------
__device__ __forceinline__ uint32_t smem_u32(const void* p) {
    uint32_t a;
    asm("{ .reg .u64 t; cvta.to.shared.u64 t, %1; cvt.u32.u64 %0, t; }" : "=r"(a) : "l"(p));
    return a;
}

__device__ __forceinline__ void cp16(uint32_t dst, const void* src, int sz) {
    asm volatile("cp.async.cg.shared.global [%0], [%1], 16, %2;"
                 :: "r"(dst), "l"(src), "r"(sz));
}
__device__ __forceinline__ void cp_commit() {
    asm volatile("cp.async.commit_group;" ::: "memory");
}

__device__ __forceinline__ void ldm_x4(unsigned& r0, unsigned& r1, unsigned& r2,
                                       unsigned& r3, uint32_t addr) {
    asm volatile("ldmatrix.sync.aligned.m8n8.x4.shared.b16 {%0,%1,%2,%3}, [%4];"
                 : "=r"(r0), "=r"(r1), "=r"(r2), "=r"(r3) : "r"(addr));
}

__device__ __forceinline__ void mma_f16(float* d, const unsigned* a, const unsigned* b) {
    asm volatile(
        "mma.sync.aligned.m16n8k16.row.col.f32.f16.f16.f32 "
        "{%0,%1,%2,%3}, {%4,%5,%6,%7}, {%8,%9}, {%0,%1,%2,%3};\n"
        : "+f"(d[0]), "+f"(d[1]), "+f"(d[2]), "+f"(d[3])
        : "r"(a[0]), "r"(a[1]), "r"(a[2]), "r"(a[3]), "r"(b[0]), "r"(b[1]));
}

__device__ __forceinline__ unsigned packh2(float x, float y) {
    __half2 h = __floats2half2_rn(x, y);
    return *reinterpret_cast<unsigned*>(&h);
}

__device__ __forceinline__ uint2 cvt4(float4 v) {
    __half2 h0 = __floats2half2_rn(v.x, v.y);
    __half2 h1 = __floats2half2_rn(v.z, v.w);
    uint2 o;
    o.x = *reinterpret_cast<unsigned*>(&h0);
    o.y = *reinterpret_cast<unsigned*>(&h1);
    return o;
}

// ---------------------------------------------------------------------------
// fp16 NT GEMM (R5 config, frozen) + epilogue fusions
// ---------------------------------------------------------------------------
#define SMEM_BYTES 98304

template <bool OUTH, int NTILE, int NSTAGE, int NTHREADS>
__global__ __launch_bounds__(NTHREADS)
void gemm_h(const __half* __restrict__ A, const __half* __restrict__ B,
            void* __restrict__ Cv,
            int M, int N, int K, int lda, int ldb, int ldc,
            long long sA, long long sB, long long sC,
            float scale, int causal, int klim,
            const int* __restrict__ aidx, const int* __restrict__ mdev,
            const int* __restrict__ cidx, const float* __restrict__ cscale,
            int pstride,
            const float* __restrict__ resid, float* __restrict__ C2, int atomicC)
{
    constexpr int STG_BYTES = (128 + NTILE) * 128;
    constexpr int LOADS = (128 + NTILE) * 8 / NTHREADS;
    extern __shared__ __align__(128) char smem[];
    const int z = blockIdx.z;
    A += (long long)z * sA;
    B += (long long)z * sB;
    if (pstride) {
        if (mdev)   mdev   += z;
        if (aidx)   aidx   += (long long)z * pstride;
        if (cidx)   cidx   += (long long)z * pstride;
        if (cscale) cscale += (long long)z * pstride;
    }
    const int Meff = mdev ? *mdev : M;
    const int m0 = blockIdx.y * 128;
    const int n0 = blockIdx.x * NTILE;
    if (m0 >= Meff) return;
    if (causal && n0 > m0 + 127) return;
    const int kmax = klim ? min(K, m0 + 128) : K;
    const int ktiles = kmax >> 6;

    const uint32_t sbase = smem_u32(smem);
    const int tid = threadIdx.x;
    const int lane = tid & 31;
    const int wid = tid >> 5;
    const int wm = (wid & 1) * 64;
    const int wn = (wid >> 1) * 64;
    const int lr = lane >> 2;
    const int lm = lane & 3;

    float acc[4][8][4];
#pragma unroll
    for (int i = 0; i < 4; i++)
#pragma unroll
        for (int j = 0; j < 8; j++)
#pragma unroll
            for (int c = 0; c < 4; c++) acc[i][j][c] = 0.f;

    auto issue_stage = [&](int i) {
        const uint32_t base = sbase + (i % NSTAGE) * STG_BYTES;
        const int kt = i << 6;
#pragma unroll
        for (int it = 0; it < LOADS; it++) {
            int c = tid + it * NTHREADS;
            int row = c >> 3, ch = c & 7;
            uint32_t dst = base + row * 128 + ((ch ^ (row & 7)) << 4);
            const __half* src;
            int sz = 0;
            if (row < 128) {
                int gm = m0 + row;
                src = A;
                if (gm < Meff) {
                    int ar = aidx ? aidx[gm] : gm;
                    src = A + (long long)ar * lda + kt + ch * 8;
                    sz = 16;
                }
            } else {
                int gn = n0 + row - 128;
                src = B;
                if (gn < N) {
                    src = B + (long long)gn * ldb + kt + ch * 8;
                    sz = 16;
                }
            }
            cp16(dst, src, sz);
        }
    };

#pragma unroll
    for (int s = 0; s < NSTAGE - 1; s++) {
        if (s < ktiles) issue_stage(s);
        cp_commit();
    }

    const int a_row = lane & 15;
    const int a_h = lane >> 4;
    const int b_t = lane >> 3;
    const int b_r = lane & 7;

    for (int i = 0; i < ktiles; i++) {
        if (i + NSTAGE - 1 < ktiles) issue_stage(i + NSTAGE - 1);
        cp_commit();
        if (NSTAGE == 2)
            asm volatile("cp.async.wait_group 1;" ::: "memory");
        else
            asm volatile("cp.async.wait_group 2;" ::: "memory");
        __syncthreads();

        const uint32_t base = sbase + (i % NSTAGE) * STG_BYTES;
#pragma unroll
        for (int kk = 0; kk < 4; kk++) {
            unsigned afr[4][4], bfr[8][2];
#pragma unroll
            for (int im = 0; im < 4; im++) {
                int row = wm + im * 16 + a_row;
                int ch = kk * 2 + a_h;
                ldm_x4(afr[im][0], afr[im][1], afr[im][2], afr[im][3],
                       base + row * 128 + ((ch ^ (row & 7)) << 4));
            }
#pragma unroll
            for (int j2 = 0; j2 < 4; j2++) {
                int jn = j2 * 2 + (b_t >> 1);
                int row = 128 + wn + jn * 8 + b_r;
                int ch = kk * 2 + (b_t & 1);
                unsigned r0, r1, r2, r3;
                ldm_x4(r0, r1, r2, r3, base + row * 128 + ((ch ^ (row & 7)) << 4));
                bfr[j2 * 2][0] = r0;     bfr[j2 * 2][1] = r1;
                bfr[j2 * 2 + 1][0] = r2; bfr[j2 * 2 + 1][1] = r3;
            }
#pragma unroll
            for (int im = 0; im < 4; im++)
#pragma unroll
                for (int jn = 0; jn < 8; jn++)
                    mma_f16(acc[im][jn], afr[im], bfr[jn]);
        }
        __syncthreads();
    }

#pragma unroll
    for (int im = 0; im < 4; im++) {
#pragma unroll
        for (int part = 0; part < 2; part++) {
            int gm = m0 + wm + im * 16 + lr + part * 8;
            if (gm >= Meff) continue;
            long long crow = gm;
            float w = scale;
            if (cidx) { crow = cidx[gm]; w = scale * cscale[gm]; }
#pragma unroll
            for (int jn = 0; jn < 8; jn++) {
                int gn = n0 + wn + jn * 8 + lm * 2;
                if (gn >= N) continue;
                float vx = acc[im][jn][part * 2] * w;
                float vy = acc[im][jn][part * 2 + 1] * w;
                if (OUTH) {
                    __half* cp = (__half*)Cv + ((long long)z * sC) + crow * (long long)ldc + gn;
                    *reinterpret_cast<__half2*>(cp) = __floats2half2_rn(vx, vy);
                } else {
                    long long off = crow * (long long)ldc + gn;
                    if (resid) {
                        vx += resid[off];
                        vy += resid[off + 1];
                    }
                    float* cp = (float*)Cv + ((long long)z * sC) + off;
                    if (atomicC) {
                        atomicAdd(cp, vx);
                        atomicAdd(cp + 1, vy);
                    } else {
                        *reinterpret_cast<float2*>(cp) = make_float2(vx, vy);
                        if (C2)
                            *reinterpret_cast<float2*>(C2 + off) = make_float2(vx, vy);
                    }
                }
            }
        }
    }
}

// ---------------------------------------------------------------------------
// Flash attention: 256 threads, 8 warps x 16 q-rows; k-blocks of 64.
// ---------------------------------------------------------------------------
#define SMEM_FLASH 131072

__global__ __launch_bounds__(256, 1)
void flash_attn_k(const __half* __restrict__ Q, const __half* __restrict__ K,
                  const __half* __restrict__ Vt, __half* __restrict__ O,
                  float scale)
{
    extern __shared__ __align__(128) char smem[];
    const int h = blockIdx.x;
    const int qb = (int)gridDim.y - 1 - (int)blockIdx.y;   // heaviest first
    const int nkb = 2 * qb + 2;
    const uint32_t sb = smem_u32(smem);
    const uint32_t Qs = sb;
    const uint32_t Ks = sb + 49152;
    const uint32_t Vs = sb + 49152 + 49152;
    const int tid = threadIdx.x, lane = tid & 31, wid = tid >> 5;
    const int wq = wid * 16;
    const int lr = lane >> 2, lm = lane & 3;

    for (int c = tid; c < 3072; c += 256) {
        int row = c / 24, kc = c % 24;
        int sub = kc >> 3, ch = kc & 7;
        cp16(Qs + row * 384 + sub * 128 + ((ch ^ (row & 7)) << 4),
             Q + ((long long)(qb * 128 + row) * (NHH * DQK) + h * DQK + kc * 8), 16);
    }
    auto load_kv = [&](int kb) {
        int buf = kb & 1;
        for (int c = tid; c < 1536; c += 256) {
            int row = c / 24, kc = c % 24;
            int sub = kc >> 3, ch = kc & 7;
            cp16(Ks + buf * 24576 + row * 384 + sub * 128 + ((ch ^ (row & 7)) << 4),
                 K + ((long long)(kb * 64 + row) * (NHH * DQK) + h * DQK + kc * 8), 16);
        }
        for (int c = tid; c < 1024; c += 256) {
            int row = c >> 3, ch = c & 7;
            cp16(Vs + buf * 16384 + row * 128 + ((ch ^ (row & 7)) << 4),
                 Vt + ((long long)(h * 128 + row) * TT + kb * 64 + ch * 8), 16);
        }
    };

    load_kv(0);
    cp_commit();

    float m_s[2] = {-1e30f, -1e30f}, l_s[2] = {0.f, 0.f};
    float acc[16][4];
#pragma unroll
    for (int dn = 0; dn < 16; dn++)
#pragma unroll
        for (int c = 0; c < 4; c++) acc[dn][c] = 0.f;

    const int a_row = lane & 15, a_h = lane >> 4;
    const int b_t = lane >> 3, b_r = lane & 7;

    for (int kb = 0; kb < nkb; kb++) {
        if (kb + 1 < nkb) load_kv(kb + 1);
        cp_commit();
        asm volatile("cp.async.wait_group 1;" ::: "memory");
        __syncthreads();
        const uint32_t kbase = Ks + (kb & 1) * 24576;
        const uint32_t vbase = Vs + (kb & 1) * 16384;

        float s[8][4];
#pragma unroll
        for (int jn = 0; jn < 8; jn++)
#pragma unroll
            for (int c = 0; c < 4; c++) s[jn][c] = 0.f;

#pragma unroll
        for (int ks = 0; ks < 12; ks++) {
            unsigned afr[4], bfr[8][2];
            {
                int row = wq + a_row;
                int kc = ks * 2 + a_h;
                ldm_x4(afr[0], afr[1], afr[2], afr[3],
                       Qs + row * 384 + (kc >> 3) * 128 + (((kc & 7) ^ (row & 7)) << 4));
            }
#pragma unroll
            for (int j2 = 0; j2 < 4; j2++) {
                int jn = j2 * 2 + (b_t >> 1);
                int row = jn * 8 + b_r;
                int kc = ks * 2 + (b_t & 1);
                unsigned r0, r1, r2, r3;
                ldm_x4(r0, r1, r2, r3,
                       kbase + row * 384 + (kc >> 3) * 128 + (((kc & 7) ^ (row & 7)) << 4));
                bfr[j2 * 2][0] = r0;     bfr[j2 * 2][1] = r1;
                bfr[j2 * 2 + 1][0] = r2; bfr[j2 * 2 + 1][1] = r3;
            }
#pragma unroll
            for (int jn = 0; jn < 8; jn++)
                mma_f16(s[jn], afr, bfr[jn]);
        }

        const int coff = kb * 64 - qb * 128;
        float alpha[2];
#pragma unroll
        for (int part = 0; part < 2; part++) {
            int r = wq + lr + part * 8;
            float mx = -1e30f;
#pragma unroll
            for (int jn = 0; jn < 8; jn++) {
#pragma unroll
                for (int q = 0; q < 2; q++) {
                    int c = jn * 8 + lm * 2 + q;
                    float v = s[jn][part * 2 + q] * scale;
                    if (c + coff > r) v = -1e30f;
                    s[jn][part * 2 + q] = v;
                    mx = fmaxf(mx, v);
                }
            }
            mx = fmaxf(mx, __shfl_xor_sync(0xffffffffu, mx, 1));
            mx = fmaxf(mx, __shfl_xor_sync(0xffffffffu, mx, 2));
            float mo = m_s[part];
            float mn = fmaxf(mo, mx);
            float al = __expf(mo - mn);
            float sum = 0.f;
#pragma unroll
            for (int jn = 0; jn < 8; jn++) {
#pragma unroll
                for (int q = 0; q < 2; q++) {
                    float p = __expf(s[jn][part * 2 + q] - mn);
                    s[jn][part * 2 + q] = p;
                    sum += p;
                }
            }
            sum += __shfl_xor_sync(0xffffffffu, sum, 1);
            sum += __shfl_xor_sync(0xffffffffu, sum, 2);
            l_s[part] = l_s[part] * al + sum;
            m_s[part] = mn;
            alpha[part] = al;
        }
#pragma unroll
        for (int dn = 0; dn < 16; dn++) {
            acc[dn][0] *= alpha[0];
            acc[dn][1] *= alpha[0];
            acc[dn][2] *= alpha[1];
            acc[dn][3] *= alpha[1];
        }

#pragma unroll
        for (int kv = 0; kv < 4; kv++) {
            unsigned ap[4];
            ap[0] = packh2(s[2 * kv][0], s[2 * kv][1]);
            ap[1] = packh2(s[2 * kv][2], s[2 * kv][3]);
            ap[2] = packh2(s[2 * kv + 1][0], s[2 * kv + 1][1]);
            ap[3] = packh2(s[2 * kv + 1][2], s[2 * kv + 1][3]);
#pragma unroll
            for (int j2 = 0; j2 < 8; j2++) {
                int dn = j2 * 2 + (b_t >> 1);
                int row = dn * 8 + b_r;
                int ch = kv * 2 + (b_t & 1);
                unsigned r0, r1, r2, r3;
                ldm_x4(r0, r1, r2, r3, vbase + row * 128 + ((ch ^ (row & 7)) << 4));
                unsigned bv0[2] = {r0, r1}, bv1[2] = {r2, r3};
                mma_f16(acc[j2 * 2], ap, bv0);
                mma_f16(acc[j2 * 2 + 1], ap, bv1);
            }
        }
        __syncthreads();
    }

#pragma unroll
    for (int part = 0; part < 2; part++) {
        float inv = 1.0f / l_s[part];
        int grow = qb * 128 + wq + lr + part * 8;
        __half* op = O + (long long)grow * (NHH * VDIM) + h * VDIM;
#pragma unroll
        for (int dn = 0; dn < 16; dn++) {
            int col = dn * 8 + lm * 2;
            *reinterpret_cast<__half2*>(op + col) =
                __floats2half2_rn(acc[dn][part * 2] * inv,
                                  acc[dn][part * 2 + 1] * inv);
        }
    }
}

// ---------------------------------------------------------------------------
// Elementwise / reduction kernels
// ---------------------------------------------------------------------------
__global__ void zero_counts_k() {
    if (threadIdx.x < NE) g_s.counts[threadIdx.x] = 0;
}

// f32 -> f16: 4 CONSECUTIVE float4 per thread -> guaranteed MLP=4.
// n4 must be a multiple of 4 (all sizes are multiples of 16 floats).
__global__ void f2h_k(const float4* __restrict__ in, uint2* __restrict__ out,
                      long long n4) {
    const long long stride4 = 4LL * gridDim.x * blockDim.x;
    for (long long base = 4LL * (blockIdx.x * (long long)blockDim.x + threadIdx.x);
         base < n4; base += stride4) {
        float4 a = in[base];
        float4 b = in[base + 1];
        float4 c = in[base + 2];
        float4 d = in[base + 3];
        out[base]     = cvt4(a);
        out[base + 1] = cvt4(b);
        out[base + 2] = cvt4(c);
        out[base + 3] = cvt4(d);
    }
}

// fused: x1 = x + skip (stored), n1h = rms(x1)*w  (row stays in registers)
__global__ __launch_bounds__(256)
void addrms_k(const float* __restrict__ x, const float* __restrict__ skip,
              const float* __restrict__ w, float* __restrict__ x1,
              __half* __restrict__ out) {
    int row = blockIdx.x;
    const float4* xp = (const float4*)(x + (long long)row * HH);
    const float4* sp = (const float4*)(skip + (long long)row * HH);
    float4* x1p = (float4*)(x1 + (long long)row * HH);
    float4 vals[2];
    float ss = 0.f;
#pragma unroll
    for (int i = 0; i < 2; i++) {
        int j = threadIdx.x + i * 256;
        float4 a = xp[j], b = sp[j];
        float4 v = make_float4(a.x + b.x, a.y + b.y, a.z + b.z, a.w + b.w);
        vals[i] = v;
        x1p[j] = v;
        ss += v.x * v.x + v.y * v.y + v.z * v.z + v.w * v.w;
    }
    __shared__ float red[256];
    red[threadIdx.x] = ss;
    __syncthreads();
    for (int st = 128; st > 0; st >>= 1) {
        if (threadIdx.x < st) red[threadIdx.x] += red[threadIdx.x + st];
        __syncthreads();
    }
    float scale = rsqrtf(red[0] / (float)HH + 1e-6f);
    uint2* op = (uint2*)(out + (long long)row * HH);
    const float4* wp = (const float4*)w;
#pragma unroll
    for (int i = 0; i < 2; i++) {
        int j = threadIdx.x + i * 256;
        float4 v = vals[i], ww = wp[j];
        op[j] = cvt4(make_float4(v.x * scale * ww.x, v.y * scale * ww.y,
                                 v.z * scale * ww.z, v.w * scale * ww.w));
    }
}

// f32 in -> half out, vectorized (cols % 4 == 0, strides % 4 == 0)
__global__ __launch_bounds__(256)
void rmsnorm_h_k(const float* __restrict__ in, const float* __restrict__ w,
                 __half* __restrict__ out, int cols, int instride, int outstride) {
    int row = blockIdx.x;
    const float4* ip = (const float4*)(in + (long long)row * instride);
    int c4 = cols >> 2;
    float ss = 0.f;
    for (int j = threadIdx.x; j < c4; j += 256) {
        float4 v = ip[j];
        ss += v.x * v.x + v.y * v.y + v.z * v.z + v.w * v.w;
    }
    __shared__ float red[256];
    red[threadIdx.x] = ss;
    __syncthreads();
    for (int st = 128; st > 0; st >>= 1) {
        if (threadIdx.x < st) red[threadIdx.x] += red[threadIdx.x + st];
        __syncthreads();
    }
    float scale = rsqrtf(red[0] / (float)cols + 1e-6f);
    uint2* op = (uint2*)(out + (long long)row * outstride);
    const float4* wp = (const float4*)w;
    for (int j = threadIdx.x; j < c4; j += 256) {
        float4 v = ip[j], ww = wp[j];
        op[j] = cvt4(make_float4(v.x * scale * ww.x, v.y * scale * ww.y,
                                 v.z * scale * ww.z, v.w * scale * ww.w));
    }
}

__global__ void rope_q_k(__half* __restrict__ q, const float* __restrict__ rsin,
                         const float* __restrict__ rcos) {
    int t = blockIdx.x;
    for (int i = threadIdx.x; i < NHH * 32; i += blockDim.x) {
        int h = i >> 5;
        int p = i & 31;
        __half* base = q + (long long)t * (NHH * DQK) + h * DQK + NOPE + 2 * p;
        float s = rsin[t * 32 + p], c = rcos[t * 32 + p];
        float a = __half2float(base[0]), b = __half2float(base[1]);
        base[0] = __float2half_rn(a * c - b * s);
        base[1] = __float2half_rn(a * s + b * c);
    }
}

// kv rope part read from fused qkv_pre (stride QKVN, offset QLAT+KVLAT)
__global__ void build_k_k(const __half* __restrict__ knope, const float* __restrict__ qkv,
                          const float* __restrict__ rsin, const float* __restrict__ rcos,
                          __half* __restrict__ kfull) {
    int t = blockIdx.x;
    __shared__ __half pe[ROPED];
    if (threadIdx.x < 32) {
        int p = threadIdx.x;
        float a = qkv[(long long)t * QKVN + QLAT + KVLAT + 2 * p];
        float b = qkv[(long long)t * QKVN + QLAT + KVLAT + 2 * p + 1];
        float s = rsin[t * 32 + p], c = rcos[t * 32 + p];
        pe[2 * p]     = __float2half_rn(a * c - b * s);
        pe[2 * p + 1] = __float2half_rn(a * s + b * c);
    }
    __syncthreads();
    for (int i = threadIdx.x; i < NHH * DQK; i += blockDim.x) {
        int h = i / DQK;
        int d = i % DQK;
        kfull[(long long)t * (NHH * DQK) + i] =
            (d < NOPE) ? knope[(long long)t * (NHH * NOPE) + h * NOPE + d] : pe[d - NOPE];
    }
}

__global__ __launch_bounds__(256)
void gate_topk_k(const __half* __restrict__ n2, const float* __restrict__ gw) {
    int t = blockIdx.x;
    __shared__ float logits[NE];
    int warp = threadIdx.x >> 5, lane = threadIdx.x & 31;
    const __half* xp = n2 + (long long)t * HH;
    const float* wp = gw + warp * HH;
    float s = 0.f;
    for (int k = lane; k < HH; k += 32) s += __half2float(xp[k]) * wp[k];
    for (int off = 16; off > 0; off >>= 1) s += __shfl_down_sync(0xffffffffu, s, off);
    if (lane == 0) logits[warp] = s;
    __syncthreads();
    if (threadIdx.x == 0) {
        float m = logits[0];
        for (int e = 1; e < NE; e++) m = fmaxf(m, logits[e]);
        float p[NE];
        float sum = 0.f;
        for (int e = 0; e < NE; e++) { p[e] = __expf(logits[e] - m); sum += p[e]; }
        for (int e = 0; e < NE; e++) p[e] /= sum;
        int i0 = 0;
        for (int e = 1; e < NE; e++) if (p[e] > p[i0]) i0 = e;
        int i1 = -1;
        for (int e = 0; e < NE; e++) {
            if (e == i0) continue;
            if (i1 < 0 || p[e] > p[i1]) i1 = e;
        }
        float w0 = p[i0], w1 = p[i1];
        float tot = w0 + w1;
        w0 /= tot; w1 /= tot;
        int pos0 = atomicAdd(&g_s.counts[i0], 1);
        g_s.tok[i0 * TT + pos0] = t;
        g_s.ew[i0 * TT + pos0] = w0;
        int pos1 = atomicAdd(&g_s.counts[i1], 1);
        g_s.tok[i1 * TT + pos1] = t;
        g_s.ew[i1 * TT + pos1] = w1;
    }
}

// vectorized silu-gate (half_ % 4 == 0)
__global__ void silu_gate_k(const float* __restrict__ in, __half* __restrict__ out,
                            int half_) {
    int row = blockIdx.x;
    const float4* ip = (const float4*)(in + (long long)row * 2 * half_);
    const float4* gp = (const float4*)(in + (long long)row * 2 * half_ + half_);
    uint2* op = (uint2*)(out + (long long)row * half_);
    int h4 = half_ >> 2;
    for (int j = threadIdx.x; j < h4; j += blockDim.x) {
        float4 a = ip[j], b = gp[j];
        float4 r;
        r.x = (a.x / (1.f + __expf(-a.x))) * b.x;
        r.y = (a.y / (1.f + __expf(-a.y))) * b.y;
        r.z = (a.z / (1.f + __expf(-a.z))) * b.z;
        r.w = (a.w / (1.f + __expf(-a.w))) * b.w;
        op[j] = cvt4(r);
    }
}

__global__ void silu_gate_moe_k() {
    int e = blockIdx.y;
    int row = blockIdx.x;
    if (row >= g_s.counts[e]) return;
    const float* base = g_s.h + ((long long)e * TT + row) * (2 * MIDIM);
    const float4* ip = (const float4*)base;
    const float4* gp = (const float4*)(base + MIDIM);
    uint2* op = (uint2*)(g_s.hah + ((long long)e * TT + row) * MIDIM);
    for (int j = threadIdx.x; j < (MIDIM >> 2); j += blockDim.x) {
        float4 a = ip[j], b = gp[j];
        float4 r;
        r.x = (a.x / (1.f + __expf(-a.x))) * b.x;
        r.y = (a.y / (1.f + __expf(-a.y))) * b.y;
        r.z = (a.z / (1.f + __expf(-a.z))) * b.z;
        r.w = (a.w / (1.f + __expf(-a.w))) * b.w;
        op[j] = cvt4(r);
    }
}

// ---------------------------------------------------------------------------
// Host-side launch helpers
// ---------------------------------------------------------------------------
static void launch_gemm(bool wide, bool outh, const __half* A, const __half* B, void* C,
                        int M, int N, int K, int lda, int ldb, int ldc,
                        long long sA, long long sB, long long sC, int bz,
                        float sc, int causal, int klim,
                        const int* aidx, const int* mdev,
                        const int* cidx, const float* cs, int pstride,
                        const float* resid = nullptr, float* C2 = nullptr,
                        int atomicC = 0)
{
    if (wide) {
        dim3 grid((N + 255) / 256, (M + 127) / 128, bz);
        if (outh)
            gemm_h<true, 256, 2, 256><<<grid, 256, SMEM_BYTES>>>(
                A, B, C, M, N, K, lda, ldb, ldc, sA, sB, sC, sc, causal, klim,
                aidx, mdev, cidx, cs, pstride, resid, C2, atomicC);
        else
            gemm_h<false, 256, 2, 256><<<grid, 256, SMEM_BYTES>>>(
                A, B, C, M, N, K, lda, ldb, ldc, sA, sB, sC, sc, causal, klim,
                aidx, mdev, cidx, cs, pstride, resid, C2, atomicC);
    } else {
        dim3 grid((N + 127) / 128, (M + 127) / 128, bz);
        if (outh)
            gemm_h<true, 128, 3, 128><<<grid, 128, SMEM_BYTES>>>(
                A, B, C, M, N, K, lda, ldb, ldc, sA, sB, sC, sc, causal, klim,
                aidx, mdev, cidx, cs, pstride, resid, C2, atomicC);
        else
            gemm_h<false, 128, 3, 128><<<grid, 128, SMEM_BYTES>>>(
                A, B, C, M, N, K, lda, ldb, ldc, sA, sB, sC, sc, causal, klim,
                aidx, mdev, cidx, cs, pstride, resid, C2, atomicC);
    }
}

static void launch_nt(bool wide, bool outh, const __half* A, const __half* B, void* C,
                      int M, int N, int K, int lda, int ldb, int ldc)
{
    launch_gemm(wide, outh, A, B, C, M, N, K, lda, ldb, ldc, 0, 0, 0, 1, 1.f, 0, 0,
                nullptr, nullptr, nullptr, nullptr, 0);
}

// ---------------------------------------------------------------------------
extern "C" void kernel_launch(void* const* d_in, const int* in_sizes, int n_in,
                              void* d_out, int out_size)
{
    const float* x    = (const float*)d_in[0];
    const float* skip = (const float*)d_in[1];
    const float* rsin = (const float*)d_in[2];
    const float* rcos = (const float*)d_in[3];
    const float* ln1  = (const float*)d_in[4];
    const float* ln2  = (const float*)d_in[5];
    const float* wqa  = (const float*)d_in[6];
    const float* qan  = (const float*)d_in[7];
    const float* wqb  = (const float*)d_in[8];
    const float* wkva = (const float*)d_in[9];
    const float* kvan = (const float*)d_in[10];
    const float* wkb  = (const float*)d_in[11];
    const float* wvb  = (const float*)d_in[12];
    const float* wo   = (const float*)d_in[13];
    const float* gw   = (const float*)d_in[14];
    const float* wup  = (const float*)d_in[15];
    const float* wdn  = (const float*)d_in[16];
    const float* wsup = (const float*)d_in[17];
    const float* wsdn = (const float*)d_in[18];
    float* out = (float*)d_out;

    Scratch* s = nullptr;
    cudaGetSymbolAddress((void**)&s, g_s);
    cudaFuncSetAttribute((const void*)gemm_h<true, 256, 2, 256>,
                         cudaFuncAttributeMaxDynamicSharedMemorySize, SMEM_BYTES);
    cudaFuncSetAttribute((const void*)gemm_h<false, 256, 2, 256>,
                         cudaFuncAttributeMaxDynamicSharedMemorySize, SMEM_BYTES);
    cudaFuncSetAttribute((const void*)gemm_h<true, 128, 3, 128>,
                         cudaFuncAttributeMaxDynamicSharedMemorySize, SMEM_BYTES);
    cudaFuncSetAttribute((const void*)gemm_h<false, 128, 3, 128>,
                         cudaFuncAttributeMaxDynamicSharedMemorySize, SMEM_BYTES);
    cudaFuncSetAttribute((const void*)flash_attn_k,
                         cudaFuncAttributeMaxDynamicSharedMemorySize, SMEM_FLASH);

    const int n = TT * HH;
    float* out2 = out + (long long)n;

    zero_counts_k<<<1, 32>>>();

    // weights -> half; MLP=4 guaranteed (4 consecutive float4 per thread)
    f2h_k<<<592, 256>>>((const float4*)wqa,  (uint2*)s->wqkva_h, (long long)QLAT * HH / 4);
    f2h_k<<<592, 256>>>((const float4*)wkva, (uint2*)(s->wqkva_h + (long long)QLAT * HH),
                        (long long)(KVLAT + ROPED) * HH / 4);
    f2h_k<<<592, 256>>>((const float4*)wqb,  (uint2*)s->wqb_h,  (long long)NHH * DQK * QLAT / 4);
    f2h_k<<<592, 256>>>((const float4*)wkb,  (uint2*)s->wkb_h,  (long long)NHH * NOPE * KVLAT / 4);
    f2h_k<<<592, 256>>>((const float4*)wvb,  (uint2*)s->wvb_h,  (long long)NHH * VDIM * KVLAT / 4);
    f2h_k<<<592, 256>>>((const float4*)wo,   (uint2*)s->wo_h,   (long long)HH * NHH * VDIM / 4);
    f2h_k<<<592, 256>>>((const float4*)wsup, (uint2*)s->wsup_h, (long long)2 * SHI * HH / 4);
    f2h_k<<<592, 256>>>((const float4*)wsdn, (uint2*)s->wsdn_h, (long long)HH * SHI / 4);
    f2h_k<<<1184, 256>>>((const float4*)wup, (uint2*)s->wup_h,  (long long)NE * 2 * MIDIM * HH / 4);
    f2h_k<<<1184, 256>>>((const float4*)wdn, (uint2*)s->wdn_h,  (long long)NE * HH * MIDIM / 4);

    // x1 = x + skip ; n1h = rms(x1)   (fused, vectorized)
    addrms_k<<<TT, 256>>>(x, skip, ln1, s->x1, s->n1h);

    // fused qa+kva projection: qkv_pre[T, 2112] = n1h @ [wqa; wkva]^T
    launch_nt(true, false, s->n1h, s->wqkva_h, s->qkv_pre, TT, QKVN, HH, HH, HH, QKVN);

    // q path
    rmsnorm_h_k<<<TT, 256>>>(s->qkv_pre, qan, s->qah, QLAT, QKVN, QLAT);
    launch_nt(true, true, s->qah, s->wqb_h, s->qh, TT, NHH * DQK, QLAT, QLAT, QLAT, NHH * DQK);
    rope_q_k<<<TT, 256>>>(s->qh, rsin, rcos);

    // kv path
    rmsnorm_h_k<<<TT, 256>>>(s->qkv_pre + QLAT, kvan, s->ckvh, KVLAT, QKVN, KVLAT);
    launch_nt(true, true, s->ckvh, s->wkb_h, s->knopeh, TT, NHH * NOPE, KVLAT, KVLAT, KVLAT, NHH * NOPE);
    build_k_k<<<TT, 256>>>(s->knopeh, s->qkv_pre, rsin, rcos, s->kfullh);
    launch_nt(true, true, s->wvb_h, s->ckvh, s->vTh, NHH * VDIM, TT, KVLAT, KVLAT, KVLAT, TT);

    // fused flash attention (QK + softmax + PV)
    float attn_scale = 1.0f / sqrtf((float)DQK);
    flash_attn_k<<<dim3(NHH, TT / 128), 256, SMEM_FLASH>>>(
        s->qh, s->kfullh, s->vTh, s->oh, attn_scale);

    // attn out + residual fused: out[0:n] = x2 = x1 + oh @ wo^T
    launch_gemm(true, false, s->oh, s->wo_h, out, TT, HH, NHH * VDIM,
                NHH * VDIM, NHH * VDIM, HH, 0, 0, 0, 1,
                1.f, 0, 0, nullptr, nullptr, nullptr, nullptr, 0,
                s->x1, s->x2, 0);

    // n2 and MoE gating
    rmsnorm_h_k<<<TT, 256>>>(s->x2, ln2, s->n2h, HH, HH, HH);
    gate_topk_k<<<TT, 256>>>(s->n2h, gw);

    // shared FFN -> out2 directly
    launch_nt(true, false, s->n2h, s->wsup_h, s->hs, TT, 2 * SHI, HH, HH, HH, 2 * SHI);
    silu_gate_k<<<TT, 256>>>(s->hs, s->hsah, SHI);
    launch_nt(true, false, s->hsah, s->wsdn_h, out2, TT, HH, SHI, SHI, SHI, HH);

    // routed experts: batched over blockIdx.z = expert
    launch_gemm(true, false, s->n2h, s->wup_h, s->h, TT, 2 * MIDIM, HH,
                HH, HH, 2 * MIDIM,
                0, (long long)(2 * MIDIM) * HH, (long long)TT * 2 * MIDIM, NE,
                1.f, 0, 0,
                s->tok, s->counts, nullptr, nullptr, TT);
    silu_gate_moe_k<<<dim3(TT, NE), 256>>>();
    // down: out2[tok[e][r]] += ew * (ha @ dn^T)  via atomicAdd
    launch_gemm(true, false, s->hah, s->wdn_h, out2, TT, HH, MIDIM,
                MIDIM, MIDIM, HH,
                (long long)TT * MIDIM, (long long)HH * MIDIM, 0, NE,
                1.f, 0, 0,
                nullptr, s->counts, s->tok, s->ew, TT,
                nullptr, nullptr, 1);
}

// round 13
// speedup vs baseline: 1.3739x; 1.0230x over previous
#include <cuda_runtime.h>
#include <cuda_fp16.h>
#include <math.h>
#include <stdint.h>

#define TT   2048
#define HH   2048
#define NHH  16
#define NOPE 128
#define ROPED 64
#define DQK  192     // NOPE + ROPE
#define VDIM 128
#define QLAT 1536
#define KVLAT 512
#define NE   8
#define MIDIM 512
#define SHI  1024    // 2*MI
#define QKVN (QLAT + KVLAT + ROPED)   // 2112

// ---------------------------------------------------------------------------
// Scratch (static device memory; no allocations anywhere)
// ---------------------------------------------------------------------------
struct __align__(128) Scratch {
    // f32 buffers
    float x1[TT * HH];
    float qkv_pre[TT * QKVN];            // [qa_pre | kv] fused
    float x2[TT * HH];
    float h[(long long)NE * TT * 2 * MIDIM];
    float hs[TT * 2 * SHI];
    float ew[NE * TT];
    int   tok[NE * TT];
    int   counts[NE];
    // half activation buffers
    __half n1h[TT * HH];
    __half qah[TT * QLAT];
    __half qh[TT * NHH * DQK];
    __half ckvh[TT * KVLAT];
    __half kfullh[TT * NHH * DQK];
    __half vTh[NHH * VDIM * TT];          // [h*128+d, t]
    __half oh[TT * NHH * VDIM];
    __half n2h[TT * HH];
    __half hsah[TT * SHI];
    __half hah[(long long)NE * TT * MIDIM];
    // half weight copies
    __half wqkva_h[QKVN * HH];            // [wqa ; wkva] fused
    __half wqb_h[NHH * DQK * QLAT];
    __half wkb_h[NHH * NOPE * KVLAT];
    __half wvb_h[NHH * VDIM * KVLAT];
    __half wo_h[HH * NHH * VDIM];
    __half wsup_h[2 * SHI * HH];
    __half wsdn_h[HH * SHI];
    __half wup_h[(long long)NE * 2 * MIDIM * HH];
    __half wdn_h[(long long)NE * HH * MIDIM];
};
__device__ Scratch g_s;

// ---------------------------------------------------------------------------
// helpers
// ---------------------------------------------------------------------------
__device__ __forceinline__ uint32_t smem_u32(const void* p) {
    uint32_t a;
    asm("{ .reg .u64 t; cvta.to.shared.u64 t, %1; cvt.u32.u64 %0, t; }" : "=r"(a) : "l"(p));
    return a;
}

__device__ __forceinline__ void cp16(uint32_t dst, const void* src, int sz) {
    asm volatile("cp.async.cg.shared.global [%0], [%1], 16, %2;"
                 :: "r"(dst), "l"(src), "r"(sz));
}
__device__ __forceinline__ void cp_commit() {
    asm volatile("cp.async.commit_group;" ::: "memory");
}

__device__ __forceinline__ void ldm_x4(unsigned& r0, unsigned& r1, unsigned& r2,
                                       unsigned& r3, uint32_t addr) {
    asm volatile("ldmatrix.sync.aligned.m8n8.x4.shared.b16 {%0,%1,%2,%3}, [%4];"
                 : "=r"(r0), "=r"(r1), "=r"(r2), "=r"(r3) : "r"(addr));
}

__device__ __forceinline__ void mma_f16(float* d, const unsigned* a, const unsigned* b) {
    asm volatile(
        "mma.sync.aligned.m16n8k16.row.col.f32.f16.f16.f32 "
        "{%0,%1,%2,%3}, {%4,%5,%6,%7}, {%8,%9}, {%0,%1,%2,%3};\n"
        : "+f"(d[0]), "+f"(d[1]), "+f"(d[2]), "+f"(d[3])
        : "r"(a[0]), "r"(a[1]), "r"(a[2]), "r"(a[3]), "r"(b[0]), "r"(b[1]));
}

__device__ __forceinline__ unsigned packh2(float x, float y) {
    __half2 h = __floats2half2_rn(x, y);
    return *reinterpret_cast<unsigned*>(&h);
}

__device__ __forceinline__ uint2 cvt4(float4 v) {
    __half2 h0 = __floats2half2_rn(v.x, v.y);
    __half2 h1 = __floats2half2_rn(v.z, v.w);
    uint2 o;
    o.x = *reinterpret_cast<unsigned*>(&h0);
    o.y = *reinterpret_cast<unsigned*>(&h1);
    return o;
}

// ---------------------------------------------------------------------------
// fp16 NT GEMM (R5 config, frozen) + epilogue fusions:
//   resid/C2/atomicC (f32 out), ropeq (rope on d>=NOPE pairs), cmap192
//   (column remap gn -> (gn>>7)*192 + (gn&127), for kb -> kfull direct write)
// ---------------------------------------------------------------------------
#define SMEM_BYTES 98304

template <bool OUTH, int NTILE, int NSTAGE, int NTHREADS>
__global__ __launch_bounds__(NTHREADS)
void gemm_h(const __half* __restrict__ A, const __half* __restrict__ B,
            void* __restrict__ Cv,
            int M, int N, int K, int lda, int ldb, int ldc,
            long long sA, long long sB, long long sC,
            float scale, int causal, int klim,
            const int* __restrict__ aidx, const int* __restrict__ mdev,
            const int* __restrict__ cidx, const float* __restrict__ cscale,
            int pstride,
            const float* __restrict__ resid, float* __restrict__ C2, int atomicC,
            const float* __restrict__ rs, const float* __restrict__ rc,
            int ropeq, int cmap192)
{
    constexpr int STG_BYTES = (128 + NTILE) * 128;
    constexpr int LOADS = (128 + NTILE) * 8 / NTHREADS;
    extern __shared__ __align__(128) char smem[];
    const int z = blockIdx.z;
    A += (long long)z * sA;
    B += (long long)z * sB;
    if (pstride) {
        if (mdev)   mdev   += z;
        if (aidx)   aidx   += (long long)z * pstride;
        if (cidx)   cidx   += (long long)z * pstride;
        if (cscale) cscale += (long long)z * pstride;
    }
    const int Meff = mdev ? *mdev : M;
    const int m0 = blockIdx.y * 128;
    const int n0 = blockIdx.x * NTILE;
    if (m0 >= Meff) return;
    if (causal && n0 > m0 + 127) return;
    const int kmax = klim ? min(K, m0 + 128) : K;
    const int ktiles = kmax >> 6;

    const uint32_t sbase = smem_u32(smem);
    const int tid = threadIdx.x;
    const int lane = tid & 31;
    const int wid = tid >> 5;
    const int wm = (wid & 1) * 64;
    const int wn = (wid >> 1) * 64;
    const int lr = lane >> 2;
    const int lm = lane & 3;

    float acc[4][8][4];
#pragma unroll
    for (int i = 0; i < 4; i++)
#pragma unroll
        for (int j = 0; j < 8; j++)
#pragma unroll
            for (int c = 0; c < 4; c++) acc[i][j][c] = 0.f;

    auto issue_stage = [&](int i) {
        const uint32_t base = sbase + (i % NSTAGE) * STG_BYTES;
        const int kt = i << 6;
#pragma unroll
        for (int it = 0; it < LOADS; it++) {
            int c = tid + it * NTHREADS;
            int row = c >> 3, ch = c & 7;
            uint32_t dst = base + row * 128 + ((ch ^ (row & 7)) << 4);
            const __half* src;
            int sz = 0;
            if (row < 128) {
                int gm = m0 + row;
                src = A;
                if (gm < Meff) {
                    int ar = aidx ? aidx[gm] : gm;
                    src = A + (long long)ar * lda + kt + ch * 8;
                    sz = 16;
                }
            } else {
                int gn = n0 + row - 128;
                src = B;
                if (gn < N) {
                    src = B + (long long)gn * ldb + kt + ch * 8;
                    sz = 16;
                }
            }
            cp16(dst, src, sz);
        }
    };

#pragma unroll
    for (int s = 0; s < NSTAGE - 1; s++) {
        if (s < ktiles) issue_stage(s);
        cp_commit();
    }

    const int a_row = lane & 15;
    const int a_h = lane >> 4;
    const int b_t = lane >> 3;
    const int b_r = lane & 7;

    for (int i = 0; i < ktiles; i++) {
        if (i + NSTAGE - 1 < ktiles) issue_stage(i + NSTAGE - 1);
        cp_commit();
        if (NSTAGE == 2)
            asm volatile("cp.async.wait_group 1;" ::: "memory");
        else
            asm volatile("cp.async.wait_group 2;" ::: "memory");
        __syncthreads();

        const uint32_t base = sbase + (i % NSTAGE) * STG_BYTES;
#pragma unroll
        for (int kk = 0; kk < 4; kk++) {
            unsigned afr[4][4], bfr[8][2];
#pragma unroll
            for (int im = 0; im < 4; im++) {
                int row = wm + im * 16 + a_row;
                int ch = kk * 2 + a_h;
                ldm_x4(afr[im][0], afr[im][1], afr[im][2], afr[im][3],
                       base + row * 128 + ((ch ^ (row & 7)) << 4));
            }
#pragma unroll
            for (int j2 = 0; j2 < 4; j2++) {
                int jn = j2 * 2 + (b_t >> 1);
                int row = 128 + wn + jn * 8 + b_r;
                int ch = kk * 2 + (b_t & 1);
                unsigned r0, r1, r2, r3;
                ldm_x4(r0, r1, r2, r3, base + row * 128 + ((ch ^ (row & 7)) << 4));
                bfr[j2 * 2][0] = r0;     bfr[j2 * 2][1] = r1;
                bfr[j2 * 2 + 1][0] = r2; bfr[j2 * 2 + 1][1] = r3;
            }
#pragma unroll
            for (int im = 0; im < 4; im++)
#pragma unroll
                for (int jn = 0; jn < 8; jn++)
                    mma_f16(acc[im][jn], afr[im], bfr[jn]);
        }
        __syncthreads();
    }

#pragma unroll
    for (int im = 0; im < 4; im++) {
#pragma unroll
        for (int part = 0; part < 2; part++) {
            int gm = m0 + wm + im * 16 + lr + part * 8;
            if (gm >= Meff) continue;
            long long crow = gm;
            float w = scale;
            if (cidx) { crow = cidx[gm]; w = scale * cscale[gm]; }
#pragma unroll
            for (int jn = 0; jn < 8; jn++) {
                int gn = n0 + wn + jn * 8 + lm * 2;
                if (gn >= N) continue;
                float vx = acc[im][jn][part * 2] * w;
                float vy = acc[im][jn][part * 2 + 1] * w;
                if (OUTH) {
                    int gn2 = gn;
                    if (ropeq) {
                        int d = gn % DQK;
                        if (d >= NOPE) {
                            int p = (d - NOPE) >> 1;
                            float sn = rs[crow * 32 + p], cs = rc[crow * 32 + p];
                            float tx = vx * cs - vy * sn;
                            vy = vx * sn + vy * cs;
                            vx = tx;
                        }
                    }
                    if (cmap192) gn2 = (gn >> 7) * 192 + (gn & 127);
                    __half* cp = (__half*)Cv + ((long long)z * sC) + crow * (long long)ldc + gn2;
                    *reinterpret_cast<__half2*>(cp) = __floats2half2_rn(vx, vy);
                } else {
                    long long off = crow * (long long)ldc + gn;
                    if (resid) {
                        vx += resid[off];
                        vy += resid[off + 1];
                    }
                    float* cp = (float*)Cv + ((long long)z * sC) + off;
                    if (atomicC) {
                        atomicAdd(cp, vx);
                        atomicAdd(cp + 1, vy);
                    } else {
                        *reinterpret_cast<float2*>(cp) = make_float2(vx, vy);
                        if (C2)
                            *reinterpret_cast<float2*>(C2 + off) = make_float2(vx, vy);
                    }
                }
            }
        }
    }
}

// ---------------------------------------------------------------------------
// Flash attention: 256 threads, 8 warps x 16 q-rows; k-blocks of 64.
// ---------------------------------------------------------------------------
#define SMEM_FLASH 131072

__global__ __launch_bounds__(256, 1)
void flash_attn_k(const __half* __restrict__ Q, const __half* __restrict__ K,
                  const __half* __restrict__ Vt, __half* __restrict__ O,
                  float scale)
{
    extern __shared__ __align__(128) char smem[];
    const int h = blockIdx.x;
    const int qb = (int)gridDim.y - 1 - (int)blockIdx.y;   // heaviest first
    const int nkb = 2 * qb + 2;
    const uint32_t sb = smem_u32(smem);
    const uint32_t Qs = sb;
    const uint32_t Ks = sb + 49152;
    const uint32_t Vs = sb + 49152 + 49152;
    const int tid = threadIdx.x, lane = tid & 31, wid = tid >> 5;
    const int wq = wid * 16;
    const int lr = lane >> 2, lm = lane & 3;

    for (int c = tid; c < 3072; c += 256) {
        int row = c / 24, kc = c % 24;
        int sub = kc >> 3, ch = kc & 7;
        cp16(Qs + row * 384 + sub * 128 + ((ch ^ (row & 7)) << 4),
             Q + ((long long)(qb * 128 + row) * (NHH * DQK) + h * DQK + kc * 8), 16);
    }
    auto load_kv = [&](int kb) {
        int buf = kb & 1;
        for (int c = tid; c < 1536; c += 256) {
            int row = c / 24, kc = c % 24;
            int sub = kc >> 3, ch = kc & 7;
            cp16(Ks + buf * 24576 + row * 384 + sub * 128 + ((ch ^ (row & 7)) << 4),
                 K + ((long long)(kb * 64 + row) * (NHH * DQK) + h * DQK + kc * 8), 16);
        }
        for (int c = tid; c < 1024; c += 256) {
            int row = c >> 3, ch = c & 7;
            cp16(Vs + buf * 16384 + row * 128 + ((ch ^ (row & 7)) << 4),
                 Vt + ((long long)(h * 128 + row) * TT + kb * 64 + ch * 8), 16);
        }
    };

    load_kv(0);
    cp_commit();

    float m_s[2] = {-1e30f, -1e30f}, l_s[2] = {0.f, 0.f};
    float acc[16][4];
#pragma unroll
    for (int dn = 0; dn < 16; dn++)
#pragma unroll
        for (int c = 0; c < 4; c++) acc[dn][c] = 0.f;

    const int a_row = lane & 15, a_h = lane >> 4;
    const int b_t = lane >> 3, b_r = lane & 7;

    for (int kb = 0; kb < nkb; kb++) {
        if (kb + 1 < nkb) load_kv(kb + 1);
        cp_commit();
        asm volatile("cp.async.wait_group 1;" ::: "memory");
        __syncthreads();
        const uint32_t kbase = Ks + (kb & 1) * 24576;
        const uint32_t vbase = Vs + (kb & 1) * 16384;

        float s[8][4];
#pragma unroll
        for (int jn = 0; jn < 8; jn++)
#pragma unroll
            for (int c = 0; c < 4; c++) s[jn][c] = 0.f;

#pragma unroll
        for (int ks = 0; ks < 12; ks++) {
            unsigned afr[4], bfr[8][2];
            {
                int row = wq + a_row;
                int kc = ks * 2 + a_h;
                ldm_x4(afr[0], afr[1], afr[2], afr[3],
                       Qs + row * 384 + (kc >> 3) * 128 + (((kc & 7) ^ (row & 7)) << 4));
            }
#pragma unroll
            for (int j2 = 0; j2 < 4; j2++) {
                int jn = j2 * 2 + (b_t >> 1);
                int row = jn * 8 + b_r;
                int kc = ks * 2 + (b_t & 1);
                unsigned r0, r1, r2, r3;
                ldm_x4(r0, r1, r2, r3,
                       kbase + row * 384 + (kc >> 3) * 128 + (((kc & 7) ^ (row & 7)) << 4));
                bfr[j2 * 2][0] = r0;     bfr[j2 * 2][1] = r1;
                bfr[j2 * 2 + 1][0] = r2; bfr[j2 * 2 + 1][1] = r3;
            }
#pragma unroll
            for (int jn = 0; jn < 8; jn++)
                mma_f16(s[jn], afr, bfr[jn]);
        }

        const int coff = kb * 64 - qb * 128;
        float alpha[2];
#pragma unroll
        for (int part = 0; part < 2; part++) {
            int r = wq + lr + part * 8;
            float mx = -1e30f;
#pragma unroll
            for (int jn = 0; jn < 8; jn++) {
#pragma unroll
                for (int q = 0; q < 2; q++) {
                    int c = jn * 8 + lm * 2 + q;
                    float v = s[jn][part * 2 + q] * scale;
                    if (c + coff > r) v = -1e30f;
                    s[jn][part * 2 + q] = v;
                    mx = fmaxf(mx, v);
                }
            }
            mx = fmaxf(mx, __shfl_xor_sync(0xffffffffu, mx, 1));
            mx = fmaxf(mx, __shfl_xor_sync(0xffffffffu, mx, 2));
            float mo = m_s[part];
            float mn = fmaxf(mo, mx);
            float al = __expf(mo - mn);
            float sum = 0.f;
#pragma unroll
            for (int jn = 0; jn < 8; jn++) {
#pragma unroll
                for (int q = 0; q < 2; q++) {
                    float p = __expf(s[jn][part * 2 + q] - mn);
                    s[jn][part * 2 + q] = p;
                    sum += p;
                }
            }
            sum += __shfl_xor_sync(0xffffffffu, sum, 1);
            sum += __shfl_xor_sync(0xffffffffu, sum, 2);
            l_s[part] = l_s[part] * al + sum;
            m_s[part] = mn;
            alpha[part] = al;
        }
#pragma unroll
        for (int dn = 0; dn < 16; dn++) {
            acc[dn][0] *= alpha[0];
            acc[dn][1] *= alpha[0];
            acc[dn][2] *= alpha[1];
            acc[dn][3] *= alpha[1];
        }

#pragma unroll
        for (int kv = 0; kv < 4; kv++) {
            unsigned ap[4];
            ap[0] = packh2(s[2 * kv][0], s[2 * kv][1]);
            ap[1] = packh2(s[2 * kv][2], s[2 * kv][3]);
            ap[2] = packh2(s[2 * kv + 1][0], s[2 * kv + 1][1]);
            ap[3] = packh2(s[2 * kv + 1][2], s[2 * kv + 1][3]);
#pragma unroll
            for (int j2 = 0; j2 < 8; j2++) {
                int dn = j2 * 2 + (b_t >> 1);
                int row = dn * 8 + b_r;
                int ch = kv * 2 + (b_t & 1);
                unsigned r0, r1, r2, r3;
                ldm_x4(r0, r1, r2, r3, vbase + row * 128 + ((ch ^ (row & 7)) << 4));
                unsigned bv0[2] = {r0, r1}, bv1[2] = {r2, r3};
                mma_f16(acc[j2 * 2], ap, bv0);
                mma_f16(acc[j2 * 2 + 1], ap, bv1);
            }
        }
        __syncthreads();
    }

#pragma unroll
    for (int part = 0; part < 2; part++) {
        float inv = 1.0f / l_s[part];
        int grow = qb * 128 + wq + lr + part * 8;
        __half* op = O + (long long)grow * (NHH * VDIM) + h * VDIM;
#pragma unroll
        for (int dn = 0; dn < 16; dn++) {
            int col = dn * 8 + lm * 2;
            *reinterpret_cast<__half2*>(op + col) =
                __floats2half2_rn(acc[dn][part * 2] * inv,
                                  acc[dn][part * 2 + 1] * inv);
        }
    }
}

// ---------------------------------------------------------------------------
// Elementwise / reduction kernels
// ---------------------------------------------------------------------------
__global__ void zero_counts_k() {
    if (threadIdx.x < NE) g_s.counts[threadIdx.x] = 0;
}

// f32 -> f16: exact-cover grid, 4 strided loads per thread.
// launch with grid = n4/1024, block = 256; requires n4 % 1024 == 0.
__global__ void f2h_k(const float4* __restrict__ in, uint2* __restrict__ out,
                      long long q /* = n4/4 */) {
    long long i = blockIdx.x * (long long)blockDim.x + threadIdx.x;
    float4 a = in[i];
    float4 b = in[i + q];
    float4 c = in[i + 2 * q];
    float4 d = in[i + 3 * q];
    out[i]         = cvt4(a);
    out[i + q]     = cvt4(b);
    out[i + 2 * q] = cvt4(c);
    out[i + 3 * q] = cvt4(d);
}

// fused: x1 = x + skip (stored), n1h = rms(x1)*w
__global__ __launch_bounds__(256)
void addrms_k(const float* __restrict__ x, const float* __restrict__ skip,
              const float* __restrict__ w, float* __restrict__ x1,
              __half* __restrict__ out) {
    int row = blockIdx.x;
    const float4* xp = (const float4*)(x + (long long)row * HH);
    const float4* sp = (const float4*)(skip + (long long)row * HH);
    float4* x1p = (float4*)(x1 + (long long)row * HH);
    float4 vals[2];
    float ss = 0.f;
#pragma unroll
    for (int i = 0; i < 2; i++) {
        int j = threadIdx.x + i * 256;
        float4 a = xp[j], b = sp[j];
        float4 v = make_float4(a.x + b.x, a.y + b.y, a.z + b.z, a.w + b.w);
        vals[i] = v;
        x1p[j] = v;
        ss += v.x * v.x + v.y * v.y + v.z * v.z + v.w * v.w;
    }
    __shared__ float red[256];
    red[threadIdx.x] = ss;
    __syncthreads();
    for (int st = 128; st > 0; st >>= 1) {
        if (threadIdx.x < st) red[threadIdx.x] += red[threadIdx.x + st];
        __syncthreads();
    }
    float scale = rsqrtf(red[0] / (float)HH + 1e-6f);
    uint2* op = (uint2*)(out + (long long)row * HH);
    const float4* wp = (const float4*)w;
#pragma unroll
    for (int i = 0; i < 2; i++) {
        int j = threadIdx.x + i * 256;
        float4 v = vals[i], ww = wp[j];
        op[j] = cvt4(make_float4(v.x * scale * ww.x, v.y * scale * ww.y,
                                 v.z * scale * ww.z, v.w * scale * ww.w));
    }
}

__global__ __launch_bounds__(256)
void rmsnorm_h_k(const float* __restrict__ in, const float* __restrict__ w,
                 __half* __restrict__ out, int cols, int instride, int outstride) {
    int row = blockIdx.x;
    const float4* ip = (const float4*)(in + (long long)row * instride);
    int c4 = cols >> 2;
    float ss = 0.f;
    for (int j = threadIdx.x; j < c4; j += 256) {
        float4 v = ip[j];
        ss += v.x * v.x + v.y * v.y + v.z * v.z + v.w * v.w;
    }
    __shared__ float red[256];
    red[threadIdx.x] = ss;
    __syncthreads();
    for (int st = 128; st > 0; st >>= 1) {
        if (threadIdx.x < st) red[threadIdx.x] += red[threadIdx.x + st];
        __syncthreads();
    }
    float scale = rsqrtf(red[0] / (float)cols + 1e-6f);
    uint2* op = (uint2*)(out + (long long)row * outstride);
    const float4* wp = (const float4*)w;
    for (int j = threadIdx.x; j < c4; j += 256) {
        float4 v = ip[j], ww = wp[j];
        op[j] = cvt4(make_float4(v.x * scale * ww.x, v.y * scale * ww.y,
                                 v.z * scale * ww.z, v.w * scale * ww.w));
    }
}

// fill rope PE columns of kfull: kfull[t, h*192 + 128 + j] = rope(kv)[j]
__global__ void build_pe_k(const float* __restrict__ qkv,
                           const float* __restrict__ rsin,
                           const float* __restrict__ rcos,
                           __half* __restrict__ kfull) {
    int t = blockIdx.x;
    __shared__ __half pe[ROPED];
    if (threadIdx.x < 32) {
        int p = threadIdx.x;
        float a = qkv[(long long)t * QKVN + QLAT + KVLAT + 2 * p];
        float b = qkv[(long long)t * QKVN + QLAT + KVLAT + 2 * p + 1];
        float s = rsin[t * 32 + p], c = rcos[t * 32 + p];
        pe[2 * p]     = __float2half_rn(a * c - b * s);
        pe[2 * p + 1] = __float2half_rn(a * s + b * c);
    }
    __syncthreads();
    for (int i = threadIdx.x; i < NHH * ROPED; i += blockDim.x) {
        int h = i >> 6;
        int d = i & 63;
        kfull[(long long)t * (NHH * DQK) + h * DQK + NOPE + d] = pe[d];
    }
}

__global__ __launch_bounds__(256)
void gate_topk_k(const __half* __restrict__ n2, const float* __restrict__ gw) {
    int t = blockIdx.x;
    __shared__ float logits[NE];
    int warp = threadIdx.x >> 5, lane = threadIdx.x & 31;
    const __half* xp = n2 + (long long)t * HH;
    const float* wp = gw + warp * HH;
    float s = 0.f;
    for (int k = lane; k < HH; k += 32) s += __half2float(xp[k]) * wp[k];
    for (int off = 16; off > 0; off >>= 1) s += __shfl_down_sync(0xffffffffu, s, off);
    if (lane == 0) logits[warp] = s;
    __syncthreads();
    if (threadIdx.x == 0) {
        float m = logits[0];
        for (int e = 1; e < NE; e++) m = fmaxf(m, logits[e]);
        float p[NE];
        float sum = 0.f;
        for (int e = 0; e < NE; e++) { p[e] = __expf(logits[e] - m); sum += p[e]; }
        for (int e = 0; e < NE; e++) p[e] /= sum;
        int i0 = 0;
        for (int e = 1; e < NE; e++) if (p[e] > p[i0]) i0 = e;
        int i1 = -1;
        for (int e = 0; e < NE; e++) {
            if (e == i0) continue;
            if (i1 < 0 || p[e] > p[i1]) i1 = e;
        }
        float w0 = p[i0], w1 = p[i1];
        float tot = w0 + w1;
        w0 /= tot; w1 /= tot;
        int pos0 = atomicAdd(&g_s.counts[i0], 1);
        g_s.tok[i0 * TT + pos0] = t;
        g_s.ew[i0 * TT + pos0] = w0;
        int pos1 = atomicAdd(&g_s.counts[i1], 1);
        g_s.tok[i1 * TT + pos1] = t;
        g_s.ew[i1 * TT + pos1] = w1;
    }
}

__global__ void silu_gate_k(const float* __restrict__ in, __half* __restrict__ out,
                            int half_) {
    int row = blockIdx.x;
    const float4* ip = (const float4*)(in + (long long)row * 2 * half_);
    const float4* gp = (const float4*)(in + (long long)row * 2 * half_ + half_);
    uint2* op = (uint2*)(out + (long long)row * half_);
    int h4 = half_ >> 2;
    for (int j = threadIdx.x; j < h4; j += blockDim.x) {
        float4 a = ip[j], b = gp[j];
        float4 r;
        r.x = (a.x / (1.f + __expf(-a.x))) * b.x;
        r.y = (a.y / (1.f + __expf(-a.y))) * b.y;
        r.z = (a.z / (1.f + __expf(-a.z))) * b.z;
        r.w = (a.w / (1.f + __expf(-a.w))) * b.w;
        op[j] = cvt4(r);
    }
}

__global__ void silu_gate_moe_k() {
    int e = blockIdx.y;
    int row = blockIdx.x;
    if (row >= g_s.counts[e]) return;
    const float* base = g_s.h + ((long long)e * TT + row) * (2 * MIDIM);
    const float4* ip = (const float4*)base;
    const float4* gp = (const float4*)(base + MIDIM);
    uint2* op = (uint2*)(g_s.hah + ((long long)e * TT + row) * MIDIM);
    for (int j = threadIdx.x; j < (MIDIM >> 2); j += blockDim.x) {
        float4 a = ip[j], b = gp[j];
        float4 r;
        r.x = (a.x / (1.f + __expf(-a.x))) * b.x;
        r.y = (a.y / (1.f + __expf(-a.y))) * b.y;
        r.z = (a.z / (1.f + __expf(-a.z))) * b.z;
        r.w = (a.w / (1.f + __expf(-a.w))) * b.w;
        op[j] = cvt4(r);
    }
}

// ---------------------------------------------------------------------------
// Host-side launch helpers
// ---------------------------------------------------------------------------
static void launch_gemm(bool wide, bool outh, const __half* A, const __half* B, void* C,
                        int M, int N, int K, int lda, int ldb, int ldc,
                        long long sA, long long sB, long long sC, int bz,
                        float sc, int causal, int klim,
                        const int* aidx, const int* mdev,
                        const int* cidx, const float* cs, int pstride,
                        const float* resid = nullptr, float* C2 = nullptr,
                        int atomicC = 0,
                        const float* rs = nullptr, const float* rc = nullptr,
                        int ropeq = 0, int cmap192 = 0)
{
    if (wide) {
        dim3 grid((N + 255) / 256, (M + 127) / 128, bz);
        if (outh)
            gemm_h<true, 256, 2, 256><<<grid, 256, SMEM_BYTES>>>(
                A, B, C, M, N, K, lda, ldb, ldc, sA, sB, sC, sc, causal, klim,
                aidx, mdev, cidx, cs, pstride, resid, C2, atomicC, rs, rc, ropeq, cmap192);
        else
            gemm_h<false, 256, 2, 256><<<grid, 256, SMEM_BYTES>>>(
                A, B, C, M, N, K, lda, ldb, ldc, sA, sB, sC, sc, causal, klim,
                aidx, mdev, cidx, cs, pstride, resid, C2, atomicC, rs, rc, ropeq, cmap192);
    } else {
        dim3 grid((N + 127) / 128, (M + 127) / 128, bz);
        if (outh)
            gemm_h<true, 128, 3, 128><<<grid, 128, SMEM_BYTES>>>(
                A, B, C, M, N, K, lda, ldb, ldc, sA, sB, sC, sc, causal, klim,
                aidx, mdev, cidx, cs, pstride, resid, C2, atomicC, rs, rc, ropeq, cmap192);
        else
            gemm_h<false, 128, 3, 128><<<grid, 128, SMEM_BYTES>>>(
                A, B, C, M, N, K, lda, ldb, ldc, sA, sB, sC, sc, causal, klim,
                aidx, mdev, cidx, cs, pstride, resid, C2, atomicC, rs, rc, ropeq, cmap192);
    }
}

static void launch_nt(bool wide, bool outh, const __half* A, const __half* B, void* C,
                      int M, int N, int K, int lda, int ldb, int ldc)
{
    launch_gemm(wide, outh, A, B, C, M, N, K, lda, ldb, ldc, 0, 0, 0, 1, 1.f, 0, 0,
                nullptr, nullptr, nullptr, nullptr, 0);
}

static void f2h(const float* in, __half* out, long long nelem) {
    long long n4 = nelem / 4;
    f2h_k<<<(unsigned)(n4 / 1024), 256>>>((const float4*)in, (uint2*)out, n4 / 4);
}

// ---------------------------------------------------------------------------
extern "C" void kernel_launch(void* const* d_in, const int* in_sizes, int n_in,
                              void* d_out, int out_size)
{
    const float* x    = (const float*)d_in[0];
    const float* skip = (const float*)d_in[1];
    const float* rsin = (const float*)d_in[2];
    const float* rcos = (const float*)d_in[3];
    const float* ln1  = (const float*)d_in[4];
    const float* ln2  = (const float*)d_in[5];
    const float* wqa  = (const float*)d_in[6];
    const float* qan  = (const float*)d_in[7];
    const float* wqb  = (const float*)d_in[8];
    const float* wkva = (const float*)d_in[9];
    const float* kvan = (const float*)d_in[10];
    const float* wkb  = (const float*)d_in[11];
    const float* wvb  = (const float*)d_in[12];
    const float* wo   = (const float*)d_in[13];
    const float* gw   = (const float*)d_in[14];
    const float* wup  = (const float*)d_in[15];
    const float* wdn  = (const float*)d_in[16];
    const float* wsup = (const float*)d_in[17];
    const float* wsdn = (const float*)d_in[18];
    float* out = (float*)d_out;

    Scratch* s = nullptr;
    cudaGetSymbolAddress((void**)&s, g_s);
    cudaFuncSetAttribute((const void*)gemm_h<true, 256, 2, 256>,
                         cudaFuncAttributeMaxDynamicSharedMemorySize, SMEM_BYTES);
    cudaFuncSetAttribute((const void*)gemm_h<false, 256, 2, 256>,
                         cudaFuncAttributeMaxDynamicSharedMemorySize, SMEM_BYTES);
    cudaFuncSetAttribute((const void*)gemm_h<true, 128, 3, 128>,
                         cudaFuncAttributeMaxDynamicSharedMemorySize, SMEM_BYTES);
    cudaFuncSetAttribute((const void*)gemm_h<false, 128, 3, 128>,
                         cudaFuncAttributeMaxDynamicSharedMemorySize, SMEM_BYTES);
    cudaFuncSetAttribute((const void*)flash_attn_k,
                         cudaFuncAttributeMaxDynamicSharedMemorySize, SMEM_FLASH);

    const int n = TT * HH;
    float* out2 = out + (long long)n;

    zero_counts_k<<<1, 32>>>();

    // weights -> half (exact-cover MLP=4); wqa+wkva fused into one buffer
    f2h(wqa,  (__half*)s->wqkva_h, (long long)QLAT * HH);
    f2h(wkva, (__half*)(s->wqkva_h + (long long)QLAT * HH), (long long)(KVLAT + ROPED) * HH);
    f2h(wqb,  s->wqb_h,  (long long)NHH * DQK * QLAT);
    f2h(wkb,  s->wkb_h,  (long long)NHH * NOPE * KVLAT);
    f2h(wvb,  s->wvb_h,  (long long)NHH * VDIM * KVLAT);
    f2h(wo,   s->wo_h,   (long long)HH * NHH * VDIM);
    f2h(wsup, s->wsup_h, (long long)2 * SHI * HH);
    f2h(wsdn, s->wsdn_h, (long long)HH * SHI);
    f2h(wup,  s->wup_h,  (long long)NE * 2 * MIDIM * HH);
    f2h(wdn,  s->wdn_h,  (long long)NE * HH * MIDIM);

    // x1 = x + skip ; n1h = rms(x1)
    addrms_k<<<TT, 256>>>(x, skip, ln1, s->x1, s->n1h);

    // fused qa+kva projection
    launch_nt(true, false, s->n1h, s->wqkva_h, s->qkv_pre, TT, QKVN, HH, HH, HH, QKVN);

    // q path: qb GEMM with fused rope epilogue
    rmsnorm_h_k<<<TT, 256>>>(s->qkv_pre, qan, s->qah, QLAT, QKVN, QLAT);
    launch_gemm(true, true, s->qah, s->wqb_h, s->qh, TT, NHH * DQK, QLAT,
                QLAT, QLAT, NHH * DQK, 0, 0, 0, 1,
                1.f, 0, 0, nullptr, nullptr, nullptr, nullptr, 0,
                nullptr, nullptr, 0, rsin, rcos, /*ropeq=*/1, 0);

    // kv path: kb GEMM writes kfull directly (column remap), then PE fill
    rmsnorm_h_k<<<TT, 256>>>(s->qkv_pre + QLAT, kvan, s->ckvh, KVLAT, QKVN, KVLAT);
    launch_gemm(true, true, s->ckvh, s->wkb_h, s->kfullh, TT, NHH * NOPE, KVLAT,
                KVLAT, KVLAT, NHH * DQK, 0, 0, 0, 1,
                1.f, 0, 0, nullptr, nullptr, nullptr, nullptr, 0,
                nullptr, nullptr, 0, nullptr, nullptr, 0, /*cmap192=*/1);
    build_pe_k<<<TT, 256>>>(s->qkv_pre, rsin, rcos, s->kfullh);
    launch_nt(true, true, s->wvb_h, s->ckvh, s->vTh, NHH * VDIM, TT, KVLAT, KVLAT, KVLAT, TT);

    // fused flash attention
    float attn_scale = 1.0f / sqrtf((float)DQK);
    flash_attn_k<<<dim3(NHH, TT / 128), 256, SMEM_FLASH>>>(
        s->qh, s->kfullh, s->vTh, s->oh, attn_scale);

    // attn out + residual fused: out[0:n] = x2 = x1 + oh @ wo^T
    launch_gemm(true, false, s->oh, s->wo_h, out, TT, HH, NHH * VDIM,
                NHH * VDIM, NHH * VDIM, HH, 0, 0, 0, 1,
                1.f, 0, 0, nullptr, nullptr, nullptr, nullptr, 0,
                s->x1, s->x2, 0);

    // n2 and MoE gating
    rmsnorm_h_k<<<TT, 256>>>(s->x2, ln2, s->n2h, HH, HH, HH);
    gate_topk_k<<<TT, 256>>>(s->n2h, gw);

    // shared FFN -> out2 directly
    launch_nt(true, false, s->n2h, s->wsup_h, s->hs, TT, 2 * SHI, HH, HH, HH, 2 * SHI);
    silu_gate_k<<<TT, 256>>>(s->hs, s->hsah, SHI);
    launch_nt(true, false, s->hsah, s->wsdn_h, out2, TT, HH, SHI, SHI, SHI, HH);

    // routed experts
    launch_gemm(true, false, s->n2h, s->wup_h, s->h, TT, 2 * MIDIM, HH,
                HH, HH, 2 * MIDIM,
                0, (long long)(2 * MIDIM) * HH, (long long)TT * 2 * MIDIM, NE,
                1.f, 0, 0,
                s->tok, s->counts, nullptr, nullptr, TT);
    silu_gate_moe_k<<<dim3(TT, NE), 256>>>();
    launch_gemm(true, false, s->hah, s->wdn_h, out2, TT, HH, MIDIM,
                MIDIM, MIDIM, HH,
                (long long)TT * MIDIM, (long long)HH * MIDIM, 0, NE,
                1.f, 0, 0,
                nullptr, s->counts, s->tok, s->ew, TT,
                nullptr, nullptr, 1);
}

// round 15
// speedup vs baseline: 1.4122x; 1.0279x over previous
#include <cuda_runtime.h>
#include <cuda_fp16.h>
#include <math.h>
#include <stdint.h>

#define TT   2048
#define HH   2048
#define NHH  16
#define NOPE 128
#define ROPED 64
#define DQK  192     // NOPE + ROPE
#define VDIM 128
#define QLAT 1536
#define KVLAT 512
#define NE   8
#define MIDIM 512
#define SHI  1024    // 2*MI
#define QKVN (QLAT + KVLAT + ROPED)   // 2112

// ---------------------------------------------------------------------------
// Scratch (static device memory; no allocations anywhere)
// ---------------------------------------------------------------------------
struct __align__(128) Scratch {
    // f32 buffers
    float x1[TT * HH];
    float qkv_pre[TT * QKVN];            // [qa_pre | kv] fused
    float x2[TT * HH];
    float h[(long long)NE * TT * 2 * MIDIM];
    float hs[TT * 2 * SHI];
    float ew[NE * TT];
    int   tok[NE * TT];
    int   counts[NE];
    // half activation buffers
    __half n1h[TT * HH];
    __half qah[TT * QLAT];
    __half qh[TT * NHH * DQK];
    __half ckvh[TT * KVLAT];
    __half kfullh[TT * NHH * DQK];
    __half vTh[NHH * VDIM * TT];          // [h*128+d, t]
    __half oh[TT * NHH * VDIM];
    __half n2h[TT * HH];
    __half hsah[TT * SHI];
    __half hah[(long long)NE * TT * MIDIM];
    // half weight copies
    __half wqkva_h[QKVN * HH];            // [wqa ; wkva] fused
    __half wqb_h[NHH * DQK * QLAT];
    __half wkb_h[NHH * NOPE * KVLAT];
    __half wvb_h[NHH * VDIM * KVLAT];
    __half wo_h[HH * NHH * VDIM];
    __half wsup_h[2 * SHI * HH];
    __half wsdn_h[HH * SHI];
    __half wup_h[(long long)NE * 2 * MIDIM * HH];
    __half wdn_h[(long long)NE * HH * MIDIM];
};
__device__ Scratch g_s;

// ---------------------------------------------------------------------------
// helpers
// ---------------------------------------------------------------------------
__device__ __forceinline__ uint32_t smem_u32(const void* p) {
    uint32_t a;
    asm("{ .reg .u64 t; cvta.to.shared.u64 t, %1; cvt.u32.u64 %0, t; }" : "=r"(a) : "l"(p));
    return a;
}

__device__ __forceinline__ void cp16(uint32_t dst, const void* src, int sz) {
    asm volatile("cp.async.cg.shared.global [%0], [%1], 16, %2;"
                 :: "r"(dst), "l"(src), "r"(sz));
}
__device__ __forceinline__ void cp_commit() {
    asm volatile("cp.async.commit_group;" ::: "memory");
}

__device__ __forceinline__ void ldm_x4(unsigned& r0, unsigned& r1, unsigned& r2,
                                       unsigned& r3, uint32_t addr) {
    asm volatile("ldmatrix.sync.aligned.m8n8.x4.shared.b16 {%0,%1,%2,%3}, [%4];"
                 : "=r"(r0), "=r"(r1), "=r"(r2), "=r"(r3) : "r"(addr));
}

__device__ __forceinline__ void mma_f16(float* d, const unsigned* a, const unsigned* b) {
    asm volatile(
        "mma.sync.aligned.m16n8k16.row.col.f32.f16.f16.f32 "
        "{%0,%1,%2,%3}, {%4,%5,%6,%7}, {%8,%9}, {%0,%1,%2,%3};\n"
        : "+f"(d[0]), "+f"(d[1]), "+f"(d[2]), "+f"(d[3])
        : "r"(a[0]), "r"(a[1]), "r"(a[2]), "r"(a[3]), "r"(b[0]), "r"(b[1]));
}

__device__ __forceinline__ unsigned packh2(float x, float y) {
    __half2 h = __floats2half2_rn(x, y);
    return *reinterpret_cast<unsigned*>(&h);
}

__device__ __forceinline__ uint2 cvt4(float4 v) {
    __half2 h0 = __floats2half2_rn(v.x, v.y);
    __half2 h1 = __floats2half2_rn(v.z, v.w);
    uint2 o;
    o.x = *reinterpret_cast<unsigned*>(&h0);
    o.y = *reinterpret_cast<unsigned*>(&h1);
    return o;
}

// ---------------------------------------------------------------------------
// fp16 NT GEMM (R5 config, frozen) + epilogue fusions
// ---------------------------------------------------------------------------
#define SMEM_BYTES 98304

template <bool OUTH, int NTILE, int NSTAGE, int NTHREADS>
__global__ __launch_bounds__(NTHREADS)
void gemm_h(const __half* __restrict__ A, const __half* __restrict__ B,
            void* __restrict__ Cv,
            int M, int N, int K, int lda, int ldb, int ldc,
            long long sA, long long sB, long long sC,
            float scale, int causal, int klim,
            const int* __restrict__ aidx, const int* __restrict__ mdev,
            const int* __restrict__ cidx, const float* __restrict__ cscale,
            int pstride,
            const float* __restrict__ resid, float* __restrict__ C2, int atomicC,
            const float* __restrict__ rs, const float* __restrict__ rc,
            int ropeq, int cmap192)
{
    constexpr int STG_BYTES = (128 + NTILE) * 128;
    constexpr int LOADS = (128 + NTILE) * 8 / NTHREADS;
    extern __shared__ __align__(128) char smem[];
    const int z = blockIdx.z;
    A += (long long)z * sA;
    B += (long long)z * sB;
    if (pstride) {
        if (mdev)   mdev   += z;
        if (aidx)   aidx   += (long long)z * pstride;
        if (cidx)   cidx   += (long long)z * pstride;
        if (cscale) cscale += (long long)z * pstride;
    }
    const int Meff = mdev ? *mdev : M;
    const int m0 = blockIdx.y * 128;
    const int n0 = blockIdx.x * NTILE;
    if (m0 >= Meff) return;
    if (causal && n0 > m0 + 127) return;
    const int kmax = klim ? min(K, m0 + 128) : K;
    const int ktiles = kmax >> 6;

    const uint32_t sbase = smem_u32(smem);
    const int tid = threadIdx.x;
    const int lane = tid & 31;
    const int wid = tid >> 5;
    const int wm = (wid & 1) * 64;
    const int wn = (wid >> 1) * 64;
    const int lr = lane >> 2;
    const int lm = lane & 3;

    float acc[4][8][4];
#pragma unroll
    for (int i = 0; i < 4; i++)
#pragma unroll
        for (int j = 0; j < 8; j++)
#pragma unroll
            for (int c = 0; c < 4; c++) acc[i][j][c] = 0.f;

    auto issue_stage = [&](int i) {
        const uint32_t base = sbase + (i % NSTAGE) * STG_BYTES;
        const int kt = i << 6;
#pragma unroll
        for (int it = 0; it < LOADS; it++) {
            int c = tid + it * NTHREADS;
            int row = c >> 3, ch = c & 7;
            uint32_t dst = base + row * 128 + ((ch ^ (row & 7)) << 4);
            const __half* src;
            int sz = 0;
            if (row < 128) {
                int gm = m0 + row;
                src = A;
                if (gm < Meff) {
                    int ar = aidx ? aidx[gm] : gm;
                    src = A + (long long)ar * lda + kt + ch * 8;
                    sz = 16;
                }
            } else {
                int gn = n0 + row - 128;
                src = B;
                if (gn < N) {
                    src = B + (long long)gn * ldb + kt + ch * 8;
                    sz = 16;
                }
            }
            cp16(dst, src, sz);
        }
    };

#pragma unroll
    for (int s = 0; s < NSTAGE - 1; s++) {
        if (s < ktiles) issue_stage(s);
        cp_commit();
    }

    const int a_row = lane & 15;
    const int a_h = lane >> 4;
    const int b_t = lane >> 3;
    const int b_r = lane & 7;

    for (int i = 0; i < ktiles; i++) {
        if (i + NSTAGE - 1 < ktiles) issue_stage(i + NSTAGE - 1);
        cp_commit();
        if (NSTAGE == 2)
            asm volatile("cp.async.wait_group 1;" ::: "memory");
        else
            asm volatile("cp.async.wait_group 2;" ::: "memory");
        __syncthreads();

        const uint32_t base = sbase + (i % NSTAGE) * STG_BYTES;
#pragma unroll
        for (int kk = 0; kk < 4; kk++) {
            unsigned afr[4][4], bfr[8][2];
#pragma unroll
            for (int im = 0; im < 4; im++) {
                int row = wm + im * 16 + a_row;
                int ch = kk * 2 + a_h;
                ldm_x4(afr[im][0], afr[im][1], afr[im][2], afr[im][3],
                       base + row * 128 + ((ch ^ (row & 7)) << 4));
            }
#pragma unroll
            for (int j2 = 0; j2 < 4; j2++) {
                int jn = j2 * 2 + (b_t >> 1);
                int row = 128 + wn + jn * 8 + b_r;
                int ch = kk * 2 + (b_t & 1);
                unsigned r0, r1, r2, r3;
                ldm_x4(r0, r1, r2, r3, base + row * 128 + ((ch ^ (row & 7)) << 4));
                bfr[j2 * 2][0] = r0;     bfr[j2 * 2][1] = r1;
                bfr[j2 * 2 + 1][0] = r2; bfr[j2 * 2 + 1][1] = r3;
            }
#pragma unroll
            for (int im = 0; im < 4; im++)
#pragma unroll
                for (int jn = 0; jn < 8; jn++)
                    mma_f16(acc[im][jn], afr[im], bfr[jn]);
        }
        __syncthreads();
    }

#pragma unroll
    for (int im = 0; im < 4; im++) {
#pragma unroll
        for (int part = 0; part < 2; part++) {
            int gm = m0 + wm + im * 16 + lr + part * 8;
            if (gm >= Meff) continue;
            long long crow = gm;
            float w = scale;
            if (cidx) { crow = cidx[gm]; w = scale * cscale[gm]; }
#pragma unroll
            for (int jn = 0; jn < 8; jn++) {
                int gn = n0 + wn + jn * 8 + lm * 2;
                if (gn >= N) continue;
                float vx = acc[im][jn][part * 2] * w;
                float vy = acc[im][jn][part * 2 + 1] * w;
                if (OUTH) {
                    int gn2 = gn;
                    if (ropeq) {
                        int d = gn % DQK;
                        if (d >= NOPE) {
                            int p = (d - NOPE) >> 1;
                            float sn = rs[crow * 32 + p], cs = rc[crow * 32 + p];
                            float tx = vx * cs - vy * sn;
                            vy = vx * sn + vy * cs;
                            vx = tx;
                        }
                    }
                    if (cmap192) gn2 = (gn >> 7) * 192 + (gn & 127);
                    __half* cp = (__half*)Cv + ((long long)z * sC) + crow * (long long)ldc + gn2;
                    *reinterpret_cast<__half2*>(cp) = __floats2half2_rn(vx, vy);
                } else {
                    long long off = crow * (long long)ldc + gn;
                    if (resid) {
                        vx += resid[off];
                        vy += resid[off + 1];
                    }
                    float* cp = (float*)Cv + ((long long)z * sC) + off;
                    if (atomicC) {
                        atomicAdd(cp, vx);
                        atomicAdd(cp + 1, vy);
                    } else {
                        *reinterpret_cast<float2*>(cp) = make_float2(vx, vy);
                        if (C2)
                            *reinterpret_cast<float2*>(C2 + off) = make_float2(vx, vy);
                    }
                }
            }
        }
    }
}

// ---------------------------------------------------------------------------
// Flash attention: 256 threads, 8 warps x 16 q-rows; k-blocks of 64.
// ---------------------------------------------------------------------------
#define SMEM_FLASH 131072

__global__ __launch_bounds__(256, 1)
void flash_attn_k(const __half* __restrict__ Q, const __half* __restrict__ K,
                  const __half* __restrict__ Vt, __half* __restrict__ O,
                  float scale)
{
    extern __shared__ __align__(128) char smem[];
    const int h = blockIdx.x;
    const int qb = (int)gridDim.y - 1 - (int)blockIdx.y;   // heaviest first
    const int nkb = 2 * qb + 2;
    const uint32_t sb = smem_u32(smem);
    const uint32_t Qs = sb;
    const uint32_t Ks = sb + 49152;
    const uint32_t Vs = sb + 49152 + 49152;
    const int tid = threadIdx.x, lane = tid & 31, wid = tid >> 5;
    const int wq = wid * 16;
    const int lr = lane >> 2, lm = lane & 3;

    for (int c = tid; c < 3072; c += 256) {
        int row = c / 24, kc = c % 24;
        int sub = kc >> 3, ch = kc & 7;
        cp16(Qs + row * 384 + sub * 128 + ((ch ^ (row & 7)) << 4),
             Q + ((long long)(qb * 128 + row) * (NHH * DQK) + h * DQK + kc * 8), 16);
    }
    auto load_kv = [&](int kb) {
        int buf = kb & 1;
        for (int c = tid; c < 1536; c += 256) {
            int row = c / 24, kc = c % 24;
            int sub = kc >> 3, ch = kc & 7;
            cp16(Ks + buf * 24576 + row * 384 + sub * 128 + ((ch ^ (row & 7)) << 4),
                 K + ((long long)(kb * 64 + row) * (NHH * DQK) + h * DQK + kc * 8), 16);
        }
        for (int c = tid; c < 1024; c += 256) {
            int row = c >> 3, ch = c & 7;
            cp16(Vs + buf * 16384 + row * 128 + ((ch ^ (row & 7)) << 4),
                 Vt + ((long long)(h * 128 + row) * TT + kb * 64 + ch * 8), 16);
        }
    };

    load_kv(0);
    cp_commit();

    float m_s[2] = {-1e30f, -1e30f}, l_s[2] = {0.f, 0.f};
    float acc[16][4];
#pragma unroll
    for (int dn = 0; dn < 16; dn++)
#pragma unroll
        for (int c = 0; c < 4; c++) acc[dn][c] = 0.f;

    const int a_row = lane & 15, a_h = lane >> 4;
    const int b_t = lane >> 3, b_r = lane & 7;

    for (int kb = 0; kb < nkb; kb++) {
        if (kb + 1 < nkb) load_kv(kb + 1);
        cp_commit();
        asm volatile("cp.async.wait_group 1;" ::: "memory");
        __syncthreads();
        const uint32_t kbase = Ks + (kb & 1) * 24576;
        const uint32_t vbase = Vs + (kb & 1) * 16384;

        float s[8][4];
#pragma unroll
        for (int jn = 0; jn < 8; jn++)
#pragma unroll
            for (int c = 0; c < 4; c++) s[jn][c] = 0.f;

#pragma unroll
        for (int ks = 0; ks < 12; ks++) {
            unsigned afr[4], bfr[8][2];
            {
                int row = wq + a_row;
                int kc = ks * 2 + a_h;
                ldm_x4(afr[0], afr[1], afr[2], afr[3],
                       Qs + row * 384 + (kc >> 3) * 128 + (((kc & 7) ^ (row & 7)) << 4));
            }
#pragma unroll
            for (int j2 = 0; j2 < 4; j2++) {
                int jn = j2 * 2 + (b_t >> 1);
                int row = jn * 8 + b_r;
                int kc = ks * 2 + (b_t & 1);
                unsigned r0, r1, r2, r3;
                ldm_x4(r0, r1, r2, r3,
                       kbase + row * 384 + (kc >> 3) * 128 + (((kc & 7) ^ (row & 7)) << 4));
                bfr[j2 * 2][0] = r0;     bfr[j2 * 2][1] = r1;
                bfr[j2 * 2 + 1][0] = r2; bfr[j2 * 2 + 1][1] = r3;
            }
#pragma unroll
            for (int jn = 0; jn < 8; jn++)
                mma_f16(s[jn], afr, bfr[jn]);
        }

        const int coff = kb * 64 - qb * 128;
        float alpha[2];
#pragma unroll
        for (int part = 0; part < 2; part++) {
            int r = wq + lr + part * 8;
            float mx = -1e30f;
#pragma unroll
            for (int jn = 0; jn < 8; jn++) {
#pragma unroll
                for (int q = 0; q < 2; q++) {
                    int c = jn * 8 + lm * 2 + q;
                    float v = s[jn][part * 2 + q] * scale;
                    if (c + coff > r) v = -1e30f;
                    s[jn][part * 2 + q] = v;
                    mx = fmaxf(mx, v);
                }
            }
            mx = fmaxf(mx, __shfl_xor_sync(0xffffffffu, mx, 1));
            mx = fmaxf(mx, __shfl_xor_sync(0xffffffffu, mx, 2));
            float mo = m_s[part];
            float mn = fmaxf(mo, mx);
            float al = __expf(mo - mn);
            float sum = 0.f;
#pragma unroll
            for (int jn = 0; jn < 8; jn++) {
#pragma unroll
                for (int q = 0; q < 2; q++) {
                    float p = __expf(s[jn][part * 2 + q] - mn);
                    s[jn][part * 2 + q] = p;
                    sum += p;
                }
            }
            sum += __shfl_xor_sync(0xffffffffu, sum, 1);
            sum += __shfl_xor_sync(0xffffffffu, sum, 2);
            l_s[part] = l_s[part] * al + sum;
            m_s[part] = mn;
            alpha[part] = al;
        }
#pragma unroll
        for (int dn = 0; dn < 16; dn++) {
            acc[dn][0] *= alpha[0];
            acc[dn][1] *= alpha[0];
            acc[dn][2] *= alpha[1];
            acc[dn][3] *= alpha[1];
        }

#pragma unroll
        for (int kv = 0; kv < 4; kv++) {
            unsigned ap[4];
            ap[0] = packh2(s[2 * kv][0], s[2 * kv][1]);
            ap[1] = packh2(s[2 * kv][2], s[2 * kv][3]);
            ap[2] = packh2(s[2 * kv + 1][0], s[2 * kv + 1][1]);
            ap[3] = packh2(s[2 * kv + 1][2], s[2 * kv + 1][3]);
#pragma unroll
            for (int j2 = 0; j2 < 8; j2++) {
                int dn = j2 * 2 + (b_t >> 1);
                int row = dn * 8 + b_r;
                int ch = kv * 2 + (b_t & 1);
                unsigned r0, r1, r2, r3;
                ldm_x4(r0, r1, r2, r3, vbase + row * 128 + ((ch ^ (row & 7)) << 4));
                unsigned bv0[2] = {r0, r1}, bv1[2] = {r2, r3};
                mma_f16(acc[j2 * 2], ap, bv0);
                mma_f16(acc[j2 * 2 + 1], ap, bv1);
            }
        }
        __syncthreads();
    }

#pragma unroll
    for (int part = 0; part < 2; part++) {
        float inv = 1.0f / l_s[part];
        int grow = qb * 128 + wq + lr + part * 8;
        __half* op = O + (long long)grow * (NHH * VDIM) + h * VDIM;
#pragma unroll
        for (int dn = 0; dn < 16; dn++) {
            int col = dn * 8 + lm * 2;
            *reinterpret_cast<__half2*>(op + col) =
                __floats2half2_rn(acc[dn][part * 2] * inv,
                                  acc[dn][part * 2 + 1] * inv);
        }
    }
}

// ---------------------------------------------------------------------------
// Elementwise / reduction kernels
// ---------------------------------------------------------------------------
__global__ void zero_counts_k() {
    if (threadIdx.x < NE) g_s.counts[threadIdx.x] = 0;
}

// ---- single-launch weight conversion ----
// thread counts per segment (n_elems / 16)
#define TQA   196608   // wqa   -> wqkva_h
#define TKVA  73728    // wkva  -> wqkva_h + QLAT*HH
#define TQB   294912
#define TKB   65536
#define TVB   65536
#define TWO   262144
#define TSUP  262144
#define TSDN  131072
#define TUP   1048576
#define TDN   524288
#define B0 TQA
#define B1 (B0 + TKVA)
#define B2 (B1 + TQB)
#define B3 (B2 + TKB)
#define B4 (B3 + TVB)
#define B5 (B4 + TWO)
#define B6 (B5 + TSUP)
#define B7 (B6 + TSDN)
#define B8 (B7 + TUP)
#define B9 (B8 + TDN)   // 2924544 total threads = 11424 * 256

__device__ __forceinline__ void f2h_seg(const float4* in, uint2* out,
                                        long long t, long long q) {
    float4 a = in[t];
    float4 b = in[t + q];
    float4 c = in[t + 2 * q];
    float4 d = in[t + 3 * q];
    out[t]         = cvt4(a);
    out[t + q]     = cvt4(b);
    out[t + 2 * q] = cvt4(c);
    out[t + 3 * q] = cvt4(d);
}

__global__ __launch_bounds__(256)
void f2h_all_k(const float* wqa, const float* wkva, const float* wqb,
               const float* wkb, const float* wvb, const float* wo,
               const float* wsup, const float* wsdn, const float* wup,
               const float* wdn)
{
    long long g = blockIdx.x * 256LL + threadIdx.x;
    if (g < B0)      f2h_seg((const float4*)wqa,  (uint2*)g_s.wqkva_h, g, TQA);
    else if (g < B1) f2h_seg((const float4*)wkva, (uint2*)(g_s.wqkva_h + (long long)QLAT * HH), g - B0, TKVA);
    else if (g < B2) f2h_seg((const float4*)wqb,  (uint2*)g_s.wqb_h,  g - B1, TQB);
    else if (g < B3) f2h_seg((const float4*)wkb,  (uint2*)g_s.wkb_h,  g - B2, TKB);
    else if (g < B4) f2h_seg((const float4*)wvb,  (uint2*)g_s.wvb_h,  g - B3, TVB);
    else if (g < B5) f2h_seg((const float4*)wo,   (uint2*)g_s.wo_h,   g - B4, TWO);
    else if (g < B6) f2h_seg((const float4*)wsup, (uint2*)g_s.wsup_h, g - B5, TSUP);
    else if (g < B7) f2h_seg((const float4*)wsdn, (uint2*)g_s.wsdn_h, g - B6, TSDN);
    else if (g < B8) f2h_seg((const float4*)wup,  (uint2*)g_s.wup_h,  g - B7, TUP);
    else             f2h_seg((const float4*)wdn,  (uint2*)g_s.wdn_h,  g - B8, TDN);
}

// fused: x1 = x + skip (stored), n1h = rms(x1)*w
__global__ __launch_bounds__(256)
void addrms_k(const float* __restrict__ x, const float* __restrict__ skip,
              const float* __restrict__ w, float* __restrict__ x1,
              __half* __restrict__ out) {
    int row = blockIdx.x;
    const float4* xp = (const float4*)(x + (long long)row * HH);
    const float4* sp = (const float4*)(skip + (long long)row * HH);
    float4* x1p = (float4*)(x1 + (long long)row * HH);
    float4 vals[2];
    float ss = 0.f;
#pragma unroll
    for (int i = 0; i < 2; i++) {
        int j = threadIdx.x + i * 256;
        float4 a = xp[j], b = sp[j];
        float4 v = make_float4(a.x + b.x, a.y + b.y, a.z + b.z, a.w + b.w);
        vals[i] = v;
        x1p[j] = v;
        ss += v.x * v.x + v.y * v.y + v.z * v.z + v.w * v.w;
    }
    __shared__ float red[256];
    red[threadIdx.x] = ss;
    __syncthreads();
    for (int st = 128; st > 0; st >>= 1) {
        if (threadIdx.x < st) red[threadIdx.x] += red[threadIdx.x + st];
        __syncthreads();
    }
    float scale = rsqrtf(red[0] / (float)HH + 1e-6f);
    uint2* op = (uint2*)(out + (long long)row * HH);
    const float4* wp = (const float4*)w;
#pragma unroll
    for (int i = 0; i < 2; i++) {
        int j = threadIdx.x + i * 256;
        float4 v = vals[i], ww = wp[j];
        op[j] = cvt4(make_float4(v.x * scale * ww.x, v.y * scale * ww.y,
                                 v.z * scale * ww.z, v.w * scale * ww.w));
    }
}

__device__ __forceinline__ void rms_row(const float* in, const float* w,
                                        __half* out, int cols) {
    const float4* ip = (const float4*)in;
    int c4 = cols >> 2;
    float ss = 0.f;
    for (int j = threadIdx.x; j < c4; j += 256) {
        float4 v = ip[j];
        ss += v.x * v.x + v.y * v.y + v.z * v.z + v.w * v.w;
    }
    __shared__ float red[256];
    red[threadIdx.x] = ss;
    __syncthreads();
    for (int st = 128; st > 0; st >>= 1) {
        if (threadIdx.x < st) red[threadIdx.x] += red[threadIdx.x + st];
        __syncthreads();
    }
    float scale = rsqrtf(red[0] / (float)cols + 1e-6f);
    uint2* op = (uint2*)out;
    const float4* wp = (const float4*)w;
    for (int j = threadIdx.x; j < c4; j += 256) {
        float4 v = ip[j], ww = wp[j];
        op[j] = cvt4(make_float4(v.x * scale * ww.x, v.y * scale * ww.y,
                                 v.z * scale * ww.z, v.w * scale * ww.w));
    }
}

__global__ __launch_bounds__(256)
void rmsnorm_h_k(const float* __restrict__ in, const float* __restrict__ w,
                 __half* __restrict__ out, int cols, int instride, int outstride) {
    int row = blockIdx.x;
    rms_row(in + (long long)row * instride, w, out + (long long)row * outstride, cols);
}

// merged qa + ckv rmsnorm (y=0: qa slice, y=1: ckv slice of qkv_pre)
__global__ __launch_bounds__(256)
void rmsnorm_qkv_k(const float* __restrict__ qkv, const float* __restrict__ qan,
                   const float* __restrict__ kvan,
                   __half* __restrict__ qah, __half* __restrict__ ckvh) {
    int row = blockIdx.x;
    if (blockIdx.y == 0)
        rms_row(qkv + (long long)row * QKVN, qan, qah + (long long)row * QLAT, QLAT);
    else
        rms_row(qkv + (long long)row * QKVN + QLAT, kvan,
                ckvh + (long long)row * KVLAT, KVLAT);
}

// fill rope PE columns of kfull
__global__ void build_pe_k(const float* __restrict__ qkv,
                           const float* __restrict__ rsin,
                           const float* __restrict__ rcos,
                           __half* __restrict__ kfull) {
    int t = blockIdx.x;
    __shared__ __half pe[ROPED];
    if (threadIdx.x < 32) {
        int p = threadIdx.x;
        float a = qkv[(long long)t * QKVN + QLAT + KVLAT + 2 * p];
        float b = qkv[(long long)t * QKVN + QLAT + KVLAT + 2 * p + 1];
        float s = rsin[t * 32 + p], c = rcos[t * 32 + p];
        pe[2 * p]     = __float2half_rn(a * c - b * s);
        pe[2 * p + 1] = __float2half_rn(a * s + b * c);
    }
    __syncthreads();
    for (int i = threadIdx.x; i < NHH * ROPED; i += blockDim.x) {
        int h = i >> 6;
        int d = i & 63;
        kfull[(long long)t * (NHH * DQK) + h * DQK + NOPE + d] = pe[d];
    }
}

__global__ __launch_bounds__(256)
void gate_topk_k(const __half* __restrict__ n2, const float* __restrict__ gw) {
    int t = blockIdx.x;
    __shared__ float logits[NE];
    int warp = threadIdx.x >> 5, lane = threadIdx.x & 31;
    const __half* xp = n2 + (long long)t * HH;
    const float* wp = gw + warp * HH;
    float s = 0.f;
    for (int k = lane; k < HH; k += 32) s += __half2float(xp[k]) * wp[k];
    for (int off = 16; off > 0; off >>= 1) s += __shfl_down_sync(0xffffffffu, s, off);
    if (lane == 0) logits[warp] = s;
    __syncthreads();
    if (threadIdx.x == 0) {
        float m = logits[0];
        for (int e = 1; e < NE; e++) m = fmaxf(m, logits[e]);
        float p[NE];
        float sum = 0.f;
        for (int e = 0; e < NE; e++) { p[e] = __expf(logits[e] - m); sum += p[e]; }
        for (int e = 0; e < NE; e++) p[e] /= sum;
        int i0 = 0;
        for (int e = 1; e < NE; e++) if (p[e] > p[i0]) i0 = e;
        int i1 = -1;
        for (int e = 0; e < NE; e++) {
            if (e == i0) continue;
            if (i1 < 0 || p[e] > p[i1]) i1 = e;
        }
        float w0 = p[i0], w1 = p[i1];
        float tot = w0 + w1;
        w0 /= tot; w1 /= tot;
        int pos0 = atomicAdd(&g_s.counts[i0], 1);
        g_s.tok[i0 * TT + pos0] = t;
        g_s.ew[i0 * TT + pos0] = w0;
        int pos1 = atomicAdd(&g_s.counts[i1], 1);
        g_s.tok[i1 * TT + pos1] = t;
        g_s.ew[i1 * TT + pos1] = w1;
    }
}

__global__ void silu_gate_k(const float* __restrict__ in, __half* __restrict__ out,
                            int half_) {
    int row = blockIdx.x;
    const float4* ip = (const float4*)(in + (long long)row * 2 * half_);
    const float4* gp = (const float4*)(in + (long long)row * 2 * half_ + half_);
    uint2* op = (uint2*)(out + (long long)row * half_);
    int h4 = half_ >> 2;
    for (int j = threadIdx.x; j < h4; j += blockDim.x) {
        float4 a = ip[j], b = gp[j];
        float4 r;
        r.x = (a.x / (1.f + __expf(-a.x))) * b.x;
        r.y = (a.y / (1.f + __expf(-a.y))) * b.y;
        r.z = (a.z / (1.f + __expf(-a.z))) * b.z;
        r.w = (a.w / (1.f + __expf(-a.w))) * b.w;
        op[j] = cvt4(r);
    }
}

__global__ void silu_gate_moe_k() {
    int e = blockIdx.y;
    int row = blockIdx.x;
    if (row >= g_s.counts[e]) return;
    const float* base = g_s.h + ((long long)e * TT + row) * (2 * MIDIM);
    const float4* ip = (const float4*)base;
    const float4* gp = (const float4*)(base + MIDIM);
    uint2* op = (uint2*)(g_s.hah + ((long long)e * TT + row) * MIDIM);
    for (int j = threadIdx.x; j < (MIDIM >> 2); j += blockDim.x) {
        float4 a = ip[j], b = gp[j];
        float4 r;
        r.x = (a.x / (1.f + __expf(-a.x))) * b.x;
        r.y = (a.y / (1.f + __expf(-a.y))) * b.y;
        r.z = (a.z / (1.f + __expf(-a.z))) * b.z;
        r.w = (a.w / (1.f + __expf(-a.w))) * b.w;
        op[j] = cvt4(r);
    }
}

// ---------------------------------------------------------------------------
// Host-side launch helpers
// ---------------------------------------------------------------------------
static void launch_gemm(bool wide, bool outh, const __half* A, const __half* B, void* C,
                        int M, int N, int K, int lda, int ldb, int ldc,
                        long long sA, long long sB, long long sC, int bz,
                        float sc, int causal, int klim,
                        const int* aidx, const int* mdev,
                        const int* cidx, const float* cs, int pstride,
                        const float* resid = nullptr, float* C2 = nullptr,
                        int atomicC = 0,
                        const float* rs = nullptr, const float* rc = nullptr,
                        int ropeq = 0, int cmap192 = 0)
{
    if (wide) {
        dim3 grid((N + 255) / 256, (M + 127) / 128, bz);
        if (outh)
            gemm_h<true, 256, 2, 256><<<grid, 256, SMEM_BYTES>>>(
                A, B, C, M, N, K, lda, ldb, ldc, sA, sB, sC, sc, causal, klim,
                aidx, mdev, cidx, cs, pstride, resid, C2, atomicC, rs, rc, ropeq, cmap192);
        else
            gemm_h<false, 256, 2, 256><<<grid, 256, SMEM_BYTES>>>(
                A, B, C, M, N, K, lda, ldb, ldc, sA, sB, sC, sc, causal, klim,
                aidx, mdev, cidx, cs, pstride, resid, C2, atomicC, rs, rc, ropeq, cmap192);
    } else {
        dim3 grid((N + 127) / 128, (M + 127) / 128, bz);
        if (outh)
            gemm_h<true, 128, 3, 128><<<grid, 128, SMEM_BYTES>>>(
                A, B, C, M, N, K, lda, ldb, ldc, sA, sB, sC, sc, causal, klim,
                aidx, mdev, cidx, cs, pstride, resid, C2, atomicC, rs, rc, ropeq, cmap192);
        else
            gemm_h<false, 128, 3, 128><<<grid, 128, SMEM_BYTES>>>(
                A, B, C, M, N, K, lda, ldb, ldc, sA, sB, sC, sc, causal, klim,
                aidx, mdev, cidx, cs, pstride, resid, C2, atomicC, rs, rc, ropeq, cmap192);
    }
}

static void launch_nt(bool wide, bool outh, const __half* A, const __half* B, void* C,
                      int M, int N, int K, int lda, int ldb, int ldc)
{
    launch_gemm(wide, outh, A, B, C, M, N, K, lda, ldb, ldc, 0, 0, 0, 1, 1.f, 0, 0,
                nullptr, nullptr, nullptr, nullptr, 0);
}

// ---------------------------------------------------------------------------
extern "C" void kernel_launch(void* const* d_in, const int* in_sizes, int n_in,
                              void* d_out, int out_size)
{
    const float* x    = (const float*)d_in[0];
    const float* skip = (const float*)d_in[1];
    const float* rsin = (const float*)d_in[2];
    const float* rcos = (const float*)d_in[3];
    const float* ln1  = (const float*)d_in[4];
    const float* ln2  = (const float*)d_in[5];
    const float* wqa  = (const float*)d_in[6];
    const float* qan  = (const float*)d_in[7];
    const float* wqb  = (const float*)d_in[8];
    const float* wkva = (const float*)d_in[9];
    const float* kvan = (const float*)d_in[10];
    const float* wkb  = (const float*)d_in[11];
    const float* wvb  = (const float*)d_in[12];
    const float* wo   = (const float*)d_in[13];
    const float* gw   = (const float*)d_in[14];
    const float* wup  = (const float*)d_in[15];
    const float* wdn  = (const float*)d_in[16];
    const float* wsup = (const float*)d_in[17];
    const float* wsdn = (const float*)d_in[18];
    float* out = (float*)d_out;

    Scratch* s = nullptr;
    cudaGetSymbolAddress((void**)&s, g_s);
    cudaFuncSetAttribute((const void*)gemm_h<true, 256, 2, 256>,
                         cudaFuncAttributeMaxDynamicSharedMemorySize, SMEM_BYTES);
    cudaFuncSetAttribute((const void*)gemm_h<false, 256, 2, 256>,
                         cudaFuncAttributeMaxDynamicSharedMemorySize, SMEM_BYTES);
    cudaFuncSetAttribute((const void*)gemm_h<true, 128, 3, 128>,
                         cudaFuncAttributeMaxDynamicSharedMemorySize, SMEM_BYTES);
    cudaFuncSetAttribute((const void*)gemm_h<false, 128, 3, 128>,
                         cudaFuncAttributeMaxDynamicSharedMemorySize, SMEM_BYTES);
    cudaFuncSetAttribute((const void*)flash_attn_k,
                         cudaFuncAttributeMaxDynamicSharedMemorySize, SMEM_FLASH);

    const int n = TT * HH;
    float* out2 = out + (long long)n;

    zero_counts_k<<<1, 32>>>();

    // all weights -> half in ONE launch
    f2h_all_k<<<B9 / 256, 256>>>(wqa, wkva, wqb, wkb, wvb, wo, wsup, wsdn, wup, wdn);

    // x1 = x + skip ; n1h = rms(x1)
    addrms_k<<<TT, 256>>>(x, skip, ln1, s->x1, s->n1h);

    // fused qa+kva projection
    launch_nt(true, false, s->n1h, s->wqkva_h, s->qkv_pre, TT, QKVN, HH, HH, HH, QKVN);

    // merged qa + ckv rmsnorm
    rmsnorm_qkv_k<<<dim3(TT, 2), 256>>>(s->qkv_pre, qan, kvan, s->qah, s->ckvh);

    // q path: qb GEMM with fused rope epilogue
    launch_gemm(true, true, s->qah, s->wqb_h, s->qh, TT, NHH * DQK, QLAT,
                QLAT, QLAT, NHH * DQK, 0, 0, 0, 1,
                1.f, 0, 0, nullptr, nullptr, nullptr, nullptr, 0,
                nullptr, nullptr, 0, rsin, rcos, /*ropeq=*/1, 0);

    // kv path: kb GEMM writes kfull directly (column remap), then PE fill
    launch_gemm(true, true, s->ckvh, s->wkb_h, s->kfullh, TT, NHH * NOPE, KVLAT,
                KVLAT, KVLAT, NHH * DQK, 0, 0, 0, 1,
                1.f, 0, 0, nullptr, nullptr, nullptr, nullptr, 0,
                nullptr, nullptr, 0, nullptr, nullptr, 0, /*cmap192=*/1);
    build_pe_k<<<TT, 256>>>(s->qkv_pre, rsin, rcos, s->kfullh);
    launch_nt(true, true, s->wvb_h, s->ckvh, s->vTh, NHH * VDIM, TT, KVLAT, KVLAT, KVLAT, TT);

    // fused flash attention
    float attn_scale = 1.0f / sqrtf((float)DQK);
    flash_attn_k<<<dim3(NHH, TT / 128), 256, SMEM_FLASH>>>(
        s->qh, s->kfullh, s->vTh, s->oh, attn_scale);

    // attn out + residual fused: out[0:n] = x2 = x1 + oh @ wo^T
    launch_gemm(true, false, s->oh, s->wo_h, out, TT, HH, NHH * VDIM,
                NHH * VDIM, NHH * VDIM, HH, 0, 0, 0, 1,
                1.f, 0, 0, nullptr, nullptr, nullptr, nullptr, 0,
                s->x1, s->x2, 0);

    // n2 and MoE gating
    rmsnorm_h_k<<<TT, 256>>>(s->x2, ln2, s->n2h, HH, HH, HH);
    gate_topk_k<<<TT, 256>>>(s->n2h, gw);

    // shared FFN -> out2 directly
    launch_nt(true, false, s->n2h, s->wsup_h, s->hs, TT, 2 * SHI, HH, HH, HH, 2 * SHI);
    silu_gate_k<<<TT, 256>>>(s->hs, s->hsah, SHI);
    launch_nt(true, false, s->hsah, s->wsdn_h, out2, TT, HH, SHI, SHI, SHI, HH);

    // routed experts
    launch_gemm(true, false, s->n2h, s->wup_h, s->h, TT, 2 * MIDIM, HH,
                HH, HH, 2 * MIDIM,
                0, (long long)(2 * MIDIM) * HH, (long long)TT * 2 * MIDIM, NE,
                1.f, 0, 0,
                s->tok, s->counts, nullptr, nullptr, TT);
    silu_gate_moe_k<<<dim3(TT, NE), 256>>>();
    launch_gemm(true, false, s->hah, s->wdn_h, out2, TT, HH, MIDIM,
                MIDIM, MIDIM, HH,
                (long long)TT * MIDIM, (long long)HH * MIDIM, 0, NE,
                1.f, 0, 0,
                nullptr, s->counts, s->tok, s->ew, TT,
                nullptr, nullptr, 1);
}

// round 16
// speedup vs baseline: 1.4128x; 1.0004x over previous
#include <cuda_runtime.h>
#include <cuda_fp16.h>
#include <math.h>
#include <stdint.h>

#define TT   2048
#define HH   2048
#define NHH  16
#define NOPE 128
#define ROPED 64
#define DQK  192     // NOPE + ROPE
#define VDIM 128
#define QLAT 1536
#define KVLAT 512
#define NE   8
#define MIDIM 512
#define SHI  1024    // 2*MI
#define QKVN (QLAT + KVLAT + ROPED)   // 2112

// ---------------------------------------------------------------------------
// Scratch (static device memory; no allocations anywhere)
// ---------------------------------------------------------------------------
struct __align__(128) Scratch {
    // f32 buffers
    float x1[TT * HH];
    float qkv_pre[TT * QKVN];            // [qa_pre | kv] fused
    float x2[TT * HH];
    float h[(long long)NE * TT * 2 * MIDIM];
    float hs[TT * 2 * SHI];
    float ew[NE * TT];
    int   tok[NE * TT];
    int   counts[NE];
    // half activation buffers
    __half n1h[TT * HH];
    __half qah[TT * QLAT];
    __half qh[TT * NHH * DQK];
    __half ckvh[TT * KVLAT];
    __half kfullh[TT * NHH * DQK];
    __half vTh[NHH * VDIM * TT];          // [h*128+d, t]
    __half oh[TT * NHH * VDIM];
    __half n2h[TT * HH];
    __half hsah[TT * SHI];
    __half hah[(long long)NE * TT * MIDIM];
    // half weight copies
    __half wqkva_h[QKVN * HH];            // [wqa ; wkva] fused
    __half wqb_h[NHH * DQK * QLAT];
    __half wkb_h[NHH * NOPE * KVLAT];
    __half wvb_h[NHH * VDIM * KVLAT];
    __half wo_h[HH * NHH * VDIM];
    __half wsup_h[2 * SHI * HH];
    __half wsdn_h[HH * SHI];
    __half wup_h[(long long)NE * 2 * MIDIM * HH];
    __half wdn_h[(long long)NE * HH * MIDIM];
};
__device__ Scratch g_s;

// ---------------------------------------------------------------------------
// helpers
// ---------------------------------------------------------------------------
__device__ __forceinline__ uint32_t smem_u32(const void* p) {
    uint32_t a;
    asm("{ .reg .u64 t; cvta.to.shared.u64 t, %1; cvt.u32.u64 %0, t; }" : "=r"(a) : "l"(p));
    return a;
}

__device__ __forceinline__ void cp16(uint32_t dst, const void* src, int sz) {
    asm volatile("cp.async.cg.shared.global [%0], [%1], 16, %2;"
                 :: "r"(dst), "l"(src), "r"(sz));
}
__device__ __forceinline__ void cp_commit() {
    asm volatile("cp.async.commit_group;" ::: "memory");
}

__device__ __forceinline__ void ldm_x4(unsigned& r0, unsigned& r1, unsigned& r2,
                                       unsigned& r3, uint32_t addr) {
    asm volatile("ldmatrix.sync.aligned.m8n8.x4.shared.b16 {%0,%1,%2,%3}, [%4];"
                 : "=r"(r0), "=r"(r1), "=r"(r2), "=r"(r3) : "r"(addr));
}

__device__ __forceinline__ void mma_f16(float* d, const unsigned* a, const unsigned* b) {
    asm volatile(
        "mma.sync.aligned.m16n8k16.row.col.f32.f16.f16.f32 "
        "{%0,%1,%2,%3}, {%4,%5,%6,%7}, {%8,%9}, {%0,%1,%2,%3};\n"
        : "+f"(d[0]), "+f"(d[1]), "+f"(d[2]), "+f"(d[3])
        : "r"(a[0]), "r"(a[1]), "r"(a[2]), "r"(a[3]), "r"(b[0]), "r"(b[1]));
}

__device__ __forceinline__ unsigned packh2(float x, float y) {
    __half2 h = __floats2half2_rn(x, y);
    return *reinterpret_cast<unsigned*>(&h);
}

__device__ __forceinline__ uint2 cvt4(float4 v) {
    __half2 h0 = __floats2half2_rn(v.x, v.y);
    __half2 h1 = __floats2half2_rn(v.z, v.w);
    uint2 o;
    o.x = *reinterpret_cast<unsigned*>(&h0);
    o.y = *reinterpret_cast<unsigned*>(&h1);
    return o;
}

// ---------------------------------------------------------------------------
// fp16 NT GEMM (R5 config, frozen) + epilogue fusions
// ---------------------------------------------------------------------------
#define SMEM_BYTES 98304

template <bool OUTH, int NTILE, int NSTAGE, int NTHREADS>
__global__ __launch_bounds__(NTHREADS)
void gemm_h(const __half* __restrict__ A, const __half* __restrict__ B,
            void* __restrict__ Cv,
            int M, int N, int K, int lda, int ldb, int ldc,
            long long sA, long long sB, long long sC,
            float scale, int causal, int klim,
            const int* __restrict__ aidx, const int* __restrict__ mdev,
            const int* __restrict__ cidx, const float* __restrict__ cscale,
            int pstride,
            const float* __restrict__ resid, float* __restrict__ C2, int atomicC,
            const float* __restrict__ rs, const float* __restrict__ rc,
            int ropeq, int cmap192)
{
    constexpr int STG_BYTES = (128 + NTILE) * 128;
    constexpr int LOADS = (128 + NTILE) * 8 / NTHREADS;
    extern __shared__ __align__(128) char smem[];
    const int z = blockIdx.z;
    A += (long long)z * sA;
    B += (long long)z * sB;
    if (pstride) {
        if (mdev)   mdev   += z;
        if (aidx)   aidx   += (long long)z * pstride;
        if (cidx)   cidx   += (long long)z * pstride;
        if (cscale) cscale += (long long)z * pstride;
    }
    const int Meff = mdev ? *mdev : M;
    const int m0 = blockIdx.y * 128;
    const int n0 = blockIdx.x * NTILE;
    if (m0 >= Meff) return;
    if (causal && n0 > m0 + 127) return;
    const int kmax = klim ? min(K, m0 + 128) : K;
    const int ktiles = kmax >> 6;

    const uint32_t sbase = smem_u32(smem);
    const int tid = threadIdx.x;
    const int lane = tid & 31;
    const int wid = tid >> 5;
    const int wm = (wid & 1) * 64;
    const int wn = (wid >> 1) * 64;
    const int lr = lane >> 2;
    const int lm = lane & 3;

    float acc[4][8][4];
#pragma unroll
    for (int i = 0; i < 4; i++)
#pragma unroll
        for (int j = 0; j < 8; j++)
#pragma unroll
            for (int c = 0; c < 4; c++) acc[i][j][c] = 0.f;

    auto issue_stage = [&](int i) {
        const uint32_t base = sbase + (i % NSTAGE) * STG_BYTES;
        const int kt = i << 6;
#pragma unroll
        for (int it = 0; it < LOADS; it++) {
            int c = tid + it * NTHREADS;
            int row = c >> 3, ch = c & 7;
            uint32_t dst = base + row * 128 + ((ch ^ (row & 7)) << 4);
            const __half* src;
            int sz = 0;
            if (row < 128) {
                int gm = m0 + row;
                src = A;
                if (gm < Meff) {
                    int ar = aidx ? aidx[gm] : gm;
                    src = A + (long long)ar * lda + kt + ch * 8;
                    sz = 16;
                }
            } else {
                int gn = n0 + row - 128;
                src = B;
                if (gn < N) {
                    src = B + (long long)gn * ldb + kt + ch * 8;
                    sz = 16;
                }
            }
            cp16(dst, src, sz);
        }
    };

#pragma unroll
    for (int s = 0; s < NSTAGE - 1; s++) {
        if (s < ktiles) issue_stage(s);
        cp_commit();
    }

    const int a_row = lane & 15;
    const int a_h = lane >> 4;
    const int b_t = lane >> 3;
    const int b_r = lane & 7;

    for (int i = 0; i < ktiles; i++) {
        if (i + NSTAGE - 1 < ktiles) issue_stage(i + NSTAGE - 1);
        cp_commit();
        if (NSTAGE == 2)
            asm volatile("cp.async.wait_group 1;" ::: "memory");
        else
            asm volatile("cp.async.wait_group 2;" ::: "memory");
        __syncthreads();

        const uint32_t base = sbase + (i % NSTAGE) * STG_BYTES;
#pragma unroll
        for (int kk = 0; kk < 4; kk++) {
            unsigned afr[4][4], bfr[8][2];
#pragma unroll
            for (int im = 0; im < 4; im++) {
                int row = wm + im * 16 + a_row;
                int ch = kk * 2 + a_h;
                ldm_x4(afr[im][0], afr[im][1], afr[im][2], afr[im][3],
                       base + row * 128 + ((ch ^ (row & 7)) << 4));
            }
#pragma unroll
            for (int j2 = 0; j2 < 4; j2++) {
                int jn = j2 * 2 + (b_t >> 1);
                int row = 128 + wn + jn * 8 + b_r;
                int ch = kk * 2 + (b_t & 1);
                unsigned r0, r1, r2, r3;
                ldm_x4(r0, r1, r2, r3, base + row * 128 + ((ch ^ (row & 7)) << 4));
                bfr[j2 * 2][0] = r0;     bfr[j2 * 2][1] = r1;
                bfr[j2 * 2 + 1][0] = r2; bfr[j2 * 2 + 1][1] = r3;
            }
#pragma unroll
            for (int im = 0; im < 4; im++)
#pragma unroll
                for (int jn = 0; jn < 8; jn++)
                    mma_f16(acc[im][jn], afr[im], bfr[jn]);
        }
        __syncthreads();
    }

#pragma unroll
    for (int im = 0; im < 4; im++) {
#pragma unroll
        for (int part = 0; part < 2; part++) {
            int gm = m0 + wm + im * 16 + lr + part * 8;
            if (gm >= Meff) continue;
            long long crow = gm;
            float w = scale;
            if (cidx) { crow = cidx[gm]; w = scale * cscale[gm]; }
#pragma unroll
            for (int jn = 0; jn < 8; jn++) {
                int gn = n0 + wn + jn * 8 + lm * 2;
                if (gn >= N) continue;
                float vx = acc[im][jn][part * 2] * w;
                float vy = acc[im][jn][part * 2 + 1] * w;
                if (OUTH) {
                    int gn2 = gn;
                    if (ropeq) {
                        int d = gn % DQK;
                        if (d >= NOPE) {
                            int p = (d - NOPE) >> 1;
                            float sn = rs[crow * 32 + p], cs = rc[crow * 32 + p];
                            float tx = vx * cs - vy * sn;
                            vy = vx * sn + vy * cs;
                            vx = tx;
                        }
                    }
                    if (cmap192) gn2 = (gn >> 7) * 192 + (gn & 127);
                    __half* cp = (__half*)Cv + ((long long)z * sC) + crow * (long long)ldc + gn2;
                    *reinterpret_cast<__half2*>(cp) = __floats2half2_rn(vx, vy);
                } else {
                    long long off = crow * (long long)ldc + gn;
                    if (resid) {
                        vx += resid[off];
                        vy += resid[off + 1];
                    }
                    float* cp = (float*)Cv + ((long long)z * sC) + off;
                    if (atomicC) {
                        atomicAdd(cp, vx);
                        atomicAdd(cp + 1, vy);
                    } else {
                        *reinterpret_cast<float2*>(cp) = make_float2(vx, vy);
                        if (C2)
                            *reinterpret_cast<float2*>(C2 + off) = make_float2(vx, vy);
                    }
                }
            }
        }
    }
}

// ---------------------------------------------------------------------------
// Flash attention: 256 threads, 8 warps x 16 q-rows; k-blocks of 64.
// ---------------------------------------------------------------------------
#define SMEM_FLASH 131072

__global__ __launch_bounds__(256, 1)
void flash_attn_k(const __half* __restrict__ Q, const __half* __restrict__ K,
                  const __half* __restrict__ Vt, __half* __restrict__ O,
                  float scale)
{
    extern __shared__ __align__(128) char smem[];
    const int h = blockIdx.x;
    const int qb = (int)gridDim.y - 1 - (int)blockIdx.y;   // heaviest first
    const int nkb = 2 * qb + 2;
    const uint32_t sb = smem_u32(smem);
    const uint32_t Qs = sb;
    const uint32_t Ks = sb + 49152;
    const uint32_t Vs = sb + 49152 + 49152;
    const int tid = threadIdx.x, lane = tid & 31, wid = tid >> 5;
    const int wq = wid * 16;
    const int lr = lane >> 2, lm = lane & 3;

    for (int c = tid; c < 3072; c += 256) {
        int row = c / 24, kc = c % 24;
        int sub = kc >> 3, ch = kc & 7;
        cp16(Qs + row * 384 + sub * 128 + ((ch ^ (row & 7)) << 4),
             Q + ((long long)(qb * 128 + row) * (NHH * DQK) + h * DQK + kc * 8), 16);
    }
    auto load_kv = [&](int kb) {
        int buf = kb & 1;
        for (int c = tid; c < 1536; c += 256) {
            int row = c / 24, kc = c % 24;
            int sub = kc >> 3, ch = kc & 7;
            cp16(Ks + buf * 24576 + row * 384 + sub * 128 + ((ch ^ (row & 7)) << 4),
                 K + ((long long)(kb * 64 + row) * (NHH * DQK) + h * DQK + kc * 8), 16);
        }
        for (int c = tid; c < 1024; c += 256) {
            int row = c >> 3, ch = c & 7;
            cp16(Vs + buf * 16384 + row * 128 + ((ch ^ (row & 7)) << 4),
                 Vt + ((long long)(h * 128 + row) * TT + kb * 64 + ch * 8), 16);
        }
    };

    load_kv(0);
    cp_commit();

    float m_s[2] = {-1e30f, -1e30f}, l_s[2] = {0.f, 0.f};
    float acc[16][4];
#pragma unroll
    for (int dn = 0; dn < 16; dn++)
#pragma unroll
        for (int c = 0; c < 4; c++) acc[dn][c] = 0.f;

    const int a_row = lane & 15, a_h = lane >> 4;
    const int b_t = lane >> 3, b_r = lane & 7;

    for (int kb = 0; kb < nkb; kb++) {
        if (kb + 1 < nkb) load_kv(kb + 1);
        cp_commit();
        asm volatile("cp.async.wait_group 1;" ::: "memory");
        __syncthreads();
        const uint32_t kbase = Ks + (kb & 1) * 24576;
        const uint32_t vbase = Vs + (kb & 1) * 16384;

        float s[8][4];
#pragma unroll
        for (int jn = 0; jn < 8; jn++)
#pragma unroll
            for (int c = 0; c < 4; c++) s[jn][c] = 0.f;

#pragma unroll
        for (int ks = 0; ks < 12; ks++) {
            unsigned afr[4], bfr[8][2];
            {
                int row = wq + a_row;
                int kc = ks * 2 + a_h;
                ldm_x4(afr[0], afr[1], afr[2], afr[3],
                       Qs + row * 384 + (kc >> 3) * 128 + (((kc & 7) ^ (row & 7)) << 4));
            }
#pragma unroll
            for (int j2 = 0; j2 < 4; j2++) {
                int jn = j2 * 2 + (b_t >> 1);
                int row = jn * 8 + b_r;
                int kc = ks * 2 + (b_t & 1);
                unsigned r0, r1, r2, r3;
                ldm_x4(r0, r1, r2, r3,
                       kbase + row * 384 + (kc >> 3) * 128 + (((kc & 7) ^ (row & 7)) << 4));
                bfr[j2 * 2][0] = r0;     bfr[j2 * 2][1] = r1;
                bfr[j2 * 2 + 1][0] = r2; bfr[j2 * 2 + 1][1] = r3;
            }
#pragma unroll
            for (int jn = 0; jn < 8; jn++)
                mma_f16(s[jn], afr, bfr[jn]);
        }

        const int coff = kb * 64 - qb * 128;
        float alpha[2];
#pragma unroll
        for (int part = 0; part < 2; part++) {
            int r = wq + lr + part * 8;
            float mx = -1e30f;
#pragma unroll
            for (int jn = 0; jn < 8; jn++) {
#pragma unroll
                for (int q = 0; q < 2; q++) {
                    int c = jn * 8 + lm * 2 + q;
                    float v = s[jn][part * 2 + q] * scale;
                    if (c + coff > r) v = -1e30f;
                    s[jn][part * 2 + q] = v;
                    mx = fmaxf(mx, v);
                }
            }
            mx = fmaxf(mx, __shfl_xor_sync(0xffffffffu, mx, 1));
            mx = fmaxf(mx, __shfl_xor_sync(0xffffffffu, mx, 2));
            float mo = m_s[part];
            float mn = fmaxf(mo, mx);
            float al = __expf(mo - mn);
            float sum = 0.f;
#pragma unroll
            for (int jn = 0; jn < 8; jn++) {
#pragma unroll
                for (int q = 0; q < 2; q++) {
                    float p = __expf(s[jn][part * 2 + q] - mn);
                    s[jn][part * 2 + q] = p;
                    sum += p;
                }
            }
            sum += __shfl_xor_sync(0xffffffffu, sum, 1);
            sum += __shfl_xor_sync(0xffffffffu, sum, 2);
            l_s[part] = l_s[part] * al + sum;
            m_s[part] = mn;
            alpha[part] = al;
        }
#pragma unroll
        for (int dn = 0; dn < 16; dn++) {
            acc[dn][0] *= alpha[0];
            acc[dn][1] *= alpha[0];
            acc[dn][2] *= alpha[1];
            acc[dn][3] *= alpha[1];
        }

#pragma unroll
        for (int kv = 0; kv < 4; kv++) {
            unsigned ap[4];
            ap[0] = packh2(s[2 * kv][0], s[2 * kv][1]);
            ap[1] = packh2(s[2 * kv][2], s[2 * kv][3]);
            ap[2] = packh2(s[2 * kv + 1][0], s[2 * kv + 1][1]);
            ap[3] = packh2(s[2 * kv + 1][2], s[2 * kv + 1][3]);
#pragma unroll
            for (int j2 = 0; j2 < 8; j2++) {
                int dn = j2 * 2 + (b_t >> 1);
                int row = dn * 8 + b_r;
                int ch = kv * 2 + (b_t & 1);
                unsigned r0, r1, r2, r3;
                ldm_x4(r0, r1, r2, r3, vbase + row * 128 + ((ch ^ (row & 7)) << 4));
                unsigned bv0[2] = {r0, r1}, bv1[2] = {r2, r3};
                mma_f16(acc[j2 * 2], ap, bv0);
                mma_f16(acc[j2 * 2 + 1], ap, bv1);
            }
        }
        __syncthreads();
    }

#pragma unroll
    for (int part = 0; part < 2; part++) {
        float inv = 1.0f / l_s[part];
        int grow = qb * 128 + wq + lr + part * 8;
        __half* op = O + (long long)grow * (NHH * VDIM) + h * VDIM;
#pragma unroll
        for (int dn = 0; dn < 16; dn++) {
            int col = dn * 8 + lm * 2;
            *reinterpret_cast<__half2*>(op + col) =
                __floats2half2_rn(acc[dn][part * 2] * inv,
                                  acc[dn][part * 2 + 1] * inv);
        }
    }
}

// ---------------------------------------------------------------------------
// Elementwise / reduction kernels
// ---------------------------------------------------------------------------
__global__ void zero_counts_k() {
    if (threadIdx.x < NE) g_s.counts[threadIdx.x] = 0;
}

// ---- single-launch weight conversion ----
// thread counts per segment (n_elems / 16)
#define TQA   196608   // wqa   -> wqkva_h
#define TKVA  73728    // wkva  -> wqkva_h + QLAT*HH
#define TQB   294912
#define TKB   65536
#define TVB   65536
#define TWO   262144
#define TSUP  262144
#define TSDN  131072
#define TUP   1048576
#define TDN   524288
#define B0 TQA
#define B1 (B0 + TKVA)
#define B2 (B1 + TQB)
#define B3 (B2 + TKB)
#define B4 (B3 + TVB)
#define B5 (B4 + TWO)
#define B6 (B5 + TSUP)
#define B7 (B6 + TSDN)
#define B8 (B7 + TUP)
#define B9 (B8 + TDN)   // 2924544 total threads = 11424 * 256

__device__ __forceinline__ void f2h_seg(const float4* in, uint2* out,
                                        long long t, long long q) {
    float4 a = in[t];
    float4 b = in[t + q];
    float4 c = in[t + 2 * q];
    float4 d = in[t + 3 * q];
    out[t]         = cvt4(a);
    out[t + q]     = cvt4(b);
    out[t + 2 * q] = cvt4(c);
    out[t + 3 * q] = cvt4(d);
}

__global__ __launch_bounds__(256)
void f2h_all_k(const float* wqa, const float* wkva, const float* wqb,
               const float* wkb, const float* wvb, const float* wo,
               const float* wsup, const float* wsdn, const float* wup,
               const float* wdn)
{
    long long g = blockIdx.x * 256LL + threadIdx.x;
    if (g < B0)      f2h_seg((const float4*)wqa,  (uint2*)g_s.wqkva_h, g, TQA);
    else if (g < B1) f2h_seg((const float4*)wkva, (uint2*)(g_s.wqkva_h + (long long)QLAT * HH), g - B0, TKVA);
    else if (g < B2) f2h_seg((const float4*)wqb,  (uint2*)g_s.wqb_h,  g - B1, TQB);
    else if (g < B3) f2h_seg((const float4*)wkb,  (uint2*)g_s.wkb_h,  g - B2, TKB);
    else if (g < B4) f2h_seg((const float4*)wvb,  (uint2*)g_s.wvb_h,  g - B3, TVB);
    else if (g < B5) f2h_seg((const float4*)wo,   (uint2*)g_s.wo_h,   g - B4, TWO);
    else if (g < B6) f2h_seg((const float4*)wsup, (uint2*)g_s.wsup_h, g - B5, TSUP);
    else if (g < B7) f2h_seg((const float4*)wsdn, (uint2*)g_s.wsdn_h, g - B6, TSDN);
    else if (g < B8) f2h_seg((const float4*)wup,  (uint2*)g_s.wup_h,  g - B7, TUP);
    else             f2h_seg((const float4*)wdn,  (uint2*)g_s.wdn_h,  g - B8, TDN);
}

// fused: x1 = x + skip (stored), n1h = rms(x1)*w
__global__ __launch_bounds__(256)
void addrms_k(const float* __restrict__ x, const float* __restrict__ skip,
              const float* __restrict__ w, float* __restrict__ x1,
              __half* __restrict__ out) {
    int row = blockIdx.x;
    const float4* xp = (const float4*)(x + (long long)row * HH);
    const float4* sp = (const float4*)(skip + (long long)row * HH);
    float4* x1p = (float4*)(x1 + (long long)row * HH);
    float4 vals[2];
    float ss = 0.f;
#pragma unroll
    for (int i = 0; i < 2; i++) {
        int j = threadIdx.x + i * 256;
        float4 a = xp[j], b = sp[j];
        float4 v = make_float4(a.x + b.x, a.y + b.y, a.z + b.z, a.w + b.w);
        vals[i] = v;
        x1p[j] = v;
        ss += v.x * v.x + v.y * v.y + v.z * v.z + v.w * v.w;
    }
    __shared__ float red[256];
    red[threadIdx.x] = ss;
    __syncthreads();
    for (int st = 128; st > 0; st >>= 1) {
        if (threadIdx.x < st) red[threadIdx.x] += red[threadIdx.x + st];
        __syncthreads();
    }
    float scale = rsqrtf(red[0] / (float)HH + 1e-6f);
    uint2* op = (uint2*)(out + (long long)row * HH);
    const float4* wp = (const float4*)w;
#pragma unroll
    for (int i = 0; i < 2; i++) {
        int j = threadIdx.x + i * 256;
        float4 v = vals[i], ww = wp[j];
        op[j] = cvt4(make_float4(v.x * scale * ww.x, v.y * scale * ww.y,
                                 v.z * scale * ww.z, v.w * scale * ww.w));
    }
}

__device__ __forceinline__ void rms_row(const float* in, const float* w,
                                        __half* out, int cols) {
    const float4* ip = (const float4*)in;
    int c4 = cols >> 2;
    float ss = 0.f;
    for (int j = threadIdx.x; j < c4; j += 256) {
        float4 v = ip[j];
        ss += v.x * v.x + v.y * v.y + v.z * v.z + v.w * v.w;
    }
    __shared__ float red[256];
    red[threadIdx.x] = ss;
    __syncthreads();
    for (int st = 128; st > 0; st >>= 1) {
        if (threadIdx.x < st) red[threadIdx.x] += red[threadIdx.x + st];
        __syncthreads();
    }
    float scale = rsqrtf(red[0] / (float)cols + 1e-6f);
    uint2* op = (uint2*)out;
    const float4* wp = (const float4*)w;
    for (int j = threadIdx.x; j < c4; j += 256) {
        float4 v = ip[j], ww = wp[j];
        op[j] = cvt4(make_float4(v.x * scale * ww.x, v.y * scale * ww.y,
                                 v.z * scale * ww.z, v.w * scale * ww.w));
    }
}

__global__ __launch_bounds__(256)
void rmsnorm_h_k(const float* __restrict__ in, const float* __restrict__ w,
                 __half* __restrict__ out, int cols, int instride, int outstride) {
    int row = blockIdx.x;
    rms_row(in + (long long)row * instride, w, out + (long long)row * outstride, cols);
}

// merged qa + ckv rmsnorm (y=0: qa slice, y=1: ckv slice of qkv_pre)
__global__ __launch_bounds__(256)
void rmsnorm_qkv_k(const float* __restrict__ qkv, const float* __restrict__ qan,
                   const float* __restrict__ kvan,
                   __half* __restrict__ qah, __half* __restrict__ ckvh) {
    int row = blockIdx.x;
    if (blockIdx.y == 0)
        rms_row(qkv + (long long)row * QKVN, qan, qah + (long long)row * QLAT, QLAT);
    else
        rms_row(qkv + (long long)row * QKVN + QLAT, kvan,
                ckvh + (long long)row * KVLAT, KVLAT);
}

// fill rope PE columns of kfull
__global__ void build_pe_k(const float* __restrict__ qkv,
                           const float* __restrict__ rsin,
                           const float* __restrict__ rcos,
                           __half* __restrict__ kfull) {
    int t = blockIdx.x;
    __shared__ __half pe[ROPED];
    if (threadIdx.x < 32) {
        int p = threadIdx.x;
        float a = qkv[(long long)t * QKVN + QLAT + KVLAT + 2 * p];
        float b = qkv[(long long)t * QKVN + QLAT + KVLAT + 2 * p + 1];
        float s = rsin[t * 32 + p], c = rcos[t * 32 + p];
        pe[2 * p]     = __float2half_rn(a * c - b * s);
        pe[2 * p + 1] = __float2half_rn(a * s + b * c);
    }
    __syncthreads();
    for (int i = threadIdx.x; i < NHH * ROPED; i += blockDim.x) {
        int h = i >> 6;
        int d = i & 63;
        kfull[(long long)t * (NHH * DQK) + h * DQK + NOPE + d] = pe[d];
    }
}

__global__ __launch_bounds__(256)
void gate_topk_k(const __half* __restrict__ n2, const float* __restrict__ gw) {
    int t = blockIdx.x;
    __shared__ float logits[NE];
    int warp = threadIdx.x >> 5, lane = threadIdx.x & 31;
    const __half* xp = n2 + (long long)t * HH;
    const float* wp = gw + warp * HH;
    float s = 0.f;
    for (int k = lane; k < HH; k += 32) s += __half2float(xp[k]) * wp[k];
    for (int off = 16; off > 0; off >>= 1) s += __shfl_down_sync(0xffffffffu, s, off);
    if (lane == 0) logits[warp] = s;
    __syncthreads();
    if (threadIdx.x == 0) {
        float m = logits[0];
        for (int e = 1; e < NE; e++) m = fmaxf(m, logits[e]);
        float p[NE];
        float sum = 0.f;
        for (int e = 0; e < NE; e++) { p[e] = __expf(logits[e] - m); sum += p[e]; }
        for (int e = 0; e < NE; e++) p[e] /= sum;
        int i0 = 0;
        for (int e = 1; e < NE; e++) if (p[e] > p[i0]) i0 = e;
        int i1 = -1;
        for (int e = 0; e < NE; e++) {
            if (e == i0) continue;
            if (i1 < 0 || p[e] > p[i1]) i1 = e;
        }
        float w0 = p[i0], w1 = p[i1];
        float tot = w0 + w1;
        w0 /= tot; w1 /= tot;
        int pos0 = atomicAdd(&g_s.counts[i0], 1);
        g_s.tok[i0 * TT + pos0] = t;
        g_s.ew[i0 * TT + pos0] = w0;
        int pos1 = atomicAdd(&g_s.counts[i1], 1);
        g_s.tok[i1 * TT + pos1] = t;
        g_s.ew[i1 * TT + pos1] = w1;
    }
}

__global__ void silu_gate_k(const float* __restrict__ in, __half* __restrict__ out,
                            int half_) {
    int row = blockIdx.x;
    const float4* ip = (const float4*)(in + (long long)row * 2 * half_);
    const float4* gp = (const float4*)(in + (long long)row * 2 * half_ + half_);
    uint2* op = (uint2*)(out + (long long)row * half_);
    int h4 = half_ >> 2;
    for (int j = threadIdx.x; j < h4; j += blockDim.x) {
        float4 a = ip[j], b = gp[j];
        float4 r;
        r.x = (a.x / (1.f + __expf(-a.x))) * b.x;
        r.y = (a.y / (1.f + __expf(-a.y))) * b.y;
        r.z = (a.z / (1.f + __expf(-a.z))) * b.z;
        r.w = (a.w / (1.f + __expf(-a.w))) * b.w;
        op[j] = cvt4(r);
    }
}

__global__ void silu_gate_moe_k() {
    int e = blockIdx.y;
    int row = blockIdx.x;
    if (row >= g_s.counts[e]) return;
    const float* base = g_s.h + ((long long)e * TT + row) * (2 * MIDIM);
    const float4* ip = (const float4*)base;
    const float4* gp = (const float4*)(base + MIDIM);
    uint2* op = (uint2*)(g_s.hah + ((long long)e * TT + row) * MIDIM);
    for (int j = threadIdx.x; j < (MIDIM >> 2); j += blockDim.x) {
        float4 a = ip[j], b = gp[j];
        float4 r;
        r.x = (a.x / (1.f + __expf(-a.x))) * b.x;
        r.y = (a.y / (1.f + __expf(-a.y))) * b.y;
        r.z = (a.z / (1.f + __expf(-a.z))) * b.z;
        r.w = (a.w / (1.f + __expf(-a.w))) * b.w;
        op[j] = cvt4(r);
    }
}

// ---------------------------------------------------------------------------
// Host-side launch helpers
// ---------------------------------------------------------------------------
static void launch_gemm(bool wide, bool outh, const __half* A, const __half* B, void* C,
                        int M, int N, int K, int lda, int ldb, int ldc,
                        long long sA, long long sB, long long sC, int bz,
                        float sc, int causal, int klim,
                        const int* aidx, const int* mdev,
                        const int* cidx, const float* cs, int pstride,
                        const float* resid = nullptr, float* C2 = nullptr,
                        int atomicC = 0,
                        const float* rs = nullptr, const float* rc = nullptr,
                        int ropeq = 0, int cmap192 = 0)
{
    if (wide) {
        dim3 grid((N + 255) / 256, (M + 127) / 128, bz);
        if (outh)
            gemm_h<true, 256, 2, 256><<<grid, 256, SMEM_BYTES>>>(
                A, B, C, M, N, K, lda, ldb, ldc, sA, sB, sC, sc, causal, klim,
                aidx, mdev, cidx, cs, pstride, resid, C2, atomicC, rs, rc, ropeq, cmap192);
        else
            gemm_h<false, 256, 2, 256><<<grid, 256, SMEM_BYTES>>>(
                A, B, C, M, N, K, lda, ldb, ldc, sA, sB, sC, sc, causal, klim,
                aidx, mdev, cidx, cs, pstride, resid, C2, atomicC, rs, rc, ropeq, cmap192);
    } else {
        dim3 grid((N + 127) / 128, (M + 127) / 128, bz);
        if (outh)
            gemm_h<true, 128, 3, 128><<<grid, 128, SMEM_BYTES>>>(
                A, B, C, M, N, K, lda, ldb, ldc, sA, sB, sC, sc, causal, klim,
                aidx, mdev, cidx, cs, pstride, resid, C2, atomicC, rs, rc, ropeq, cmap192);
        else
            gemm_h<false, 128, 3, 128><<<grid, 128, SMEM_BYTES>>>(
                A, B, C, M, N, K, lda, ldb, ldc, sA, sB, sC, sc, causal, klim,
                aidx, mdev, cidx, cs, pstride, resid, C2, atomicC, rs, rc, ropeq, cmap192);
    }
}

static void launch_nt(bool wide, bool outh, const __half* A, const __half* B, void* C,
                      int M, int N, int K, int lda, int ldb, int ldc)
{
    launch_gemm(wide, outh, A, B, C, M, N, K, lda, ldb, ldc, 0, 0, 0, 1, 1.f, 0, 0,
                nullptr, nullptr, nullptr, nullptr, 0);
}

// ---------------------------------------------------------------------------
extern "C" void kernel_launch(void* const* d_in, const int* in_sizes, int n_in,
                              void* d_out, int out_size)
{
    const float* x    = (const float*)d_in[0];
    const float* skip = (const float*)d_in[1];
    const float* rsin = (const float*)d_in[2];
    const float* rcos = (const float*)d_in[3];
    const float* ln1  = (const float*)d_in[4];
    const float* ln2  = (const float*)d_in[5];
    const float* wqa  = (const float*)d_in[6];
    const float* qan  = (const float*)d_in[7];
    const float* wqb  = (const float*)d_in[8];
    const float* wkva = (const float*)d_in[9];
    const float* kvan = (const float*)d_in[10];
    const float* wkb  = (const float*)d_in[11];
    const float* wvb  = (const float*)d_in[12];
    const float* wo   = (const float*)d_in[13];
    const float* gw   = (const float*)d_in[14];
    const float* wup  = (const float*)d_in[15];
    const float* wdn  = (const float*)d_in[16];
    const float* wsup = (const float*)d_in[17];
    const float* wsdn = (const float*)d_in[18];
    float* out = (float*)d_out;

    Scratch* s = nullptr;
    cudaGetSymbolAddress((void**)&s, g_s);
    cudaFuncSetAttribute((const void*)gemm_h<true, 256, 2, 256>,
                         cudaFuncAttributeMaxDynamicSharedMemorySize, SMEM_BYTES);
    cudaFuncSetAttribute((const void*)gemm_h<false, 256, 2, 256>,
                         cudaFuncAttributeMaxDynamicSharedMemorySize, SMEM_BYTES);
    cudaFuncSetAttribute((const void*)gemm_h<true, 128, 3, 128>,
                         cudaFuncAttributeMaxDynamicSharedMemorySize, SMEM_BYTES);
    cudaFuncSetAttribute((const void*)gemm_h<false, 128, 3, 128>,
                         cudaFuncAttributeMaxDynamicSharedMemorySize, SMEM_BYTES);
    cudaFuncSetAttribute((const void*)flash_attn_k,
                         cudaFuncAttributeMaxDynamicSharedMemorySize, SMEM_FLASH);

    const int n = TT * HH;
    float* out2 = out + (long long)n;

    zero_counts_k<<<1, 32>>>();

    // all weights -> half in ONE launch
    f2h_all_k<<<B9 / 256, 256>>>(wqa, wkva, wqb, wkb, wvb, wo, wsup, wsdn, wup, wdn);

    // x1 = x + skip ; n1h = rms(x1)
    addrms_k<<<TT, 256>>>(x, skip, ln1, s->x1, s->n1h);

    // fused qa+kva projection
    launch_nt(true, false, s->n1h, s->wqkva_h, s->qkv_pre, TT, QKVN, HH, HH, HH, QKVN);

    // merged qa + ckv rmsnorm
    rmsnorm_qkv_k<<<dim3(TT, 2), 256>>>(s->qkv_pre, qan, kvan, s->qah, s->ckvh);

    // q path: qb GEMM with fused rope epilogue
    launch_gemm(true, true, s->qah, s->wqb_h, s->qh, TT, NHH * DQK, QLAT,
                QLAT, QLAT, NHH * DQK, 0, 0, 0, 1,
                1.f, 0, 0, nullptr, nullptr, nullptr, nullptr, 0,
                nullptr, nullptr, 0, rsin, rcos, /*ropeq=*/1, 0);

    // kv path: kb GEMM writes kfull directly (column remap), then PE fill
    launch_gemm(true, true, s->ckvh, s->wkb_h, s->kfullh, TT, NHH * NOPE, KVLAT,
                KVLAT, KVLAT, NHH * DQK, 0, 0, 0, 1,
                1.f, 0, 0, nullptr, nullptr, nullptr, nullptr, 0,
                nullptr, nullptr, 0, nullptr, nullptr, 0, /*cmap192=*/1);
    build_pe_k<<<TT, 256>>>(s->qkv_pre, rsin, rcos, s->kfullh);
    launch_nt(true, true, s->wvb_h, s->ckvh, s->vTh, NHH * VDIM, TT, KVLAT, KVLAT, KVLAT, TT);

    // fused flash attention
    float attn_scale = 1.0f / sqrtf((float)DQK);
    flash_attn_k<<<dim3(NHH, TT / 128), 256, SMEM_FLASH>>>(
        s->qh, s->kfullh, s->vTh, s->oh, attn_scale);

    // attn out + residual fused: out[0:n] = x2 = x1 + oh @ wo^T
    launch_gemm(true, false, s->oh, s->wo_h, out, TT, HH, NHH * VDIM,
                NHH * VDIM, NHH * VDIM, HH, 0, 0, 0, 1,
                1.f, 0, 0, nullptr, nullptr, nullptr, nullptr, 0,
                s->x1, s->x2, 0);

    // n2 and MoE gating
    rmsnorm_h_k<<<TT, 256>>>(s->x2, ln2, s->n2h, HH, HH, HH);
    gate_topk_k<<<TT, 256>>>(s->n2h, gw);

    // shared FFN -> out2 directly
    launch_nt(true, false, s->n2h, s->wsup_h, s->hs, TT, 2 * SHI, HH, HH, HH, 2 * SHI);
    silu_gate_k<<<TT, 256>>>(s->hs, s->hsah, SHI);
    launch_nt(true, false, s->hsah, s->wsdn_h, out2, TT, HH, SHI, SHI, SHI, HH);

    // routed experts
    launch_gemm(true, false, s->n2h, s->wup_h, s->h, TT, 2 * MIDIM, HH,
                HH, HH, 2 * MIDIM,
                0, (long long)(2 * MIDIM) * HH, (long long)TT * 2 * MIDIM, NE,
                1.f, 0, 0,
                s->tok, s->counts, nullptr, nullptr, TT);
    silu_gate_moe_k<<<dim3(TT, NE), 256>>>();
    launch_gemm(true, false, s->hah, s->wdn_h, out2, TT, HH, MIDIM,
                MIDIM, MIDIM, HH,
                (long long)TT * MIDIM, (long long)HH * MIDIM, 0, NE,
                1.f, 0, 0,
                nullptr, s->counts, s->tok, s->ew, TT,
                nullptr, nullptr, 1);
}

// round 17
// speedup vs baseline: 1.4686x; 1.0394x over previous
#include <cuda_runtime.h>
#include <cuda_fp16.h>
#include <math.h>
#include <stdint.h>

#define TT   2048
#define HH   2048
#define NHH  16
#define NOPE 128
#define ROPED 64
#define DQK  192     // NOPE + ROPE
#define VDIM 128
#define QLAT 1536
#define KVLAT 512
#define NE   8
#define MIDIM 512
#define SHI  1024    // 2*MI
#define QKVN (QLAT + KVLAT + ROPED)   // 2112

// ---------------------------------------------------------------------------
// Scratch (static device memory; no allocations anywhere)
// ---------------------------------------------------------------------------
struct __align__(128) Scratch {
    // f32 buffers
    float x1[TT * HH];
    float qkv_pre[TT * QKVN];            // [qa_pre | kv] fused
    float x2[TT * HH];
    float h[(long long)NE * TT * 2 * MIDIM];
    float hs[TT * 2 * SHI];
    float ew[NE * TT];
    int   tok[NE * TT];
    int   counts[NE];
    // half activation buffers
    __half n1h[TT * HH];
    __half qah[TT * QLAT];
    __half qh[TT * NHH * DQK];
    __half ckvh[TT * KVLAT];
    __half kfullh[TT * NHH * DQK];
    __half vTh[NHH * VDIM * TT];          // [h*128+d, t]
    __half oh[TT * NHH * VDIM];
    __half n2h[TT * HH];
    __half hsah[TT * SHI];
    __half hah[(long long)NE * TT * MIDIM];
    // half weight copies
    __half wqkva_h[QKVN * HH];            // [wqa ; wkva] fused
    __half wqb_h[NHH * DQK * QLAT];
    __half wkb_h[NHH * NOPE * KVLAT];
    __half wvb_h[NHH * VDIM * KVLAT];
    __half wo_h[HH * NHH * VDIM];
    __half wsup_h[2 * SHI * HH];
    __half wsdn_h[HH * SHI];
    __half wup_h[(long long)NE * 2 * MIDIM * HH];
    __half wdn_h[(long long)NE * HH * MIDIM];
};
__device__ Scratch g_s;

// ---------------------------------------------------------------------------
// helpers
// ---------------------------------------------------------------------------
__device__ __forceinline__ uint32_t smem_u32(const void* p) {
    uint32_t a;
    asm("{ .reg .u64 t; cvta.to.shared.u64 t, %1; cvt.u32.u64 %0, t; }" : "=r"(a) : "l"(p));
    return a;
}

__device__ __forceinline__ void cp16(uint32_t dst, const void* src, int sz) {
    asm volatile("cp.async.cg.shared.global [%0], [%1], 16, %2;"
                 :: "r"(dst), "l"(src), "r"(sz));
}
__device__ __forceinline__ void cp_commit() {
    asm volatile("cp.async.commit_group;" ::: "memory");
}

__device__ __forceinline__ void ldm_x4(unsigned& r0, unsigned& r1, unsigned& r2,
                                       unsigned& r3, uint32_t addr) {
    asm volatile("ldmatrix.sync.aligned.m8n8.x4.shared.b16 {%0,%1,%2,%3}, [%4];"
                 : "=r"(r0), "=r"(r1), "=r"(r2), "=r"(r3) : "r"(addr));
}

__device__ __forceinline__ void mma_f16(float* d, const unsigned* a, const unsigned* b) {
    asm volatile(
        "mma.sync.aligned.m16n8k16.row.col.f32.f16.f16.f32 "
        "{%0,%1,%2,%3}, {%4,%5,%6,%7}, {%8,%9}, {%0,%1,%2,%3};\n"
        : "+f"(d[0]), "+f"(d[1]), "+f"(d[2]), "+f"(d[3])
        : "r"(a[0]), "r"(a[1]), "r"(a[2]), "r"(a[3]), "r"(b[0]), "r"(b[1]));
}

__device__ __forceinline__ unsigned packh2(float x, float y) {
    __half2 h = __floats2half2_rn(x, y);
    return *reinterpret_cast<unsigned*>(&h);
}

__device__ __forceinline__ uint2 cvt4(float4 v) {
    __half2 h0 = __floats2half2_rn(v.x, v.y);
    __half2 h1 = __floats2half2_rn(v.z, v.w);
    uint2 o;
    o.x = *reinterpret_cast<unsigned*>(&h0);
    o.y = *reinterpret_cast<unsigned*>(&h1);
    return o;
}

// ---------------------------------------------------------------------------
// fp16 NT GEMM — narrow 128x128x64, 3-stage, 128 threads (R5-proven config)
// + epilogue fusions: resid/C2/atomicC (f32 out), ropeq, cmap192
// ---------------------------------------------------------------------------
#define SMEM_BYTES 98304

template <bool OUTH>
__global__ __launch_bounds__(128)
void gemm_h(const __half* __restrict__ A, const __half* __restrict__ B,
            void* __restrict__ Cv,
            int M, int N, int K, int lda, int ldb, int ldc,
            long long sA, long long sB, long long sC,
            float scale, int causal, int klim,
            const int* __restrict__ aidx, const int* __restrict__ mdev,
            const int* __restrict__ cidx, const float* __restrict__ cscale,
            int pstride,
            const float* __restrict__ resid, float* __restrict__ C2, int atomicC,
            const float* __restrict__ rs, const float* __restrict__ rc,
            int ropeq, int cmap192)
{
    constexpr int NSTAGE = 3;
    constexpr int STG_BYTES = 256 * 128;
    extern __shared__ __align__(128) char smem[];
    const int z = blockIdx.z;
    A += (long long)z * sA;
    B += (long long)z * sB;
    if (pstride) {
        if (mdev)   mdev   += z;
        if (aidx)   aidx   += (long long)z * pstride;
        if (cidx)   cidx   += (long long)z * pstride;
        if (cscale) cscale += (long long)z * pstride;
    }
    const int Meff = mdev ? *mdev : M;
    const int m0 = blockIdx.y * 128;
    const int n0 = blockIdx.x * 128;
    if (m0 >= Meff) return;
    if (causal && n0 > m0 + 127) return;
    const int kmax = klim ? min(K, m0 + 128) : K;
    const int ktiles = kmax >> 6;

    const uint32_t sbase = smem_u32(smem);
    const int tid = threadIdx.x;
    const int lane = tid & 31;
    const int wid = tid >> 5;
    const int wm = (wid & 1) * 64;
    const int wn = (wid >> 1) * 64;
    const int lr = lane >> 2;
    const int lm = lane & 3;

    float acc[4][8][4];
#pragma unroll
    for (int i = 0; i < 4; i++)
#pragma unroll
        for (int j = 0; j < 8; j++)
#pragma unroll
            for (int c = 0; c < 4; c++) acc[i][j][c] = 0.f;

    auto issue_stage = [&](int i) {
        const uint32_t base = sbase + (i % NSTAGE) * STG_BYTES;
        const int kt = i << 6;
#pragma unroll
        for (int it = 0; it < 16; it++) {
            int c = tid + it * 128;
            int row = c >> 3, ch = c & 7;
            uint32_t dst = base + row * 128 + ((ch ^ (row & 7)) << 4);
            const __half* src;
            int sz = 0;
            if (row < 128) {
                int gm = m0 + row;
                src = A;
                if (gm < Meff) {
                    int ar = aidx ? aidx[gm] : gm;
                    src = A + (long long)ar * lda + kt + ch * 8;
                    sz = 16;
                }
            } else {
                int gn = n0 + row - 128;
                src = B;
                if (gn < N) {
                    src = B + (long long)gn * ldb + kt + ch * 8;
                    sz = 16;
                }
            }
            cp16(dst, src, sz);
        }
    };

#pragma unroll
    for (int s = 0; s < NSTAGE - 1; s++) {
        if (s < ktiles) issue_stage(s);
        cp_commit();
    }

    const int a_row = lane & 15;
    const int a_h = lane >> 4;
    const int b_t = lane >> 3;
    const int b_r = lane & 7;

    for (int i = 0; i < ktiles; i++) {
        if (i + NSTAGE - 1 < ktiles) issue_stage(i + NSTAGE - 1);
        cp_commit();
        asm volatile("cp.async.wait_group 2;" ::: "memory");
        __syncthreads();

        const uint32_t base = sbase + (i % NSTAGE) * STG_BYTES;
#pragma unroll
        for (int kk = 0; kk < 4; kk++) {
            unsigned afr[4][4], bfr[8][2];
#pragma unroll
            for (int im = 0; im < 4; im++) {
                int row = wm + im * 16 + a_row;
                int ch = kk * 2 + a_h;
                ldm_x4(afr[im][0], afr[im][1], afr[im][2], afr[im][3],
                       base + row * 128 + ((ch ^ (row & 7)) << 4));
            }
#pragma unroll
            for (int j2 = 0; j2 < 4; j2++) {
                int jn = j2 * 2 + (b_t >> 1);
                int row = 128 + wn + jn * 8 + b_r;
                int ch = kk * 2 + (b_t & 1);
                unsigned r0, r1, r2, r3;
                ldm_x4(r0, r1, r2, r3, base + row * 128 + ((ch ^ (row & 7)) << 4));
                bfr[j2 * 2][0] = r0;     bfr[j2 * 2][1] = r1;
                bfr[j2 * 2 + 1][0] = r2; bfr[j2 * 2 + 1][1] = r3;
            }
#pragma unroll
            for (int im = 0; im < 4; im++)
#pragma unroll
                for (int jn = 0; jn < 8; jn++)
                    mma_f16(acc[im][jn], afr[im], bfr[jn]);
        }
        __syncthreads();
    }

#pragma unroll
    for (int im = 0; im < 4; im++) {
#pragma unroll
        for (int part = 0; part < 2; part++) {
            int gm = m0 + wm + im * 16 + lr + part * 8;
            if (gm >= Meff) continue;
            long long crow = gm;
            float w = scale;
            if (cidx) { crow = cidx[gm]; w = scale * cscale[gm]; }
#pragma unroll
            for (int jn = 0; jn < 8; jn++) {
                int gn = n0 + wn + jn * 8 + lm * 2;
                if (gn >= N) continue;
                float vx = acc[im][jn][part * 2] * w;
                float vy = acc[im][jn][part * 2 + 1] * w;
                if (OUTH) {
                    int gn2 = gn;
                    if (ropeq) {
                        int d = gn % DQK;
                        if (d >= NOPE) {
                            int p = (d - NOPE) >> 1;
                            float sn = rs[crow * 32 + p], cs = rc[crow * 32 + p];
                            float tx = vx * cs - vy * sn;
                            vy = vx * sn + vy * cs;
                            vx = tx;
                        }
                    }
                    if (cmap192) gn2 = (gn >> 7) * 192 + (gn & 127);
                    __half* cp = (__half*)Cv + ((long long)z * sC) + crow * (long long)ldc + gn2;
                    *reinterpret_cast<__half2*>(cp) = __floats2half2_rn(vx, vy);
                } else {
                    long long off = crow * (long long)ldc + gn;
                    if (resid) {
                        vx += resid[off];
                        vy += resid[off + 1];
                    }
                    float* cp = (float*)Cv + ((long long)z * sC) + off;
                    if (atomicC) {
                        atomicAdd(cp, vx);
                        atomicAdd(cp + 1, vy);
                    } else {
                        *reinterpret_cast<float2*>(cp) = make_float2(vx, vy);
                        if (C2)
                            *reinterpret_cast<float2*>(C2 + off) = make_float2(vx, vy);
                    }
                }
            }
        }
    }
}

// ---------------------------------------------------------------------------
// Flash attention: 256 threads, 8 warps x 16 q-rows; k-blocks of 64.
// ---------------------------------------------------------------------------
#define SMEM_FLASH 131072

__global__ __launch_bounds__(256, 1)
void flash_attn_k(const __half* __restrict__ Q, const __half* __restrict__ K,
                  const __half* __restrict__ Vt, __half* __restrict__ O,
                  float scale)
{
    extern __shared__ __align__(128) char smem[];
    const int h = blockIdx.x;
    const int qb = (int)gridDim.y - 1 - (int)blockIdx.y;   // heaviest first
    const int nkb = 2 * qb + 2;
    const uint32_t sb = smem_u32(smem);
    const uint32_t Qs = sb;
    const uint32_t Ks = sb + 49152;
    const uint32_t Vs = sb + 49152 + 49152;
    const int tid = threadIdx.x, lane = tid & 31, wid = tid >> 5;
    const int wq = wid * 16;
    const int lr = lane >> 2, lm = lane & 3;

    for (int c = tid; c < 3072; c += 256) {
        int row = c / 24, kc = c % 24;
        int sub = kc >> 3, ch = kc & 7;
        cp16(Qs + row * 384 + sub * 128 + ((ch ^ (row & 7)) << 4),
             Q + ((long long)(qb * 128 + row) * (NHH * DQK) + h * DQK + kc * 8), 16);
    }
    auto load_kv = [&](int kb) {
        int buf = kb & 1;
        for (int c = tid; c < 1536; c += 256) {
            int row = c / 24, kc = c % 24;
            int sub = kc >> 3, ch = kc & 7;
            cp16(Ks + buf * 24576 + row * 384 + sub * 128 + ((ch ^ (row & 7)) << 4),
                 K + ((long long)(kb * 64 + row) * (NHH * DQK) + h * DQK + kc * 8), 16);
        }
        for (int c = tid; c < 1024; c += 256) {
            int row = c >> 3, ch = c & 7;
            cp16(Vs + buf * 16384 + row * 128 + ((ch ^ (row & 7)) << 4),
                 Vt + ((long long)(h * 128 + row) * TT + kb * 64 + ch * 8), 16);
        }
    };

    load_kv(0);
    cp_commit();

    float m_s[2] = {-1e30f, -1e30f}, l_s[2] = {0.f, 0.f};
    float acc[16][4];
#pragma unroll
    for (int dn = 0; dn < 16; dn++)
#pragma unroll
        for (int c = 0; c < 4; c++) acc[dn][c] = 0.f;

    const int a_row = lane & 15, a_h = lane >> 4;
    const int b_t = lane >> 3, b_r = lane & 7;

    for (int kb = 0; kb < nkb; kb++) {
        if (kb + 1 < nkb) load_kv(kb + 1);
        cp_commit();
        asm volatile("cp.async.wait_group 1;" ::: "memory");
        __syncthreads();
        const uint32_t kbase = Ks + (kb & 1) * 24576;
        const uint32_t vbase = Vs + (kb & 1) * 16384;

        float s[8][4];
#pragma unroll
        for (int jn = 0; jn < 8; jn++)
#pragma unroll
            for (int c = 0; c < 4; c++) s[jn][c] = 0.f;

#pragma unroll
        for (int ks = 0; ks < 12; ks++) {
            unsigned afr[4], bfr[8][2];
            {
                int row = wq + a_row;
                int kc = ks * 2 + a_h;
                ldm_x4(afr[0], afr[1], afr[2], afr[3],
                       Qs + row * 384 + (kc >> 3) * 128 + (((kc & 7) ^ (row & 7)) << 4));
            }
#pragma unroll
            for (int j2 = 0; j2 < 4; j2++) {
                int jn = j2 * 2 + (b_t >> 1);
                int row = jn * 8 + b_r;
                int kc = ks * 2 + (b_t & 1);
                unsigned r0, r1, r2, r3;
                ldm_x4(r0, r1, r2, r3,
                       kbase + row * 384 + (kc >> 3) * 128 + (((kc & 7) ^ (row & 7)) << 4));
                bfr[j2 * 2][0] = r0;     bfr[j2 * 2][1] = r1;
                bfr[j2 * 2 + 1][0] = r2; bfr[j2 * 2 + 1][1] = r3;
            }
#pragma unroll
            for (int jn = 0; jn < 8; jn++)
                mma_f16(s[jn], afr, bfr[jn]);
        }

        const int coff = kb * 64 - qb * 128;
        float alpha[2];
#pragma unroll
        for (int part = 0; part < 2; part++) {
            int r = wq + lr + part * 8;
            float mx = -1e30f;
#pragma unroll
            for (int jn = 0; jn < 8; jn++) {
#pragma unroll
                for (int q = 0; q < 2; q++) {
                    int c = jn * 8 + lm * 2 + q;
                    float v = s[jn][part * 2 + q] * scale;
                    if (c + coff > r) v = -1e30f;
                    s[jn][part * 2 + q] = v;
                    mx = fmaxf(mx, v);
                }
            }
            mx = fmaxf(mx, __shfl_xor_sync(0xffffffffu, mx, 1));
            mx = fmaxf(mx, __shfl_xor_sync(0xffffffffu, mx, 2));
            float mo = m_s[part];
            float mn = fmaxf(mo, mx);
            float al = __expf(mo - mn);
            float sum = 0.f;
#pragma unroll
            for (int jn = 0; jn < 8; jn++) {
#pragma unroll
                for (int q = 0; q < 2; q++) {
                    float p = __expf(s[jn][part * 2 + q] - mn);
                    s[jn][part * 2 + q] = p;
                    sum += p;
                }
            }
            sum += __shfl_xor_sync(0xffffffffu, sum, 1);
            sum += __shfl_xor_sync(0xffffffffu, sum, 2);
            l_s[part] = l_s[part] * al + sum;
            m_s[part] = mn;
            alpha[part] = al;
        }
#pragma unroll
        for (int dn = 0; dn < 16; dn++) {
            acc[dn][0] *= alpha[0];
            acc[dn][1] *= alpha[0];
            acc[dn][2] *= alpha[1];
            acc[dn][3] *= alpha[1];
        }

#pragma unroll
        for (int kv = 0; kv < 4; kv++) {
            unsigned ap[4];
            ap[0] = packh2(s[2 * kv][0], s[2 * kv][1]);
            ap[1] = packh2(s[2 * kv][2], s[2 * kv][3]);
            ap[2] = packh2(s[2 * kv + 1][0], s[2 * kv + 1][1]);
            ap[3] = packh2(s[2 * kv + 1][2], s[2 * kv + 1][3]);
#pragma unroll
            for (int j2 = 0; j2 < 8; j2++) {
                int dn = j2 * 2 + (b_t >> 1);
                int row = dn * 8 + b_r;
                int ch = kv * 2 + (b_t & 1);
                unsigned r0, r1, r2, r3;
                ldm_x4(r0, r1, r2, r3, vbase + row * 128 + ((ch ^ (row & 7)) << 4));
                unsigned bv0[2] = {r0, r1}, bv1[2] = {r2, r3};
                mma_f16(acc[j2 * 2], ap, bv0);
                mma_f16(acc[j2 * 2 + 1], ap, bv1);
            }
        }
        __syncthreads();
    }

#pragma unroll
    for (int part = 0; part < 2; part++) {
        float inv = 1.0f / l_s[part];
        int grow = qb * 128 + wq + lr + part * 8;
        __half* op = O + (long long)grow * (NHH * VDIM) + h * VDIM;
#pragma unroll
        for (int dn = 0; dn < 16; dn++) {
            int col = dn * 8 + lm * 2;
            *reinterpret_cast<__half2*>(op + col) =
                __floats2half2_rn(acc[dn][part * 2] * inv,
                                  acc[dn][part * 2 + 1] * inv);
        }
    }
}

// ---------------------------------------------------------------------------
// Elementwise / reduction kernels
// ---------------------------------------------------------------------------
__global__ void zero_counts_k() {
    if (threadIdx.x < NE) g_s.counts[threadIdx.x] = 0;
}

// ---- single-launch weight conversion ----
#define TQA   196608
#define TKVA  73728
#define TQB   294912
#define TKB   65536
#define TVB   65536
#define TWO   262144
#define TSUP  262144
#define TSDN  131072
#define TUP   1048576
#define TDN   524288
#define B0 TQA
#define B1 (B0 + TKVA)
#define B2 (B1 + TQB)
#define B3 (B2 + TKB)
#define B4 (B3 + TVB)
#define B5 (B4 + TWO)
#define B6 (B5 + TSUP)
#define B7 (B6 + TSDN)
#define B8 (B7 + TUP)
#define B9 (B8 + TDN)   // 2924544 threads = 11424 * 256

__device__ __forceinline__ void f2h_seg(const float4* in, uint2* out,
                                        long long t, long long q) {
    float4 a = in[t];
    float4 b = in[t + q];
    float4 c = in[t + 2 * q];
    float4 d = in[t + 3 * q];
    out[t]         = cvt4(a);
    out[t + q]     = cvt4(b);
    out[t + 2 * q] = cvt4(c);
    out[t + 3 * q] = cvt4(d);
}

__global__ __launch_bounds__(256)
void f2h_all_k(const float* wqa, const float* wkva, const float* wqb,
               const float* wkb, const float* wvb, const float* wo,
               const float* wsup, const float* wsdn, const float* wup,
               const float* wdn)
{
    long long g = blockIdx.x * 256LL + threadIdx.x;
    if (g < B0)      f2h_seg((const float4*)wqa,  (uint2*)g_s.wqkva_h, g, TQA);
    else if (g < B1) f2h_seg((const float4*)wkva, (uint2*)(g_s.wqkva_h + (long long)QLAT * HH), g - B0, TKVA);
    else if (g < B2) f2h_seg((const float4*)wqb,  (uint2*)g_s.wqb_h,  g - B1, TQB);
    else if (g < B3) f2h_seg((const float4*)wkb,  (uint2*)g_s.wkb_h,  g - B2, TKB);
    else if (g < B4) f2h_seg((const float4*)wvb,  (uint2*)g_s.wvb_h,  g - B3, TVB);
    else if (g < B5) f2h_seg((const float4*)wo,   (uint2*)g_s.wo_h,   g - B4, TWO);
    else if (g < B6) f2h_seg((const float4*)wsup, (uint2*)g_s.wsup_h, g - B5, TSUP);
    else if (g < B7) f2h_seg((const float4*)wsdn, (uint2*)g_s.wsdn_h, g - B6, TSDN);
    else if (g < B8) f2h_seg((const float4*)wup,  (uint2*)g_s.wup_h,  g - B7, TUP);
    else             f2h_seg((const float4*)wdn,  (uint2*)g_s.wdn_h,  g - B8, TDN);
}

// fused: x1 = x + skip (stored), n1h = rms(x1)*w
__global__ __launch_bounds__(256)
void addrms_k(const float* __restrict__ x, const float* __restrict__ skip,
              const float* __restrict__ w, float* __restrict__ x1,
              __half* __restrict__ out) {
    int row = blockIdx.x;
    const float4* xp = (const float4*)(x + (long long)row * HH);
    const float4* sp = (const float4*)(skip + (long long)row * HH);
    float4* x1p = (float4*)(x1 + (long long)row * HH);
    float4 vals[2];
    float ss = 0.f;
#pragma unroll
    for (int i = 0; i < 2; i++) {
        int j = threadIdx.x + i * 256;
        float4 a = xp[j], b = sp[j];
        float4 v = make_float4(a.x + b.x, a.y + b.y, a.z + b.z, a.w + b.w);
        vals[i] = v;
        x1p[j] = v;
        ss += v.x * v.x + v.y * v.y + v.z * v.z + v.w * v.w;
    }
    __shared__ float red[256];
    red[threadIdx.x] = ss;
    __syncthreads();
    for (int st = 128; st > 0; st >>= 1) {
        if (threadIdx.x < st) red[threadIdx.x] += red[threadIdx.x + st];
        __syncthreads();
    }
    float scale = rsqrtf(red[0] / (float)HH + 1e-6f);
    uint2* op = (uint2*)(out + (long long)row * HH);
    const float4* wp = (const float4*)w;
#pragma unroll
    for (int i = 0; i < 2; i++) {
        int j = threadIdx.x + i * 256;
        float4 v = vals[i], ww = wp[j];
        op[j] = cvt4(make_float4(v.x * scale * ww.x, v.y * scale * ww.y,
                                 v.z * scale * ww.z, v.w * scale * ww.w));
    }
}

__device__ __forceinline__ void rms_row(const float* in, const float* w,
                                        __half* out, int cols) {
    const float4* ip = (const float4*)in;
    int c4 = cols >> 2;
    float ss = 0.f;
    for (int j = threadIdx.x; j < c4; j += 256) {
        float4 v = ip[j];
        ss += v.x * v.x + v.y * v.y + v.z * v.z + v.w * v.w;
    }
    __shared__ float red[256];
    red[threadIdx.x] = ss;
    __syncthreads();
    for (int st = 128; st > 0; st >>= 1) {
        if (threadIdx.x < st) red[threadIdx.x] += red[threadIdx.x + st];
        __syncthreads();
    }
    float scale = rsqrtf(red[0] / (float)cols + 1e-6f);
    uint2* op = (uint2*)out;
    const float4* wp = (const float4*)w;
    for (int j = threadIdx.x; j < c4; j += 256) {
        float4 v = ip[j], ww = wp[j];
        op[j] = cvt4(make_float4(v.x * scale * ww.x, v.y * scale * ww.y,
                                 v.z * scale * ww.z, v.w * scale * ww.w));
    }
}

__global__ __launch_bounds__(256)
void rmsnorm_h_k(const float* __restrict__ in, const float* __restrict__ w,
                 __half* __restrict__ out, int cols, int instride, int outstride) {
    int row = blockIdx.x;
    rms_row(in + (long long)row * instride, w, out + (long long)row * outstride, cols);
}

// merged qa + ckv rmsnorm
__global__ __launch_bounds__(256)
void rmsnorm_qkv_k(const float* __restrict__ qkv, const float* __restrict__ qan,
                   const float* __restrict__ kvan,
                   __half* __restrict__ qah, __half* __restrict__ ckvh) {
    int row = blockIdx.x;
    if (blockIdx.y == 0)
        rms_row(qkv + (long long)row * QKVN, qan, qah + (long long)row * QLAT, QLAT);
    else
        rms_row(qkv + (long long)row * QKVN + QLAT, kvan,
                ckvh + (long long)row * KVLAT, KVLAT);
}

// fill rope PE columns of kfull
__global__ void build_pe_k(const float* __restrict__ qkv,
                           const float* __restrict__ rsin,
                           const float* __restrict__ rcos,
                           __half* __restrict__ kfull) {
    int t = blockIdx.x;
    __shared__ __half pe[ROPED];
    if (threadIdx.x < 32) {
        int p = threadIdx.x;
        float a = qkv[(long long)t * QKVN + QLAT + KVLAT + 2 * p];
        float b = qkv[(long long)t * QKVN + QLAT + KVLAT + 2 * p + 1];
        float s = rsin[t * 32 + p], c = rcos[t * 32 + p];
        pe[2 * p]     = __float2half_rn(a * c - b * s);
        pe[2 * p + 1] = __float2half_rn(a * s + b * c);
    }
    __syncthreads();
    for (int i = threadIdx.x; i < NHH * ROPED; i += blockDim.x) {
        int h = i >> 6;
        int d = i & 63;
        kfull[(long long)t * (NHH * DQK) + h * DQK + NOPE + d] = pe[d];
    }
}

__global__ __launch_bounds__(256)
void gate_topk_k(const __half* __restrict__ n2, const float* __restrict__ gw) {
    int t = blockIdx.x;
    __shared__ float logits[NE];
    int warp = threadIdx.x >> 5, lane = threadIdx.x & 31;
    const __half* xp = n2 + (long long)t * HH;
    const float* wp = gw + warp * HH;
    float s = 0.f;
    for (int k = lane; k < HH; k += 32) s += __half2float(xp[k]) * wp[k];
    for (int off = 16; off > 0; off >>= 1) s += __shfl_down_sync(0xffffffffu, s, off);
    if (lane == 0) logits[warp] = s;
    __syncthreads();
    if (threadIdx.x == 0) {
        float m = logits[0];
        for (int e = 1; e < NE; e++) m = fmaxf(m, logits[e]);
        float p[NE];
        float sum = 0.f;
        for (int e = 0; e < NE; e++) { p[e] = __expf(logits[e] - m); sum += p[e]; }
        for (int e = 0; e < NE; e++) p[e] /= sum;
        int i0 = 0;
        for (int e = 1; e < NE; e++) if (p[e] > p[i0]) i0 = e;
        int i1 = -1;
        for (int e = 0; e < NE; e++) {
            if (e == i0) continue;
            if (i1 < 0 || p[e] > p[i1]) i1 = e;
        }
        float w0 = p[i0], w1 = p[i1];
        float tot = w0 + w1;
        w0 /= tot; w1 /= tot;
        int pos0 = atomicAdd(&g_s.counts[i0], 1);
        g_s.tok[i0 * TT + pos0] = t;
        g_s.ew[i0 * TT + pos0] = w0;
        int pos1 = atomicAdd(&g_s.counts[i1], 1);
        g_s.tok[i1 * TT + pos1] = t;
        g_s.ew[i1 * TT + pos1] = w1;
    }
}

__global__ void silu_gate_k(const float* __restrict__ in, __half* __restrict__ out,
                            int half_) {
    int row = blockIdx.x;
    const float4* ip = (const float4*)(in + (long long)row * 2 * half_);
    const float4* gp = (const float4*)(in + (long long)row * 2 * half_ + half_);
    uint2* op = (uint2*)(out + (long long)row * half_);
    int h4 = half_ >> 2;
    for (int j = threadIdx.x; j < h4; j += blockDim.x) {
        float4 a = ip[j], b = gp[j];
        float4 r;
        r.x = (a.x / (1.f + __expf(-a.x))) * b.x;
        r.y = (a.y / (1.f + __expf(-a.y))) * b.y;
        r.z = (a.z / (1.f + __expf(-a.z))) * b.z;
        r.w = (a.w / (1.f + __expf(-a.w))) * b.w;
        op[j] = cvt4(r);
    }
}

__global__ void silu_gate_moe_k() {
    int e = blockIdx.y;
    int row = blockIdx.x;
    if (row >= g_s.counts[e]) return;
    const float* base = g_s.h + ((long long)e * TT + row) * (2 * MIDIM);
    const float4* ip = (const float4*)base;
    const float4* gp = (const float4*)(base + MIDIM);
    uint2* op = (uint2*)(g_s.hah + ((long long)e * TT + row) * MIDIM);
    for (int j = threadIdx.x; j < (MIDIM >> 2); j += blockDim.x) {
        float4 a = ip[j], b = gp[j];
        float4 r;
        r.x = (a.x / (1.f + __expf(-a.x))) * b.x;
        r.y = (a.y / (1.f + __expf(-a.y))) * b.y;
        r.z = (a.z / (1.f + __expf(-a.z))) * b.z;
        r.w = (a.w / (1.f + __expf(-a.w))) * b.w;
        op[j] = cvt4(r);
    }
}

// ---------------------------------------------------------------------------
// Host-side launch helpers — all dense GEMMs use the narrow config
// ---------------------------------------------------------------------------
static void launch_gemm(bool outh, const __half* A, const __half* B, void* C,
                        int M, int N, int K, int lda, int ldb, int ldc,
                        long long sA, long long sB, long long sC, int bz,
                        float sc, int causal, int klim,
                        const int* aidx, const int* mdev,
                        const int* cidx, const float* cs, int pstride,
                        const float* resid = nullptr, float* C2 = nullptr,
                        int atomicC = 0,
                        const float* rs = nullptr, const float* rc = nullptr,
                        int ropeq = 0, int cmap192 = 0)
{
    dim3 grid((N + 127) / 128, (M + 127) / 128, bz);
    if (outh)
        gemm_h<true><<<grid, 128, SMEM_BYTES>>>(
            A, B, C, M, N, K, lda, ldb, ldc, sA, sB, sC, sc, causal, klim,
            aidx, mdev, cidx, cs, pstride, resid, C2, atomicC, rs, rc, ropeq, cmap192);
    else
        gemm_h<false><<<grid, 128, SMEM_BYTES>>>(
            A, B, C, M, N, K, lda, ldb, ldc, sA, sB, sC, sc, causal, klim,
            aidx, mdev, cidx, cs, pstride, resid, C2, atomicC, rs, rc, ropeq, cmap192);
}

static void launch_nt(bool outh, const __half* A, const __half* B, void* C,
                      int M, int N, int K, int lda, int ldb, int ldc)
{
    launch_gemm(outh, A, B, C, M, N, K, lda, ldb, ldc, 0, 0, 0, 1, 1.f, 0, 0,
                nullptr, nullptr, nullptr, nullptr, 0);
}

// ---------------------------------------------------------------------------
extern "C" void kernel_launch(void* const* d_in, const int* in_sizes, int n_in,
                              void* d_out, int out_size)
{
    const float* x    = (const float*)d_in[0];
    const float* skip = (const float*)d_in[1];
    const float* rsin = (const float*)d_in[2];
    const float* rcos = (const float*)d_in[3];
    const float* ln1  = (const float*)d_in[4];
    const float* ln2  = (const float*)d_in[5];
    const float* wqa  = (const float*)d_in[6];
    const float* qan  = (const float*)d_in[7];
    const float* wqb  = (const float*)d_in[8];
    const float* wkva = (const float*)d_in[9];
    const float* kvan = (const float*)d_in[10];
    const float* wkb  = (const float*)d_in[11];
    const float* wvb  = (const float*)d_in[12];
    const float* wo   = (const float*)d_in[13];
    const float* gw   = (const float*)d_in[14];
    const float* wup  = (const float*)d_in[15];
    const float* wdn  = (const float*)d_in[16];
    const float* wsup = (const float*)d_in[17];
    const float* wsdn = (const float*)d_in[18];
    float* out = (float*)d_out;

    Scratch* s = nullptr;
    cudaGetSymbolAddress((void**)&s, g_s);
    cudaFuncSetAttribute((const void*)gemm_h<true>,
                         cudaFuncAttributeMaxDynamicSharedMemorySize, SMEM_BYTES);
    cudaFuncSetAttribute((const void*)gemm_h<false>,
                         cudaFuncAttributeMaxDynamicSharedMemorySize, SMEM_BYTES);
    cudaFuncSetAttribute((const void*)flash_attn_k,
                         cudaFuncAttributeMaxDynamicSharedMemorySize, SMEM_FLASH);

    const int n = TT * HH;
    float* out2 = out + (long long)n;

    zero_counts_k<<<1, 32>>>();

    // all weights -> half in ONE launch
    f2h_all_k<<<B9 / 256, 256>>>(wqa, wkva, wqb, wkb, wvb, wo, wsup, wsdn, wup, wdn);

    // x1 = x + skip ; n1h = rms(x1)
    addrms_k<<<TT, 256>>>(x, skip, ln1, s->x1, s->n1h);

    // fused qa+kva projection
    launch_nt(false, s->n1h, s->wqkva_h, s->qkv_pre, TT, QKVN, HH, HH, HH, QKVN);

    // merged qa + ckv rmsnorm
    rmsnorm_qkv_k<<<dim3(TT, 2), 256>>>(s->qkv_pre, qan, kvan, s->qah, s->ckvh);

    // q path: qb GEMM with fused rope epilogue
    launch_gemm(true, s->qah, s->wqb_h, s->qh, TT, NHH * DQK, QLAT,
                QLAT, QLAT, NHH * DQK, 0, 0, 0, 1,
                1.f, 0, 0, nullptr, nullptr, nullptr, nullptr, 0,
                nullptr, nullptr, 0, rsin, rcos, /*ropeq=*/1, 0);

    // kv path: kb GEMM writes kfull directly (column remap), then PE fill
    launch_gemm(true, s->ckvh, s->wkb_h, s->kfullh, TT, NHH * NOPE, KVLAT,
                KVLAT, KVLAT, NHH * DQK, 0, 0, 0, 1,
                1.f, 0, 0, nullptr, nullptr, nullptr, nullptr, 0,
                nullptr, nullptr, 0, nullptr, nullptr, 0, /*cmap192=*/1);
    build_pe_k<<<TT, 256>>>(s->qkv_pre, rsin, rcos, s->kfullh);
    launch_nt(true, s->wvb_h, s->ckvh, s->vTh, NHH * VDIM, TT, KVLAT, KVLAT, KVLAT, TT);

    // fused flash attention
    float attn_scale = 1.0f / sqrtf((float)DQK);
    flash_attn_k<<<dim3(NHH, TT / 128), 256, SMEM_FLASH>>>(
        s->qh, s->kfullh, s->vTh, s->oh, attn_scale);

    // attn out + residual fused: out[0:n] = x2 = x1 + oh @ wo^T
    launch_gemm(false, s->oh, s->wo_h, out, TT, HH, NHH * VDIM,
                NHH * VDIM, NHH * VDIM, HH, 0, 0, 0, 1,
                1.f, 0, 0, nullptr, nullptr, nullptr, nullptr, 0,
                s->x1, s->x2, 0);

    // n2 and MoE gating
    rmsnorm_h_k<<<TT, 256>>>(s->x2, ln2, s->n2h, HH, HH, HH);
    gate_topk_k<<<TT, 256>>>(s->n2h, gw);

    // shared FFN -> out2 directly
    launch_nt(false, s->n2h, s->wsup_h, s->hs, TT, 2 * SHI, HH, HH, HH, 2 * SHI);
    silu_gate_k<<<TT, 256>>>(s->hs, s->hsah, SHI);
    launch_nt(false, s->hsah, s->wsdn_h, out2, TT, HH, SHI, SHI, SHI, HH);

    // routed experts
    launch_gemm(false, s->n2h, s->wup_h, s->h, TT, 2 * MIDIM, HH,
                HH, HH, 2 * MIDIM,
                0, (long long)(2 * MIDIM) * HH, (long long)TT * 2 * MIDIM, NE,
                1.f, 0, 0,
                s->tok, s->counts, nullptr, nullptr, TT);
    silu_gate_moe_k<<<dim3(TT, NE), 256>>>();
    launch_gemm(false, s->hah, s->wdn_h, out2, TT, HH, MIDIM,
                MIDIM, MIDIM, HH,
                (long long)TT * MIDIM, (long long)HH * MIDIM, 0, NE,
                1.f, 0, 0,
                nullptr, s->counts, s->tok, s->ew, TT,
                nullptr, nullptr, 1);
}